// round 1
// baseline (speedup 1.0000x reference)
#include <cuda_runtime.h>
#include <math.h>

// ---------------- Problem constants ----------------
#define B_    2
#define S_    2048
#define HID_  2048
#define NH_   16
#define HD_   128
#define QR_   6
#define KR_   2
#define VR_   2
#define M_    (B_*S_)          // 4096 tokens
#define NPROJ 1440             // 96+32+32+768+256+256
#define SCALING_F 0.08838834764831845f  // 128^-0.5

// Y row layout offsets
#define OFF_AQ 0
#define OFF_AK 96
#define OFF_AV 128
#define OFF_BQ 160
#define OFF_BK 928
#define OFF_BV 1184

// ---------------- Scratch (device globals; no allocation allowed) ----------------
__device__ float g_Wcat[NPROJ * HID_];          // 11.8 MB
__device__ float g_Y[(size_t)M_ * NPROJ];       // 23.6 MB
__device__ float g_q[(size_t)B_*NH_*S_*HD_];    // 33.5 MB  layout [b][h][s][d]
__device__ float g_k[(size_t)B_*NH_*S_*HD_];
__device__ float g_v[(size_t)B_*NH_*S_*HD_];
__device__ float g_O[(size_t)M_ * NH_ * HD_];   // 33.5 MB  layout [b][s][h*HD+d]

// ---------------- Kernel 0: concatenate weights into one [1440][2048] matrix ----------------
__global__ void concat_w_kernel(const float* __restrict__ waq, const float* __restrict__ wak,
                                const float* __restrict__ wav, const float* __restrict__ wbq,
                                const float* __restrict__ wbk, const float* __restrict__ wbv)
{
    int idx = blockIdx.x * blockDim.x + threadIdx.x;
    if (idx >= NPROJ * HID_) return;
    int row = idx >> 11;          // /2048
    int col = idx & 2047;
    const float* src; int r;
    if      (row < OFF_AK) { src = waq; r = row;          }
    else if (row < OFF_AV) { src = wak; r = row - OFF_AK; }
    else if (row < OFF_BQ) { src = wav; r = row - OFF_AV; }
    else if (row < OFF_BK) { src = wbq; r = row - OFF_BQ; }
    else if (row < OFF_BV) { src = wbk; r = row - OFF_BK; }
    else                   { src = wbv; r = row - OFF_BV; }
    g_Wcat[idx] = src[(size_t)r * HID_ + col];
}

// ---------------- SGEMM (NT): C[M][N] = A[M][K] * B[N][K]^T, both row-major K-inner ----------------
// 128x128 block tile, BK=16, 256 threads, 8x8 per thread.
__global__ __launch_bounds__(256, 2)
void sgemm_nt(const float* __restrict__ A, const float* __restrict__ Bm,
              float* __restrict__ C, int M, int N, int K)
{
    const int BM = 128, BN = 128, BK = 16;
    __shared__ float As[BK][BM + 4];
    __shared__ float Bs[BK][BN + 4];

    int tid = threadIdx.x;
    int bm = blockIdx.y * BM;
    int bn = blockIdx.x * BN;

    int lr = tid >> 2;            // 0..63
    int lc = (tid & 3) << 2;      // 0,4,8,12

    int ty = tid >> 4;            // 0..15
    int tx = tid & 15;            // 0..15

    float acc[8][8];
    #pragma unroll
    for (int i = 0; i < 8; i++)
        #pragma unroll
        for (int j = 0; j < 8; j++) acc[i][j] = 0.f;

    for (int k0 = 0; k0 < K; k0 += BK) {
        #pragma unroll
        for (int half = 0; half < 2; half++) {
            int r = lr + half * 64;
            int gm = bm + r;
            float4 va = make_float4(0.f, 0.f, 0.f, 0.f);
            if (gm < M) va = *(const float4*)(A + (size_t)gm * K + k0 + lc);
            As[lc + 0][r] = va.x; As[lc + 1][r] = va.y;
            As[lc + 2][r] = va.z; As[lc + 3][r] = va.w;

            int gn = bn + r;
            float4 vb = make_float4(0.f, 0.f, 0.f, 0.f);
            if (gn < N) vb = *(const float4*)(Bm + (size_t)gn * K + k0 + lc);
            Bs[lc + 0][r] = vb.x; Bs[lc + 1][r] = vb.y;
            Bs[lc + 2][r] = vb.z; Bs[lc + 3][r] = vb.w;
        }
        __syncthreads();

        #pragma unroll
        for (int k = 0; k < BK; k++) {
            float a[8], b[8];
            #pragma unroll
            for (int i = 0; i < 8; i++) a[i] = As[k][ty * 8 + i];
            #pragma unroll
            for (int j = 0; j < 8; j++) b[j] = Bs[k][tx * 8 + j];
            #pragma unroll
            for (int i = 0; i < 8; i++)
                #pragma unroll
                for (int j = 0; j < 8; j++) acc[i][j] += a[i] * b[j];
        }
        __syncthreads();
    }

    #pragma unroll
    for (int i = 0; i < 8; i++) {
        int gm = bm + ty * 8 + i;
        if (gm >= M) continue;
        #pragma unroll
        for (int j0 = 0; j0 < 8; j0 += 4) {
            int gn = bn + tx * 8 + j0;
            if (gn < N) {
                float4 v = make_float4(acc[i][j0], acc[i][j0+1], acc[i][j0+2], acc[i][j0+3]);
                *(float4*)(C + (size_t)gm * N + gn) = v;
            }
        }
    }
}

// ---------------- Kernel 2: RoPE + rank contraction -> q,k,v [b][h][s][d] ----------------
__global__ void rope_contract_kernel(const float* __restrict__ cosb, const float* __restrict__ sinb)
{
    int token = blockIdx.x;              // b*S + s
    int b = token / S_;
    int s = token % S_;
    const float* y = g_Y + (size_t)token * NPROJ;
    int d = threadIdx.x;                 // 0..127

    __shared__ float sA[160];            // Aq(96) | Ak(32) | Av(32)
    for (int i = d; i < 160; i += 128) sA[i] = y[i];
    __syncthreads();

    int dh = d & 63;
    float c  = cosb[s * 64 + dh];
    float sn = sinb[s * 64 + dh];
    bool hi = (d >= 64);

    float bq[QR_], bk[KR_], bv[VR_];
    #pragma unroll
    for (int r = 0; r < QR_; r++) {
        float x1 = y[OFF_BQ + r * HD_ + dh];
        float x2 = y[OFF_BQ + r * HD_ + 64 + dh];
        bq[r] = hi ? (x1 * sn + x2 * c) : (x1 * c - x2 * sn);
    }
    #pragma unroll
    for (int r = 0; r < KR_; r++) {
        float x1 = y[OFF_BK + r * HD_ + dh];
        float x2 = y[OFF_BK + r * HD_ + 64 + dh];
        bk[r] = hi ? (x1 * sn + x2 * c) : (x1 * c - x2 * sn);
    }
    #pragma unroll
    for (int r = 0; r < VR_; r++) bv[r] = y[OFF_BV + r * HD_ + d];

    #pragma unroll
    for (int h = 0; h < NH_; h++) {
        float accq = 0.f, acck = 0.f, accv = 0.f;
        #pragma unroll
        for (int r = 0; r < QR_; r++) accq += sA[h * QR_ + r] * bq[r];
        #pragma unroll
        for (int r = 0; r < KR_; r++) acck += sA[96 + h * KR_ + r] * bk[r];
        #pragma unroll
        for (int r = 0; r < VR_; r++) accv += sA[128 + h * VR_ + r] * bv[r];
        size_t o = (((size_t)b * NH_ + h) * S_ + s) * HD_ + d;
        g_q[o] = accq * (SCALING_F / (float)QR_);   // fold /QR and sqrt(d) scaling
        g_k[o] = acck * (1.f / (float)KR_);
        g_v[o] = accv * (1.f / (float)VR_);
    }
}

// ---------------- Kernel 3: flash attention (fp32, full softmax, +mask) ----------------
// Block: 64 q-rows x full HD=128. 256 threads. KV tiles of 64.
#define QST_LD 68
#define SS_LD  68
#define ATT_SMEM_FLOATS (128*QST_LD /*Qst*/ + 128*QST_LD /*Kst*/ + 64*128 /*Vs*/ + 64*SS_LD /*Ss*/ + 192)
#define ATT_SMEM_BYTES  (ATT_SMEM_FLOATS * 4)

__global__ __launch_bounds__(256, 1)
void attn_kernel(const float* __restrict__ mask)
{
    extern __shared__ float sm[];
    float* Qst  = sm;                          // [128][QST_LD] transposed: [d][row]
    float* Kst  = Qst + 128 * QST_LD;          // [128][QST_LD] transposed: [d][kv]
    float* Vs   = Kst + 128 * QST_LD;          // [64][128] natural
    float* Ss   = Vs  + 64 * 128;              // [64][SS_LD]
    float* mrow = Ss  + 64 * SS_LD;            // [64]
    float* lrow = mrow + 64;                   // [64]
    float* frow = lrow + 64;                   // [64]

    int tid = threadIdx.x;
    int q0  = blockIdx.x * 64;
    int h   = blockIdx.y;
    int b   = blockIdx.z;

    size_t headbase = ((size_t)b * NH_ + h) * S_ * HD_;
    const float* qp = g_q + headbase + (size_t)q0 * HD_;

    // Load Q tile transposed
    for (int t = tid; t < 64 * 32; t += 256) {
        int row = t >> 5, d4 = (t & 31) << 2;
        float4 val = *(const float4*)(qp + row * HD_ + d4);
        Qst[(d4 + 0) * QST_LD + row] = val.x;
        Qst[(d4 + 1) * QST_LD + row] = val.y;
        Qst[(d4 + 2) * QST_LD + row] = val.z;
        Qst[(d4 + 3) * QST_LD + row] = val.w;
    }
    if (tid < 64) { mrow[tid] = -INFINITY; lrow[tid] = 0.f; }

    float acc[4][8];
    #pragma unroll
    for (int i = 0; i < 4; i++)
        #pragma unroll
        for (int u = 0; u < 8; u++) acc[i][u] = 0.f;

    int tr = tid >> 4, tc = tid & 15;    // PV mapping: rows tr*4.., cols tc*8..
    int sy = tr, sx = tc;                // score mapping: rows sy*4.., cols sx*4..
    const float* maskbase = mask + ((size_t)b * S_ + q0) * S_;

    for (int kv0 = 0; kv0 < S_; kv0 += 64) {
        const float* kp = g_k + headbase + (size_t)kv0 * HD_;
        const float* vp = g_v + headbase + (size_t)kv0 * HD_;
        for (int t = tid; t < 64 * 32; t += 256) {
            int row = t >> 5, d4 = (t & 31) << 2;
            float4 val = *(const float4*)(kp + row * HD_ + d4);
            Kst[(d4 + 0) * QST_LD + row] = val.x;
            Kst[(d4 + 1) * QST_LD + row] = val.y;
            Kst[(d4 + 2) * QST_LD + row] = val.z;
            Kst[(d4 + 3) * QST_LD + row] = val.w;
            ((float4*)Vs)[t] = *(const float4*)(vp + row * HD_ + d4);
        }
        __syncthreads();

        // ---- scores: S = Q K^T (Q already scaled) ----
        float sc[4][4];
        #pragma unroll
        for (int i = 0; i < 4; i++)
            #pragma unroll
            for (int j = 0; j < 4; j++) sc[i][j] = 0.f;

        #pragma unroll 8
        for (int kk = 0; kk < 128; kk++) {
            float4 a = *(const float4*)&Qst[kk * QST_LD + sy * 4];
            float4 bb = *(const float4*)&Kst[kk * QST_LD + sx * 4];
            float av[4] = {a.x, a.y, a.z, a.w};
            float bvv[4] = {bb.x, bb.y, bb.z, bb.w};
            #pragma unroll
            for (int i = 0; i < 4; i++)
                #pragma unroll
                for (int j = 0; j < 4; j++) sc[i][j] += av[i] * bvv[j];
        }

        // store scores + mask
        #pragma unroll
        for (int i = 0; i < 4; i++) {
            int qr = sy * 4 + i;
            #pragma unroll
            for (int j = 0; j < 4; j++) {
                Ss[qr * SS_LD + sx * 4 + j] =
                    sc[i][j] + maskbase[(size_t)qr * S_ + kv0 + sx * 4 + j];
            }
        }
        __syncthreads();

        // ---- online softmax update ----
        {
            int r = tid >> 2, g = tid & 3;
            float mloc = -INFINITY;
            #pragma unroll
            for (int cc = 0; cc < 16; cc++)
                mloc = fmaxf(mloc, Ss[r * SS_LD + g * 16 + cc]);
            mloc = fmaxf(mloc, __shfl_xor_sync(0xffffffffu, mloc, 1));
            mloc = fmaxf(mloc, __shfl_xor_sync(0xffffffffu, mloc, 2));
            float mold = mrow[r];
            float mnew = fmaxf(mold, mloc);
            float suml = 0.f;
            #pragma unroll
            for (int cc = 0; cc < 16; cc++) {
                float p = __expf(Ss[r * SS_LD + g * 16 + cc] - mnew);
                Ss[r * SS_LD + g * 16 + cc] = p;
                suml += p;
            }
            suml += __shfl_xor_sync(0xffffffffu, suml, 1);
            suml += __shfl_xor_sync(0xffffffffu, suml, 2);
            if (g == 0) {
                float f = __expf(mold - mnew);
                frow[r] = f;
                lrow[r] = lrow[r] * f + suml;
                mrow[r] = mnew;
            }
        }
        __syncthreads();

        // ---- rescale + PV ----
        float ff[4];
        #pragma unroll
        for (int i = 0; i < 4; i++) ff[i] = frow[tr * 4 + i];
        #pragma unroll
        for (int i = 0; i < 4; i++)
            #pragma unroll
            for (int u = 0; u < 8; u++) acc[i][u] *= ff[i];

        #pragma unroll 4
        for (int j = 0; j < 64; j++) {
            float p[4];
            #pragma unroll
            for (int i = 0; i < 4; i++) p[i] = Ss[(tr * 4 + i) * SS_LD + j];
            float4 v0 = *(const float4*)&Vs[j * 128 + tc * 8];
            float4 v1 = *(const float4*)&Vs[j * 128 + tc * 8 + 4];
            float vv[8] = {v0.x, v0.y, v0.z, v0.w, v1.x, v1.y, v1.z, v1.w};
            #pragma unroll
            for (int i = 0; i < 4; i++)
                #pragma unroll
                for (int u = 0; u < 8; u++) acc[i][u] += p[i] * vv[u];
        }
        __syncthreads();
    }

    // ---- epilogue: normalize, write O[b][s][h*HD+d] ----
    #pragma unroll
    for (int i = 0; i < 4; i++) {
        int qr = q0 + tr * 4 + i;
        float inv = 1.f / lrow[tr * 4 + i];
        size_t o = ((size_t)b * S_ + qr) * (NH_ * HD_) + h * HD_ + tc * 8;
        float4 w0 = make_float4(acc[i][0]*inv, acc[i][1]*inv, acc[i][2]*inv, acc[i][3]*inv);
        float4 w1 = make_float4(acc[i][4]*inv, acc[i][5]*inv, acc[i][6]*inv, acc[i][7]*inv);
        *(float4*)(g_O + o)     = w0;
        *(float4*)(g_O + o + 4) = w1;
    }
}

// ---------------- Host launcher ----------------
extern "C" void kernel_launch(void* const* d_in, const int* in_sizes, int n_in,
                              void* d_out, int out_size)
{
    const float* x    = (const float*)d_in[0];   // hidden_states [B,S,HID]
    const float* cosb = (const float*)d_in[1];   // freqs_cos [S,64]
    const float* sinb = (const float*)d_in[2];   // freqs_sin [S,64]
    // d_in[3] = kv_write_indices (unused by reference)
    const float* mask = (const float*)d_in[4];   // [B,1,S,S]
    const float* waq  = (const float*)d_in[5];
    const float* wak  = (const float*)d_in[6];
    const float* wav  = (const float*)d_in[7];
    const float* wbq  = (const float*)d_in[8];
    const float* wbk  = (const float*)d_in[9];
    const float* wbv  = (const float*)d_in[10];
    const float* wo   = (const float*)d_in[11];  // [HID, NH*HD]
    float* out = (float*)d_out;

    float *pWcat, *pY, *pO;
    cudaGetSymbolAddress((void**)&pWcat, g_Wcat);
    cudaGetSymbolAddress((void**)&pY,    g_Y);
    cudaGetSymbolAddress((void**)&pO,    g_O);

    // 1) concat weights
    concat_w_kernel<<<(NPROJ * HID_ + 255) / 256, 256>>>(waq, wak, wav, wbq, wbk, wbv);

    // 2) projection GEMM: Y = X @ Wcat^T   [4096 x 1440]
    sgemm_nt<<<dim3((NPROJ + 127) / 128, M_ / 128), 256>>>(x, pWcat, pY, M_, NPROJ, HID_);

    // 3) RoPE + contraction -> q,k,v
    rope_contract_kernel<<<M_, 128>>>(cosb, sinb);

    // 4) attention
    cudaFuncSetAttribute(attn_kernel, cudaFuncAttributeMaxDynamicSharedMemorySize, ATT_SMEM_BYTES);
    attn_kernel<<<dim3(S_ / 64, NH_, B_), 256, ATT_SMEM_BYTES>>>(mask);

    // 5) output GEMM: out = O @ W_o^T   [4096 x 2048]
    sgemm_nt<<<dim3((NH_ * HD_) / 128, M_ / 128), 256>>>(pO, wo, out, M_, NH_ * HD_, NH_ * HD_);
}

// round 7
// speedup vs baseline: 2.1863x; 2.1863x over previous
#include <cuda_runtime.h>
#include <cuda_bf16.h>
#include <math.h>
#include <stdint.h>

// ---------------- Problem constants ----------------
#define B_    2
#define S_    2048
#define HID_  2048
#define NH_   16
#define HD_   128
#define QR_   6
#define KR_   2
#define VR_   2
#define M_    (B_*S_)          // 4096 tokens
#define NPROJ 1440             // 96+32+32+768+256+256
#define NPROJ_PAD 1536
#define KS_   (3*HID_)         // 6144: A=[hi|lo|hi], B=[hi|hi|lo]
#define SCALING_F 0.08838834764831845f  // 128^-0.5

// Y row layout offsets
#define OFF_AQ 0
#define OFF_AK 96
#define OFF_AV 128
#define OFF_BQ 160
#define OFF_BK 928
#define OFF_BV 1184

// ---------------- Scratch (device globals; no allocation allowed) ----------------
__device__ __nv_bfloat16 g_Xs [(size_t)M_ * KS_];        // hidden [hi|lo|hi]   50 MB
__device__ __nv_bfloat16 g_Ws [(size_t)NPROJ_PAD * KS_]; // Wcat  [hi|hi|lo]   19 MB
__device__ __nv_bfloat16 g_Wos[(size_t)HID_ * KS_];      // W_o   [hi|hi|lo]   25 MB
__device__ __nv_bfloat16 g_Os [(size_t)M_ * KS_];        // attn out [hi|lo|hi] 50 MB
__device__ float g_Y[(size_t)M_ * NPROJ];                // projections fp32
__device__ float g_q[(size_t)B_*NH_*S_*HD_];             // [b][h][s][d]
__device__ float g_k[(size_t)B_*NH_*S_*HD_];
__device__ float g_v[(size_t)B_*NH_*S_*HD_];

// ---------------- helpers ----------------
__device__ __forceinline__ uint32_t smem_u32(const void* p) {
    uint32_t a;
    asm("{ .reg .u64 t; cvta.to.shared.u64 t, %1; cvt.u32.u64 %0, t; }" : "=r"(a) : "l"(p));
    return a;
}
__device__ __forceinline__ void split2(float x, __nv_bfloat16& h, __nv_bfloat16& l) {
    h = __float2bfloat16_rn(x);
    l = __float2bfloat16_rn(x - __bfloat162float(h));
}

// ---------------- Kernel: split fp32 -> 3-segment bf16 along K ----------------
// mode 0 (A-operand): [hi | lo | hi]    mode 1 (B-operand): [hi | hi | lo]
__global__ void split_fp32(const float* __restrict__ src, __nv_bfloat16* __restrict__ dst,
                           int rows, int cols, int mode)
{
    int idx = blockIdx.x * blockDim.x + threadIdx.x;
    int c4n = cols >> 2;
    if (idx >= rows * c4n) return;
    int r  = idx / c4n;
    int c  = (idx - r * c4n) << 2;
    float4 v = *(const float4*)(src + (size_t)r * cols + c);
    __nv_bfloat16 h[4], l[4];
    split2(v.x, h[0], l[0]); split2(v.y, h[1], l[1]);
    split2(v.z, h[2], l[2]); split2(v.w, h[3], l[3]);
    size_t base = (size_t)r * (3 * cols) + c;
    if (mode == 0) {   // hi | lo | hi
        *(uint2*)(dst + base)            = *(uint2*)h;
        *(uint2*)(dst + base + cols)     = *(uint2*)l;
        *(uint2*)(dst + base + 2*cols)   = *(uint2*)h;
    } else {           // hi | hi | lo
        *(uint2*)(dst + base)            = *(uint2*)h;
        *(uint2*)(dst + base + cols)     = *(uint2*)h;
        *(uint2*)(dst + base + 2*cols)   = *(uint2*)l;
    }
}

// ---------------- Kernel: concat 6 weight mats + split -> g_Ws [1536][6144] (B layout) ----------------
__global__ void concat_w_split(const float* __restrict__ waq, const float* __restrict__ wak,
                               const float* __restrict__ wav, const float* __restrict__ wbq,
                               const float* __restrict__ wbk, const float* __restrict__ wbv)
{
    int idx = blockIdx.x * blockDim.x + threadIdx.x;   // over 1536*512 float4s
    if (idx >= NPROJ_PAD * (HID_ / 4)) return;
    int row = idx >> 9;            // /512
    int c   = (idx & 511) << 2;
    float4 v = make_float4(0.f, 0.f, 0.f, 0.f);
    if (row < NPROJ) {
        const float* src; int r;
        if      (row < OFF_AK) { src = waq; r = row;          }
        else if (row < OFF_AV) { src = wak; r = row - OFF_AK; }
        else if (row < OFF_BQ) { src = wav; r = row - OFF_AV; }
        else if (row < OFF_BK) { src = wbq; r = row - OFF_BQ; }
        else if (row < OFF_BV) { src = wbk; r = row - OFF_BK; }   // FIXED (was OFF_BV)
        else                   { src = wbv; r = row - OFF_BV; }
        v = *(const float4*)(src + (size_t)r * HID_ + c);
    }
    __nv_bfloat16 h[4], l[4];
    split2(v.x, h[0], l[0]); split2(v.y, h[1], l[1]);
    split2(v.z, h[2], l[2]); split2(v.w, h[3], l[3]);
    size_t base = (size_t)row * KS_ + c;
    *(uint2*)(g_Ws + base)              = *(uint2*)h;   // hi
    *(uint2*)(g_Ws + base + HID_)       = *(uint2*)h;   // hi
    *(uint2*)(g_Ws + base + 2*HID_)     = *(uint2*)l;   // lo
}

// ---------------- HMMA bf16 GEMM (NT): C[M][Nreal] = A[M][Kp] * B[N][Kp]^T ----------------
// A,B bf16 row-major (K-inner). 128x128 tile, BK=32, 8 warps (4x2), warp tile 32x64.
#define BK_ 32
#define LDA_ 40   // padded row length in bf16 elems

__device__ __forceinline__ void ldmx4(uint32_t* r, uint32_t addr) {
    asm volatile("ldmatrix.sync.aligned.m8n8.x4.shared.b16 {%0,%1,%2,%3}, [%4];"
                 : "=r"(r[0]), "=r"(r[1]), "=r"(r[2]), "=r"(r[3]) : "r"(addr));
}
__device__ __forceinline__ void mma16816(float* c, const uint32_t* a, const uint32_t* b) {
    asm volatile(
        "mma.sync.aligned.m16n8k16.row.col.f32.bf16.bf16.f32 "
        "{%0,%1,%2,%3}, {%4,%5,%6,%7}, {%8,%9}, {%0,%1,%2,%3};"
        : "+f"(c[0]), "+f"(c[1]), "+f"(c[2]), "+f"(c[3])
        : "r"(a[0]), "r"(a[1]), "r"(a[2]), "r"(a[3]), "r"(b[0]), "r"(b[1]));
}

__global__ __launch_bounds__(256, 2)
void gemm_bf16(const __nv_bfloat16* __restrict__ A, const __nv_bfloat16* __restrict__ Bm,
               float* __restrict__ C, int Nreal, int ldc, int Kp)
{
    __shared__ __align__(16) __nv_bfloat16 sAB[2][2][128][LDA_];

    const int tid  = threadIdx.x;
    const int lane = tid & 31;
    const int wid  = tid >> 5;
    const int wm   = wid & 3;          // 0..3  -> m offset wm*32
    const int wn   = wid >> 2;         // 0..1  -> n offset wn*64
    const int bm   = blockIdx.y * 128;
    const int bn   = blockIdx.x * 128;

    // load assignment: row = tid>>1 (0..127), seg = tid&1 (16 elems each)
    const int lrow = tid >> 1;
    const int lseg = (tid & 1) * 16;
    const __nv_bfloat16* arow = A  + (size_t)(bm + lrow) * Kp + lseg;
    const __nv_bfloat16* brow = Bm + (size_t)(bn + lrow) * Kp + lseg;

    float acc[2][8][4];
    #pragma unroll
    for (int i = 0; i < 2; i++)
        #pragma unroll
        for (int j = 0; j < 8; j++)
            #pragma unroll
            for (int q = 0; q < 4; q++) acc[i][j][q] = 0.f;

    const int iters = Kp / BK_;

    // prologue: tile 0 -> buf 0
    {
        uint4 a0 = *(const uint4*)(arow);
        uint4 a1 = *(const uint4*)(arow + 8);
        uint4 b0 = *(const uint4*)(brow);
        uint4 b1 = *(const uint4*)(brow + 8);
        *(uint4*)&sAB[0][0][lrow][lseg]     = a0;
        *(uint4*)&sAB[0][0][lrow][lseg + 8] = a1;
        *(uint4*)&sAB[0][1][lrow][lseg]     = b0;
        *(uint4*)&sAB[0][1][lrow][lseg + 8] = b1;
    }
    __syncthreads();

    // fragment address lane math
    const int arow16 = lane & 15;
    const int akoff  = (lane >> 4) << 3;
    const int brow8  = (lane & 7) + ((lane >> 4) << 3);
    const int bkoff  = ((lane >> 3) & 1) << 3;

    for (int it = 0; it < iters; it++) {
        const int cur = it & 1;
        uint4 pa0, pa1, pb0, pb1;
        const bool pf = (it + 1 < iters);
        if (pf) {
            const int k0 = (it + 1) * BK_;
            pa0 = *(const uint4*)(arow + k0);
            pa1 = *(const uint4*)(arow + k0 + 8);
            pb0 = *(const uint4*)(brow + k0);
            pb1 = *(const uint4*)(brow + k0 + 8);
        }

        #pragma unroll
        for (int ks = 0; ks < 2; ks++) {
            const int k0 = ks * 16;
            uint32_t ar[2][4];
            #pragma unroll
            for (int mf = 0; mf < 2; mf++)
                ldmx4(ar[mf], smem_u32(&sAB[cur][0][wm * 32 + mf * 16 + arow16][k0 + akoff]));
            uint32_t br[8][2];
            #pragma unroll
            for (int nf2 = 0; nf2 < 4; nf2++) {
                uint32_t r[4];
                ldmx4(r, smem_u32(&sAB[cur][1][wn * 64 + nf2 * 16 + brow8][k0 + bkoff]));
                br[2*nf2][0] = r[0]; br[2*nf2][1] = r[1];
                br[2*nf2+1][0] = r[2]; br[2*nf2+1][1] = r[3];
            }
            #pragma unroll
            for (int mf = 0; mf < 2; mf++)
                #pragma unroll
                for (int nf = 0; nf < 8; nf++)
                    mma16816(acc[mf][nf], ar[mf], br[nf]);
        }

        if (pf) {
            const int nxt = cur ^ 1;
            __syncthreads();    // all warps done reading buf nxt (from iter it-1)
            *(uint4*)&sAB[nxt][0][lrow][lseg]     = pa0;
            *(uint4*)&sAB[nxt][0][lrow][lseg + 8] = pa1;
            *(uint4*)&sAB[nxt][1][lrow][lseg]     = pb0;
            *(uint4*)&sAB[nxt][1][lrow][lseg + 8] = pb1;
            __syncthreads();
        }
    }

    // epilogue
    #pragma unroll
    for (int mf = 0; mf < 2; mf++) {
        const int grow = bm + wm * 32 + mf * 16 + (lane >> 2);
        #pragma unroll
        for (int nf = 0; nf < 8; nf++) {
            const int gcol = bn + wn * 64 + nf * 8 + (lane & 3) * 2;
            if (gcol < Nreal) {
                *(float2*)(C + (size_t)grow * ldc + gcol) =
                    make_float2(acc[mf][nf][0], acc[mf][nf][1]);
                *(float2*)(C + (size_t)(grow + 8) * ldc + gcol) =
                    make_float2(acc[mf][nf][2], acc[mf][nf][3]);
            }
        }
    }
}

// ---------------- RoPE + rank contraction -> q,k,v [b][h][s][d] ----------------
__global__ void rope_contract_kernel(const float* __restrict__ cosb, const float* __restrict__ sinb)
{
    int token = blockIdx.x;              // b*S + s
    int b = token / S_;
    int s = token % S_;
    const float* y = g_Y + (size_t)token * NPROJ;
    int d = threadIdx.x;                 // 0..127

    __shared__ float sA[160];            // Aq(96) | Ak(32) | Av(32)
    for (int i = d; i < 160; i += 128) sA[i] = y[i];
    __syncthreads();

    int dh = d & 63;
    float c  = cosb[s * 64 + dh];
    float sn = sinb[s * 64 + dh];
    bool hi = (d >= 64);

    float bq[QR_], bk[KR_], bv[VR_];
    #pragma unroll
    for (int r = 0; r < QR_; r++) {
        float x1 = y[OFF_BQ + r * HD_ + dh];
        float x2 = y[OFF_BQ + r * HD_ + 64 + dh];
        bq[r] = hi ? (x1 * sn + x2 * c) : (x1 * c - x2 * sn);
    }
    #pragma unroll
    for (int r = 0; r < KR_; r++) {
        float x1 = y[OFF_BK + r * HD_ + dh];
        float x2 = y[OFF_BK + r * HD_ + 64 + dh];
        bk[r] = hi ? (x1 * sn + x2 * c) : (x1 * c - x2 * sn);
    }
    #pragma unroll
    for (int r = 0; r < VR_; r++) bv[r] = y[OFF_BV + r * HD_ + d];

    #pragma unroll
    for (int h = 0; h < NH_; h++) {
        float accq = 0.f, acck = 0.f, accv = 0.f;
        #pragma unroll
        for (int r = 0; r < QR_; r++) accq += sA[h * QR_ + r] * bq[r];
        #pragma unroll
        for (int r = 0; r < KR_; r++) acck += sA[96 + h * KR_ + r] * bk[r];
        #pragma unroll
        for (int r = 0; r < VR_; r++) accv += sA[128 + h * VR_ + r] * bv[r];
        size_t o = (((size_t)b * NH_ + h) * S_ + s) * HD_ + d;
        g_q[o] = accq * (SCALING_F / (float)QR_);
        g_k[o] = acck * (1.f / (float)KR_);
        g_v[o] = accv * (1.f / (float)VR_);
    }
}

// ---------------- Flash attention (fp32 SIMT); epilogue writes 3-seg split bf16 ----------------
#define QST_LD 68
#define SS_LD  68
#define ATT_SMEM_FLOATS (128*QST_LD + 128*QST_LD + 64*128 + 64*SS_LD + 192)
#define ATT_SMEM_BYTES  (ATT_SMEM_FLOATS * 4)

__global__ __launch_bounds__(256, 1)
void attn_kernel(const float* __restrict__ mask)
{
    extern __shared__ float smf[];
    float* Qst  = smf;
    float* Kst  = Qst + 128 * QST_LD;
    float* Vs   = Kst + 128 * QST_LD;
    float* Ss   = Vs  + 64 * 128;
    float* mrow = Ss  + 64 * SS_LD;
    float* lrow = mrow + 64;
    float* frow = lrow + 64;

    int tid = threadIdx.x;
    int q0  = blockIdx.x * 64;
    int h   = blockIdx.y;
    int b   = blockIdx.z;

    size_t headbase = ((size_t)b * NH_ + h) * S_ * HD_;
    const float* qp = g_q + headbase + (size_t)q0 * HD_;

    for (int t = tid; t < 64 * 32; t += 256) {
        int row = t >> 5, d4 = (t & 31) << 2;
        float4 val = *(const float4*)(qp + row * HD_ + d4);
        Qst[(d4 + 0) * QST_LD + row] = val.x;
        Qst[(d4 + 1) * QST_LD + row] = val.y;
        Qst[(d4 + 2) * QST_LD + row] = val.z;
        Qst[(d4 + 3) * QST_LD + row] = val.w;
    }
    if (tid < 64) { mrow[tid] = -INFINITY; lrow[tid] = 0.f; }

    float acc[4][8];
    #pragma unroll
    for (int i = 0; i < 4; i++)
        #pragma unroll
        for (int u = 0; u < 8; u++) acc[i][u] = 0.f;

    int tr = tid >> 4, tc = tid & 15;
    int sy = tr, sx = tc;
    const float* maskbase = mask + ((size_t)b * S_ + q0) * S_;

    for (int kv0 = 0; kv0 < S_; kv0 += 64) {
        const float* kp = g_k + headbase + (size_t)kv0 * HD_;
        const float* vp = g_v + headbase + (size_t)kv0 * HD_;
        for (int t = tid; t < 64 * 32; t += 256) {
            int row = t >> 5, d4 = (t & 31) << 2;
            float4 val = *(const float4*)(kp + row * HD_ + d4);
            Kst[(d4 + 0) * QST_LD + row] = val.x;
            Kst[(d4 + 1) * QST_LD + row] = val.y;
            Kst[(d4 + 2) * QST_LD + row] = val.z;
            Kst[(d4 + 3) * QST_LD + row] = val.w;
            ((float4*)Vs)[t] = *(const float4*)(vp + row * HD_ + d4);
        }
        __syncthreads();

        float sc[4][4];
        #pragma unroll
        for (int i = 0; i < 4; i++)
            #pragma unroll
            for (int j = 0; j < 4; j++) sc[i][j] = 0.f;

        #pragma unroll 8
        for (int kk = 0; kk < 128; kk++) {
            float4 a = *(const float4*)&Qst[kk * QST_LD + sy * 4];
            float4 bb = *(const float4*)&Kst[kk * QST_LD + sx * 4];
            float av[4] = {a.x, a.y, a.z, a.w};
            float bvv[4] = {bb.x, bb.y, bb.z, bb.w};
            #pragma unroll
            for (int i = 0; i < 4; i++)
                #pragma unroll
                for (int j = 0; j < 4; j++) sc[i][j] += av[i] * bvv[j];
        }

        #pragma unroll
        for (int i = 0; i < 4; i++) {
            int qr = sy * 4 + i;
            #pragma unroll
            for (int j = 0; j < 4; j++) {
                Ss[qr * SS_LD + sx * 4 + j] =
                    sc[i][j] + maskbase[(size_t)qr * S_ + kv0 + sx * 4 + j];
            }
        }
        __syncthreads();

        {
            int r = tid >> 2, g = tid & 3;
            float mloc = -INFINITY;
            #pragma unroll
            for (int cc = 0; cc < 16; cc++)
                mloc = fmaxf(mloc, Ss[r * SS_LD + g * 16 + cc]);
            mloc = fmaxf(mloc, __shfl_xor_sync(0xffffffffu, mloc, 1));
            mloc = fmaxf(mloc, __shfl_xor_sync(0xffffffffu, mloc, 2));
            float mold = mrow[r];
            float mnew = fmaxf(mold, mloc);
            float suml = 0.f;
            #pragma unroll
            for (int cc = 0; cc < 16; cc++) {
                float p = __expf(Ss[r * SS_LD + g * 16 + cc] - mnew);
                Ss[r * SS_LD + g * 16 + cc] = p;
                suml += p;
            }
            suml += __shfl_xor_sync(0xffffffffu, suml, 1);
            suml += __shfl_xor_sync(0xffffffffu, suml, 2);
            if (g == 0) {
                float f = __expf(mold - mnew);
                frow[r] = f;
                lrow[r] = lrow[r] * f + suml;
                mrow[r] = mnew;
            }
        }
        __syncthreads();

        float ff[4];
        #pragma unroll
        for (int i = 0; i < 4; i++) ff[i] = frow[tr * 4 + i];
        #pragma unroll
        for (int i = 0; i < 4; i++)
            #pragma unroll
            for (int u = 0; u < 8; u++) acc[i][u] *= ff[i];

        #pragma unroll 4
        for (int j = 0; j < 64; j++) {
            float p[4];
            #pragma unroll
            for (int i = 0; i < 4; i++) p[i] = Ss[(tr * 4 + i) * SS_LD + j];
            float4 v0 = *(const float4*)&Vs[j * 128 + tc * 8];
            float4 v1 = *(const float4*)&Vs[j * 128 + tc * 8 + 4];
            float vv[8] = {v0.x, v0.y, v0.z, v0.w, v1.x, v1.y, v1.z, v1.w};
            #pragma unroll
            for (int i = 0; i < 4; i++)
                #pragma unroll
                for (int u = 0; u < 8; u++) acc[i][u] += p[i] * vv[u];
        }
        __syncthreads();
    }

    // epilogue: normalize, write A-layout [hi | lo | hi] into g_Os [4096][6144]
    #pragma unroll
    for (int i = 0; i < 4; i++) {
        int qr = q0 + tr * 4 + i;
        float inv = 1.f / lrow[tr * 4 + i];
        size_t rowbase = ((size_t)b * S_ + qr) * KS_;
        size_t ohi = rowbase + h * HD_ + tc * 8;
        __nv_bfloat16 hbuf[8], lbuf[8];
        #pragma unroll
        for (int u = 0; u < 8; u++) split2(acc[i][u] * inv, hbuf[u], lbuf[u]);
        *(uint4*)(g_Os + ohi)            = *(uint4*)hbuf;
        *(uint4*)(g_Os + ohi + HID_)     = *(uint4*)lbuf;
        *(uint4*)(g_Os + ohi + 2*HID_)   = *(uint4*)hbuf;
    }
}

// ---------------- Host launcher ----------------
extern "C" void kernel_launch(void* const* d_in, const int* in_sizes, int n_in,
                              void* d_out, int out_size)
{
    const float* x    = (const float*)d_in[0];   // hidden_states [B,S,HID]
    const float* cosb = (const float*)d_in[1];   // freqs_cos [S,64]
    const float* sinb = (const float*)d_in[2];   // freqs_sin [S,64]
    // d_in[3] = kv_write_indices (unused by reference)
    const float* mask = (const float*)d_in[4];   // [B,1,S,S]
    const float* waq  = (const float*)d_in[5];
    const float* wak  = (const float*)d_in[6];
    const float* wav  = (const float*)d_in[7];
    const float* wbq  = (const float*)d_in[8];
    const float* wbk  = (const float*)d_in[9];
    const float* wbv  = (const float*)d_in[10];
    const float* wo   = (const float*)d_in[11];  // [HID, NH*HD]
    float* out = (float*)d_out;

    __nv_bfloat16 *pXs, *pWs, *pWos, *pOs;
    float *pY;
    cudaGetSymbolAddress((void**)&pXs,  g_Xs);
    cudaGetSymbolAddress((void**)&pWs,  g_Ws);
    cudaGetSymbolAddress((void**)&pWos, g_Wos);
    cudaGetSymbolAddress((void**)&pOs,  g_Os);
    cudaGetSymbolAddress((void**)&pY,   g_Y);

    // 1) conversions: X (A-layout), Wcat (B-layout), Wo (B-layout)
    split_fp32<<<(M_ * (HID_/4) + 255)/256, 256>>>(x, pXs, M_, HID_, 0);
    concat_w_split<<<(NPROJ_PAD * (HID_/4) + 255)/256, 256>>>(waq, wak, wav, wbq, wbk, wbv);
    split_fp32<<<(HID_ * (HID_/4) + 255)/256, 256>>>(wo, pWos, HID_, HID_, 1);

    // 2) projection GEMM (HMMA bf16 3-seg split): Y = X @ Wcat^T  [4096 x 1440]
    gemm_bf16<<<dim3(NPROJ_PAD/128, M_/128), 256>>>(pXs, pWs, pY, NPROJ, NPROJ, KS_);

    // 3) RoPE + contraction -> q,k,v
    rope_contract_kernel<<<M_, 128>>>(cosb, sinb);

    // 4) attention (SIMT fp32); writes 3-seg split bf16 output
    cudaFuncSetAttribute(attn_kernel, cudaFuncAttributeMaxDynamicSharedMemorySize, ATT_SMEM_BYTES);
    attn_kernel<<<dim3(S_/64, NH_, B_), 256, ATT_SMEM_BYTES>>>(mask);

    // 5) output GEMM (HMMA bf16 3-seg split): out = O @ W_o^T  [4096 x 2048]
    gemm_bf16<<<dim3(HID_/128, M_/128), 256>>>(pOs, pWos, out, HID_, HID_, KS_);
}

// round 8
// speedup vs baseline: 3.7273x; 1.7049x over previous
#include <cuda_runtime.h>
#include <cuda_bf16.h>
#include <math.h>
#include <stdint.h>

// ---------------- Problem constants ----------------
#define B_    2
#define S_    2048
#define HID_  2048
#define NH_   16
#define HD_   128
#define QR_   6
#define KR_   2
#define VR_   2
#define M_    (B_*S_)          // 4096 tokens
#define NPROJ 1440             // 96+32+32+768+256+256
#define NPROJ_PAD 1536
#define KS_   (3*HID_)         // 6144: A=[hi|lo|hi], B=[hi|hi|lo]
#define SCALING_F 0.08838834764831845f  // 128^-0.5

// Y row layout offsets
#define OFF_AQ 0
#define OFF_AK 96
#define OFF_AV 128
#define OFF_BQ 160
#define OFF_BK 928
#define OFF_BV 1184

// ---------------- Scratch (device globals; no allocation allowed) ----------------
__device__ __nv_bfloat16 g_Xs [(size_t)M_ * KS_];        // hidden [hi|lo|hi]
__device__ __nv_bfloat16 g_Ws [(size_t)NPROJ_PAD * KS_]; // Wcat  [hi|hi|lo]
__device__ __nv_bfloat16 g_Wos[(size_t)HID_ * KS_];      // W_o   [hi|hi|lo]
__device__ __nv_bfloat16 g_Os [(size_t)M_ * KS_];        // attn out [hi|lo|hi]
__device__ float g_Y[(size_t)M_ * NPROJ];                // projections fp32
__device__ __nv_bfloat16 g_qh[(size_t)B_*NH_*S_*HD_];    // [b][h][s][d] split bf16
__device__ __nv_bfloat16 g_ql[(size_t)B_*NH_*S_*HD_];
__device__ __nv_bfloat16 g_kh[(size_t)B_*NH_*S_*HD_];
__device__ __nv_bfloat16 g_kl[(size_t)B_*NH_*S_*HD_];
__device__ __nv_bfloat16 g_vh[(size_t)B_*NH_*S_*HD_];
__device__ __nv_bfloat16 g_vl[(size_t)B_*NH_*S_*HD_];

// ---------------- helpers ----------------
__device__ __forceinline__ uint32_t smem_u32(const void* p) {
    uint32_t a;
    asm("{ .reg .u64 t; cvta.to.shared.u64 t, %1; cvt.u32.u64 %0, t; }" : "=r"(a) : "l"(p));
    return a;
}
__device__ __forceinline__ void split2(float x, __nv_bfloat16& h, __nv_bfloat16& l) {
    h = __float2bfloat16_rn(x);
    l = __float2bfloat16_rn(x - __bfloat162float(h));
}
__device__ __forceinline__ void ldmx4(uint32_t* r, uint32_t addr) {
    asm volatile("ldmatrix.sync.aligned.m8n8.x4.shared.b16 {%0,%1,%2,%3}, [%4];"
                 : "=r"(r[0]), "=r"(r[1]), "=r"(r[2]), "=r"(r[3]) : "r"(addr));
}
__device__ __forceinline__ void ldmx4t(uint32_t* r, uint32_t addr) {
    asm volatile("ldmatrix.sync.aligned.m8n8.x4.trans.shared.b16 {%0,%1,%2,%3}, [%4];"
                 : "=r"(r[0]), "=r"(r[1]), "=r"(r[2]), "=r"(r[3]) : "r"(addr));
}
__device__ __forceinline__ void mma16816(float* c, const uint32_t* a, const uint32_t* b) {
    asm volatile(
        "mma.sync.aligned.m16n8k16.row.col.f32.bf16.bf16.f32 "
        "{%0,%1,%2,%3}, {%4,%5,%6,%7}, {%8,%9}, {%0,%1,%2,%3};"
        : "+f"(c[0]), "+f"(c[1]), "+f"(c[2]), "+f"(c[3])
        : "r"(a[0]), "r"(a[1]), "r"(a[2]), "r"(a[3]), "r"(b[0]), "r"(b[1]));
}

// ---------------- Kernel: split fp32 -> 3-segment bf16 along K ----------------
// mode 0 (A-operand): [hi | lo | hi]    mode 1 (B-operand): [hi | hi | lo]
__global__ void split_fp32(const float* __restrict__ src, __nv_bfloat16* __restrict__ dst,
                           int rows, int cols, int mode)
{
    int idx = blockIdx.x * blockDim.x + threadIdx.x;
    int c4n = cols >> 2;
    if (idx >= rows * c4n) return;
    int r  = idx / c4n;
    int c  = (idx - r * c4n) << 2;
    float4 v = *(const float4*)(src + (size_t)r * cols + c);
    __nv_bfloat16 h[4], l[4];
    split2(v.x, h[0], l[0]); split2(v.y, h[1], l[1]);
    split2(v.z, h[2], l[2]); split2(v.w, h[3], l[3]);
    size_t base = (size_t)r * (3 * cols) + c;
    if (mode == 0) {   // hi | lo | hi
        *(uint2*)(dst + base)            = *(uint2*)h;
        *(uint2*)(dst + base + cols)     = *(uint2*)l;
        *(uint2*)(dst + base + 2*cols)   = *(uint2*)h;
    } else {           // hi | hi | lo
        *(uint2*)(dst + base)            = *(uint2*)h;
        *(uint2*)(dst + base + cols)     = *(uint2*)h;
        *(uint2*)(dst + base + 2*cols)   = *(uint2*)l;
    }
}

// ---------------- Kernel: concat 6 weight mats + split -> g_Ws [1536][6144] (B layout) ----------------
__global__ void concat_w_split(const float* __restrict__ waq, const float* __restrict__ wak,
                               const float* __restrict__ wav, const float* __restrict__ wbq,
                               const float* __restrict__ wbk, const float* __restrict__ wbv)
{
    int idx = blockIdx.x * blockDim.x + threadIdx.x;   // over 1536*512 float4s
    if (idx >= NPROJ_PAD * (HID_ / 4)) return;
    int row = idx >> 9;            // /512
    int c   = (idx & 511) << 2;
    float4 v = make_float4(0.f, 0.f, 0.f, 0.f);
    if (row < NPROJ) {
        const float* src; int r;
        if      (row < OFF_AK) { src = waq; r = row;          }
        else if (row < OFF_AV) { src = wak; r = row - OFF_AK; }
        else if (row < OFF_BQ) { src = wav; r = row - OFF_AV; }
        else if (row < OFF_BK) { src = wbq; r = row - OFF_BQ; }
        else if (row < OFF_BV) { src = wbk; r = row - OFF_BK; }
        else                   { src = wbv; r = row - OFF_BV; }
        v = *(const float4*)(src + (size_t)r * HID_ + c);
    }
    __nv_bfloat16 h[4], l[4];
    split2(v.x, h[0], l[0]); split2(v.y, h[1], l[1]);
    split2(v.z, h[2], l[2]); split2(v.w, h[3], l[3]);
    size_t base = (size_t)row * KS_ + c;
    *(uint2*)(g_Ws + base)              = *(uint2*)h;   // hi
    *(uint2*)(g_Ws + base + HID_)       = *(uint2*)h;   // hi
    *(uint2*)(g_Ws + base + 2*HID_)     = *(uint2*)l;   // lo
}

// ---------------- HMMA bf16 GEMM (NT): unchanged from round 7 (verified) ----------------
#define BK_ 32
#define LDA_ 40

__global__ __launch_bounds__(256, 2)
void gemm_bf16(const __nv_bfloat16* __restrict__ A, const __nv_bfloat16* __restrict__ Bm,
               float* __restrict__ C, int Nreal, int ldc, int Kp)
{
    __shared__ __align__(16) __nv_bfloat16 sAB[2][2][128][LDA_];

    const int tid  = threadIdx.x;
    const int lane = tid & 31;
    const int wid  = tid >> 5;
    const int wm   = wid & 3;
    const int wn   = wid >> 2;
    const int bm   = blockIdx.y * 128;
    const int bn   = blockIdx.x * 128;

    const int lrow = tid >> 1;
    const int lseg = (tid & 1) * 16;
    const __nv_bfloat16* arow = A  + (size_t)(bm + lrow) * Kp + lseg;
    const __nv_bfloat16* brow = Bm + (size_t)(bn + lrow) * Kp + lseg;

    float acc[2][8][4];
    #pragma unroll
    for (int i = 0; i < 2; i++)
        #pragma unroll
        for (int j = 0; j < 8; j++)
            #pragma unroll
            for (int q = 0; q < 4; q++) acc[i][j][q] = 0.f;

    const int iters = Kp / BK_;

    {
        uint4 a0 = *(const uint4*)(arow);
        uint4 a1 = *(const uint4*)(arow + 8);
        uint4 b0 = *(const uint4*)(brow);
        uint4 b1 = *(const uint4*)(brow + 8);
        *(uint4*)&sAB[0][0][lrow][lseg]     = a0;
        *(uint4*)&sAB[0][0][lrow][lseg + 8] = a1;
        *(uint4*)&sAB[0][1][lrow][lseg]     = b0;
        *(uint4*)&sAB[0][1][lrow][lseg + 8] = b1;
    }
    __syncthreads();

    const int arow16 = lane & 15;
    const int akoff  = (lane >> 4) << 3;
    const int brow8  = (lane & 7) + ((lane >> 4) << 3);
    const int bkoff  = ((lane >> 3) & 1) << 3;

    for (int it = 0; it < iters; it++) {
        const int cur = it & 1;
        uint4 pa0, pa1, pb0, pb1;
        const bool pf = (it + 1 < iters);
        if (pf) {
            const int k0 = (it + 1) * BK_;
            pa0 = *(const uint4*)(arow + k0);
            pa1 = *(const uint4*)(arow + k0 + 8);
            pb0 = *(const uint4*)(brow + k0);
            pb1 = *(const uint4*)(brow + k0 + 8);
        }

        #pragma unroll
        for (int ks = 0; ks < 2; ks++) {
            const int k0 = ks * 16;
            uint32_t ar[2][4];
            #pragma unroll
            for (int mf = 0; mf < 2; mf++)
                ldmx4(ar[mf], smem_u32(&sAB[cur][0][wm * 32 + mf * 16 + arow16][k0 + akoff]));
            uint32_t br[8][2];
            #pragma unroll
            for (int nf2 = 0; nf2 < 4; nf2++) {
                uint32_t r[4];
                ldmx4(r, smem_u32(&sAB[cur][1][wn * 64 + nf2 * 16 + brow8][k0 + bkoff]));
                br[2*nf2][0] = r[0]; br[2*nf2][1] = r[1];
                br[2*nf2+1][0] = r[2]; br[2*nf2+1][1] = r[3];
            }
            #pragma unroll
            for (int mf = 0; mf < 2; mf++)
                #pragma unroll
                for (int nf = 0; nf < 8; nf++)
                    mma16816(acc[mf][nf], ar[mf], br[nf]);
        }

        if (pf) {
            const int nxt = cur ^ 1;
            __syncthreads();
            *(uint4*)&sAB[nxt][0][lrow][lseg]     = pa0;
            *(uint4*)&sAB[nxt][0][lrow][lseg + 8] = pa1;
            *(uint4*)&sAB[nxt][1][lrow][lseg]     = pb0;
            *(uint4*)&sAB[nxt][1][lrow][lseg + 8] = pb1;
            __syncthreads();
        }
    }

    #pragma unroll
    for (int mf = 0; mf < 2; mf++) {
        const int grow = bm + wm * 32 + mf * 16 + (lane >> 2);
        #pragma unroll
        for (int nf = 0; nf < 8; nf++) {
            const int gcol = bn + wn * 64 + nf * 8 + (lane & 3) * 2;
            if (gcol < Nreal) {
                *(float2*)(C + (size_t)grow * ldc + gcol) =
                    make_float2(acc[mf][nf][0], acc[mf][nf][1]);
                *(float2*)(C + (size_t)(grow + 8) * ldc + gcol) =
                    make_float2(acc[mf][nf][2], acc[mf][nf][3]);
            }
        }
    }
}

// ---------------- RoPE + rank contraction -> split bf16 q,k,v [b][h][s][d] ----------------
__global__ void rope_contract_kernel(const float* __restrict__ cosb, const float* __restrict__ sinb)
{
    int token = blockIdx.x;              // b*S + s
    int b = token / S_;
    int s = token % S_;
    const float* y = g_Y + (size_t)token * NPROJ;
    int d = threadIdx.x;                 // 0..127

    __shared__ float sA[160];            // Aq(96) | Ak(32) | Av(32)
    for (int i = d; i < 160; i += 128) sA[i] = y[i];
    __syncthreads();

    int dh = d & 63;
    float c  = cosb[s * 64 + dh];
    float sn = sinb[s * 64 + dh];
    bool hi = (d >= 64);

    float bq[QR_], bk[KR_], bv[VR_];
    #pragma unroll
    for (int r = 0; r < QR_; r++) {
        float x1 = y[OFF_BQ + r * HD_ + dh];
        float x2 = y[OFF_BQ + r * HD_ + 64 + dh];
        bq[r] = hi ? (x1 * sn + x2 * c) : (x1 * c - x2 * sn);
    }
    #pragma unroll
    for (int r = 0; r < KR_; r++) {
        float x1 = y[OFF_BK + r * HD_ + dh];
        float x2 = y[OFF_BK + r * HD_ + 64 + dh];
        bk[r] = hi ? (x1 * sn + x2 * c) : (x1 * c - x2 * sn);
    }
    #pragma unroll
    for (int r = 0; r < VR_; r++) bv[r] = y[OFF_BV + r * HD_ + d];

    #pragma unroll
    for (int h = 0; h < NH_; h++) {
        float accq = 0.f, acck = 0.f, accv = 0.f;
        #pragma unroll
        for (int r = 0; r < QR_; r++) accq += sA[h * QR_ + r] * bq[r];
        #pragma unroll
        for (int r = 0; r < KR_; r++) acck += sA[96 + h * KR_ + r] * bk[r];
        #pragma unroll
        for (int r = 0; r < VR_; r++) accv += sA[128 + h * VR_ + r] * bv[r];
        size_t o = (((size_t)b * NH_ + h) * S_ + s) * HD_ + d;
        __nv_bfloat16 hh, ll;
        split2(accq * (SCALING_F / (float)QR_), hh, ll);
        g_qh[o] = hh; g_ql[o] = ll;
        split2(acck * (1.f / (float)KR_), hh, ll);
        g_kh[o] = hh; g_kl[o] = ll;
        split2(accv * (1.f / (float)VR_), hh, ll);
        g_vh[o] = hh; g_vl[o] = ll;
    }
}

// ---------------- Flash attention: HMMA split-bf16 QK^T and PV, SIMT softmax ----------------
#define AQ_LD 136   // bf16 row stride for Q/K/V tiles (272B, conflict-free ldmatrix)
#define AP_LD 72    // bf16 row stride for P tiles (144B)
#define SS_LD 68    // fp32 row stride for scores

#define SM_QH 0
#define SM_QL (SM_QH + 64*AQ_LD*2)
#define SM_KH (SM_QL + 64*AQ_LD*2)
#define SM_KL (SM_KH + 64*AQ_LD*2)
#define SM_VH (SM_KL + 64*AQ_LD*2)
#define SM_VL (SM_VH + 64*AQ_LD*2)
#define SM_PH (SM_VL + 64*AQ_LD*2)
#define SM_PL (SM_PH + 64*AP_LD*2)
#define SM_SS (SM_PL + 64*AP_LD*2)
#define SM_MR (SM_SS + 64*SS_LD*4)
#define SM_LR (SM_MR + 256)
#define SM_FR (SM_LR + 256)
#define ATT_SMEM_BYTES (SM_FR + 256)

__global__ __launch_bounds__(256, 1)
void attn_kernel(const float* __restrict__ mask)
{
    extern __shared__ char smc[];
    __nv_bfloat16* Qh_s = (__nv_bfloat16*)(smc + SM_QH);
    __nv_bfloat16* Ql_s = (__nv_bfloat16*)(smc + SM_QL);
    __nv_bfloat16* Kh_s = (__nv_bfloat16*)(smc + SM_KH);
    __nv_bfloat16* Kl_s = (__nv_bfloat16*)(smc + SM_KL);
    __nv_bfloat16* Vh_s = (__nv_bfloat16*)(smc + SM_VH);
    __nv_bfloat16* Vl_s = (__nv_bfloat16*)(smc + SM_VL);
    __nv_bfloat16* Ph_s = (__nv_bfloat16*)(smc + SM_PH);
    __nv_bfloat16* Pl_s = (__nv_bfloat16*)(smc + SM_PL);
    float* Ss   = (float*)(smc + SM_SS);
    float* mrow = (float*)(smc + SM_MR);
    float* lrow = (float*)(smc + SM_LR);
    float* frow = (float*)(smc + SM_FR);

    const int tid  = threadIdx.x;
    const int lane = tid & 31;
    const int wid  = tid >> 5;
    const int wq   = wid & 3;     // q-row group: rows wq*16..+15
    const int wk   = wid >> 2;    // QK col group (32) / PV col group (64)
    const int q0   = blockIdx.x * 64;
    const int h    = blockIdx.y;
    const int b    = blockIdx.z;

    const size_t headbase = ((size_t)b * NH_ + h) * S_ * HD_;

    // ---- load Q tile (hi, lo) ----
    {
        int row = tid >> 2, cg = (tid & 3) * 32;
        const size_t go = headbase + (size_t)(q0 + row) * HD_ + cg;
        #pragma unroll
        for (int j = 0; j < 4; j++) {
            *(uint4*)&Qh_s[row * AQ_LD + cg + j*8] = *(const uint4*)(g_qh + go + j*8);
            *(uint4*)&Ql_s[row * AQ_LD + cg + j*8] = *(const uint4*)(g_ql + go + j*8);
        }
    }
    if (tid < 64) { mrow[tid] = -INFINITY; lrow[tid] = 0.f; }

    float acc[8][4];
    #pragma unroll
    for (int i = 0; i < 8; i++)
        #pragma unroll
        for (int j = 0; j < 4; j++) acc[i][j] = 0.f;

    const int arow  = lane & 15;
    const int akoff = (lane >> 4) << 3;
    const int brow8 = (lane & 7) + ((lane >> 4) << 3);
    const int bkoff = ((lane >> 3) & 1) << 3;
    const float* maskbase = mask + ((size_t)b * S_ + q0) * S_;

    for (int kv0 = 0; kv0 < S_; kv0 += 64) {
        // ---- load K, V tiles (hi, lo) ----
        {
            int row = tid >> 2, cg = (tid & 3) * 32;
            const size_t go = headbase + (size_t)(kv0 + row) * HD_ + cg;
            #pragma unroll
            for (int j = 0; j < 4; j++) {
                *(uint4*)&Kh_s[row * AQ_LD + cg + j*8] = *(const uint4*)(g_kh + go + j*8);
                *(uint4*)&Kl_s[row * AQ_LD + cg + j*8] = *(const uint4*)(g_kl + go + j*8);
                *(uint4*)&Vh_s[row * AQ_LD + cg + j*8] = *(const uint4*)(g_vh + go + j*8);
                *(uint4*)&Vl_s[row * AQ_LD + cg + j*8] = *(const uint4*)(g_vl + go + j*8);
            }
        }
        __syncthreads();

        // ---- QK^T (3-term split): warp tile 16 x 32 ----
        float sc[4][4];
        #pragma unroll
        for (int i = 0; i < 4; i++)
            #pragma unroll
            for (int j = 0; j < 4; j++) sc[i][j] = 0.f;

        #pragma unroll
        for (int k0 = 0; k0 < 128; k0 += 16) {
            uint32_t ah[4], al[4];
            const int aoff = (wq * 16 + arow) * AQ_LD + k0 + akoff;
            ldmx4(ah, smem_u32(&Qh_s[aoff]));
            ldmx4(al, smem_u32(&Ql_s[aoff]));
            #pragma unroll
            for (int nb = 0; nb < 2; nb++) {
                uint32_t bh[4], bl[4];
                const int boff = (wk * 32 + nb * 16 + brow8) * AQ_LD + k0 + bkoff;
                ldmx4(bh, smem_u32(&Kh_s[boff]));
                ldmx4(bl, smem_u32(&Kl_s[boff]));
                mma16816(sc[nb*2],   ah, bh);     mma16816(sc[nb*2+1], ah, bh + 2);
                mma16816(sc[nb*2],   al, bh);     mma16816(sc[nb*2+1], al, bh + 2);
                mma16816(sc[nb*2],   ah, bl);     mma16816(sc[nb*2+1], ah, bl + 2);
            }
        }

        // ---- store scores + mask ----
        {
            const int r0 = wq * 16 + (lane >> 2);
            const float* mp0 = maskbase + (size_t)r0 * S_ + kv0 + wk * 32;
            const float* mp1 = mp0 + (size_t)8 * S_;
            #pragma unroll
            for (int nf = 0; nf < 4; nf++) {
                int cl = nf * 8 + (lane & 3) * 2;
                int c  = wk * 32 + cl;
                float2 m0 = *(const float2*)(mp0 + cl);
                float2 m1 = *(const float2*)(mp1 + cl);
                Ss[r0 * SS_LD + c]           = sc[nf][0] + m0.x;
                Ss[r0 * SS_LD + c + 1]       = sc[nf][1] + m0.y;
                Ss[(r0 + 8) * SS_LD + c]     = sc[nf][2] + m1.x;
                Ss[(r0 + 8) * SS_LD + c + 1] = sc[nf][3] + m1.y;
            }
        }
        __syncthreads();

        // ---- online softmax (verified SIMT code) ----
        {
            int r = tid >> 2, g = tid & 3;
            float mloc = -INFINITY;
            #pragma unroll
            for (int cc = 0; cc < 16; cc++)
                mloc = fmaxf(mloc, Ss[r * SS_LD + g * 16 + cc]);
            mloc = fmaxf(mloc, __shfl_xor_sync(0xffffffffu, mloc, 1));
            mloc = fmaxf(mloc, __shfl_xor_sync(0xffffffffu, mloc, 2));
            float mold = mrow[r];
            float mnew = fmaxf(mold, mloc);
            float suml = 0.f;
            #pragma unroll
            for (int cc = 0; cc < 16; cc++) {
                float p = __expf(Ss[r * SS_LD + g * 16 + cc] - mnew);
                Ss[r * SS_LD + g * 16 + cc] = p;
                suml += p;
            }
            suml += __shfl_xor_sync(0xffffffffu, suml, 1);
            suml += __shfl_xor_sync(0xffffffffu, suml, 2);
            if (g == 0) {
                float f = __expf(mold - mnew);
                frow[r] = f;
                lrow[r] = lrow[r] * f + suml;
                mrow[r] = mnew;
            }
        }
        __syncthreads();

        // ---- convert P -> bf16 hi/lo ----
        {
            int row = tid >> 2, cg = (tid & 3) * 16;
            __nv_bfloat16 hh[8], ll[8];
            #pragma unroll
            for (int half = 0; half < 2; half++) {
                #pragma unroll
                for (int j = 0; j < 2; j++) {
                    float4 v = *(float4*)&Ss[row * SS_LD + cg + half * 8 + j * 4];
                    split2(v.x, hh[j*4+0], ll[j*4+0]);
                    split2(v.y, hh[j*4+1], ll[j*4+1]);
                    split2(v.z, hh[j*4+2], ll[j*4+2]);
                    split2(v.w, hh[j*4+3], ll[j*4+3]);
                }
                *(uint4*)&Ph_s[row * AP_LD + cg + half * 8] = *(uint4*)hh;
                *(uint4*)&Pl_s[row * AP_LD + cg + half * 8] = *(uint4*)ll;
            }
        }
        __syncthreads();

        // ---- rescale acc + PV (3-term split): warp tile 16 x 64 ----
        {
            const float f0 = frow[wq * 16 + (lane >> 2)];
            const float f1 = frow[wq * 16 + 8 + (lane >> 2)];
            #pragma unroll
            for (int nf = 0; nf < 8; nf++) {
                acc[nf][0] *= f0; acc[nf][1] *= f0;
                acc[nf][2] *= f1; acc[nf][3] *= f1;
            }
            #pragma unroll
            for (int k0 = 0; k0 < 64; k0 += 16) {
                uint32_t ah[4], al[4];
                const int aoff = (wq * 16 + arow) * AP_LD + k0 + akoff;
                ldmx4(ah, smem_u32(&Ph_s[aoff]));
                ldmx4(al, smem_u32(&Pl_s[aoff]));
                #pragma unroll
                for (int nb = 0; nb < 4; nb++) {
                    uint32_t vh[4], vl[4];
                    const int voff = (k0 + arow) * AQ_LD + wk * 64 + nb * 16 + akoff;
                    ldmx4t(vh, smem_u32(&Vh_s[voff]));
                    ldmx4t(vl, smem_u32(&Vl_s[voff]));
                    mma16816(acc[nb*2],   ah, vh);     mma16816(acc[nb*2+1], ah, vh + 2);
                    mma16816(acc[nb*2],   al, vh);     mma16816(acc[nb*2+1], al, vh + 2);
                    mma16816(acc[nb*2],   ah, vl);     mma16816(acc[nb*2+1], ah, vl + 2);
                }
            }
        }
        __syncthreads();
    }

    // ---- epilogue: normalize, write A-layout [hi|lo|hi] into g_Os ----
    {
        const int r0 = wq * 16 + (lane >> 2);
        const float inv0 = 1.f / lrow[r0];
        const float inv1 = 1.f / lrow[r0 + 8];
        const size_t row0 = ((size_t)b * S_ + q0 + r0) * KS_ + h * HD_;
        const size_t row1 = ((size_t)b * S_ + q0 + r0 + 8) * KS_ + h * HD_;
        #pragma unroll
        for (int nf = 0; nf < 8; nf++) {
            const int c = wk * 64 + nf * 8 + (lane & 3) * 2;
            __nv_bfloat16 h2[2], l2[2];
            split2(acc[nf][0] * inv0, h2[0], l2[0]);
            split2(acc[nf][1] * inv0, h2[1], l2[1]);
            *(uint32_t*)(g_Os + row0 + c)            = *(uint32_t*)h2;
            *(uint32_t*)(g_Os + row0 + c + HID_)     = *(uint32_t*)l2;
            *(uint32_t*)(g_Os + row0 + c + 2*HID_)   = *(uint32_t*)h2;
            split2(acc[nf][2] * inv1, h2[0], l2[0]);
            split2(acc[nf][3] * inv1, h2[1], l2[1]);
            *(uint32_t*)(g_Os + row1 + c)            = *(uint32_t*)h2;
            *(uint32_t*)(g_Os + row1 + c + HID_)     = *(uint32_t*)l2;
            *(uint32_t*)(g_Os + row1 + c + 2*HID_)   = *(uint32_t*)h2;
        }
    }
}

// ---------------- Host launcher ----------------
extern "C" void kernel_launch(void* const* d_in, const int* in_sizes, int n_in,
                              void* d_out, int out_size)
{
    const float* x    = (const float*)d_in[0];   // hidden_states [B,S,HID]
    const float* cosb = (const float*)d_in[1];   // freqs_cos [S,64]
    const float* sinb = (const float*)d_in[2];   // freqs_sin [S,64]
    // d_in[3] = kv_write_indices (unused by reference)
    const float* mask = (const float*)d_in[4];   // [B,1,S,S]
    const float* waq  = (const float*)d_in[5];
    const float* wak  = (const float*)d_in[6];
    const float* wav  = (const float*)d_in[7];
    const float* wbq  = (const float*)d_in[8];
    const float* wbk  = (const float*)d_in[9];
    const float* wbv  = (const float*)d_in[10];
    const float* wo   = (const float*)d_in[11];  // [HID, NH*HD]
    float* out = (float*)d_out;

    __nv_bfloat16 *pXs, *pWs, *pWos, *pOs;
    float *pY;
    cudaGetSymbolAddress((void**)&pXs,  g_Xs);
    cudaGetSymbolAddress((void**)&pWs,  g_Ws);
    cudaGetSymbolAddress((void**)&pWos, g_Wos);
    cudaGetSymbolAddress((void**)&pOs,  g_Os);
    cudaGetSymbolAddress((void**)&pY,   g_Y);

    // 1) conversions: X (A-layout), Wcat (B-layout), Wo (B-layout)
    split_fp32<<<(M_ * (HID_/4) + 255)/256, 256>>>(x, pXs, M_, HID_, 0);
    concat_w_split<<<(NPROJ_PAD * (HID_/4) + 255)/256, 256>>>(waq, wak, wav, wbq, wbk, wbv);
    split_fp32<<<(HID_ * (HID_/4) + 255)/256, 256>>>(wo, pWos, HID_, HID_, 1);

    // 2) projection GEMM (HMMA bf16 3-seg split): Y = X @ Wcat^T  [4096 x 1440]
    gemm_bf16<<<dim3(NPROJ_PAD/128, M_/128), 256>>>(pXs, pWs, pY, NPROJ, NPROJ, KS_);

    // 3) RoPE + contraction -> split bf16 q,k,v
    rope_contract_kernel<<<M_, 128>>>(cosb, sinb);

    // 4) attention (HMMA split-bf16 QK^T + PV, SIMT softmax)
    cudaFuncSetAttribute(attn_kernel, cudaFuncAttributeMaxDynamicSharedMemorySize, ATT_SMEM_BYTES);
    attn_kernel<<<dim3(S_/64, NH_, B_), 256, ATT_SMEM_BYTES>>>(mask);

    // 5) output GEMM (HMMA bf16 3-seg split): out = O @ W_o^T  [4096 x 2048]
    gemm_bf16<<<dim3(HID_/128, M_/128), 256>>>(pOs, pWos, out, HID_, HID_, KS_);
}

// round 9
// speedup vs baseline: 4.4891x; 1.2044x over previous
#include <cuda_runtime.h>
#include <cuda_bf16.h>
#include <math.h>
#include <stdint.h>

// ---------------- Problem constants ----------------
#define B_    2
#define S_    2048
#define HID_  2048
#define NH_   16
#define HD_   128
#define QR_   6
#define KR_   2
#define VR_   2
#define M_    (B_*S_)          // 4096 tokens
#define NPROJ 1440
#define NPROJ_PAD 1536
#define KS_   (3*HID_)         // 6144: A=[hi|lo|hi], B=[hi|hi|lo]
#define SCALING_F 0.08838834764831845f  // 128^-0.5

// Y row layout offsets
#define OFF_AQ 0
#define OFF_AK 96
#define OFF_AV 128
#define OFF_BQ 160
#define OFF_BK 928
#define OFF_BV 1184

// ---------------- Scratch (device globals; no allocation allowed) ----------------
__device__ __nv_bfloat16 g_Xs [(size_t)M_ * KS_];        // hidden [hi|lo|hi]
__device__ __nv_bfloat16 g_Ws [(size_t)NPROJ_PAD * KS_]; // Wcat  [hi|hi|lo]
__device__ __nv_bfloat16 g_Wos[(size_t)HID_ * KS_];      // W_o   [hi|hi|lo]
__device__ __nv_bfloat16 g_Os [(size_t)M_ * KS_];        // attn out [hi|lo|hi]
__device__ float g_Y[(size_t)M_ * NPROJ];                // projections fp32
__device__ __nv_bfloat16 g_qh[(size_t)B_*NH_*S_*HD_];    // [b][h][s][d] split bf16
__device__ __nv_bfloat16 g_ql[(size_t)B_*NH_*S_*HD_];
__device__ __nv_bfloat16 g_kh[(size_t)B_*NH_*S_*HD_];
__device__ __nv_bfloat16 g_kl[(size_t)B_*NH_*S_*HD_];
__device__ __nv_bfloat16 g_vh[(size_t)B_*NH_*S_*HD_];
__device__ __nv_bfloat16 g_vl[(size_t)B_*NH_*S_*HD_];

// ---------------- helpers ----------------
__device__ __forceinline__ uint32_t smem_u32(const void* p) {
    uint32_t a;
    asm("{ .reg .u64 t; cvta.to.shared.u64 t, %1; cvt.u32.u64 %0, t; }" : "=r"(a) : "l"(p));
    return a;
}
__device__ __forceinline__ void split2(float x, __nv_bfloat16& h, __nv_bfloat16& l) {
    h = __float2bfloat16_rn(x);
    l = __float2bfloat16_rn(x - __bfloat162float(h));
}
__device__ __forceinline__ void packsplit(float a, float b, uint32_t& ph, uint32_t& pl) {
    __nv_bfloat16 ha, la, hb, lb;
    split2(a, ha, la); split2(b, hb, lb);
    __nv_bfloat162 H; H.x = ha; H.y = hb;
    __nv_bfloat162 L; L.x = la; L.y = lb;
    ph = *(uint32_t*)&H; pl = *(uint32_t*)&L;
}
__device__ __forceinline__ void ldmx4(uint32_t* r, uint32_t addr) {
    asm volatile("ldmatrix.sync.aligned.m8n8.x4.shared.b16 {%0,%1,%2,%3}, [%4];"
                 : "=r"(r[0]), "=r"(r[1]), "=r"(r[2]), "=r"(r[3]) : "r"(addr));
}
__device__ __forceinline__ void ldmx4t(uint32_t* r, uint32_t addr) {
    asm volatile("ldmatrix.sync.aligned.m8n8.x4.trans.shared.b16 {%0,%1,%2,%3}, [%4];"
                 : "=r"(r[0]), "=r"(r[1]), "=r"(r[2]), "=r"(r[3]) : "r"(addr));
}
__device__ __forceinline__ void mma16816(float* c, const uint32_t* a, const uint32_t* b) {
    asm volatile(
        "mma.sync.aligned.m16n8k16.row.col.f32.bf16.bf16.f32 "
        "{%0,%1,%2,%3}, {%4,%5,%6,%7}, {%8,%9}, {%0,%1,%2,%3};"
        : "+f"(c[0]), "+f"(c[1]), "+f"(c[2]), "+f"(c[3])
        : "r"(a[0]), "r"(a[1]), "r"(a[2]), "r"(a[3]), "r"(b[0]), "r"(b[1]));
}
#define CP16(dst, src) \
    asm volatile("cp.async.cg.shared.global [%0], [%1], 16;" \
                 :: "r"(dst), "l"((size_t)__cvta_generic_to_global(src)) : "memory")
#define CP_COMMIT() asm volatile("cp.async.commit_group;" ::: "memory")
#define CP_WAIT0()  asm volatile("cp.async.wait_group 0;" ::: "memory")

// ---------------- Kernel: split fp32 -> 3-segment bf16 along K ----------------
// mode 0 (A-operand): [hi | lo | hi]    mode 1 (B-operand): [hi | hi | lo]
__global__ void split_fp32(const float* __restrict__ src, __nv_bfloat16* __restrict__ dst,
                           int rows, int cols, int mode)
{
    int idx = blockIdx.x * blockDim.x + threadIdx.x;
    int c4n = cols >> 2;
    if (idx >= rows * c4n) return;
    int r  = idx / c4n;
    int c  = (idx - r * c4n) << 2;
    float4 v = *(const float4*)(src + (size_t)r * cols + c);
    __nv_bfloat16 h[4], l[4];
    split2(v.x, h[0], l[0]); split2(v.y, h[1], l[1]);
    split2(v.z, h[2], l[2]); split2(v.w, h[3], l[3]);
    size_t base = (size_t)r * (3 * cols) + c;
    if (mode == 0) {
        *(uint2*)(dst + base)            = *(uint2*)h;
        *(uint2*)(dst + base + cols)     = *(uint2*)l;
        *(uint2*)(dst + base + 2*cols)   = *(uint2*)h;
    } else {
        *(uint2*)(dst + base)            = *(uint2*)h;
        *(uint2*)(dst + base + cols)     = *(uint2*)h;
        *(uint2*)(dst + base + 2*cols)   = *(uint2*)l;
    }
}

// ---------------- Kernel: concat 6 weight mats + split -> g_Ws (B layout) ----------------
__global__ void concat_w_split(const float* __restrict__ waq, const float* __restrict__ wak,
                               const float* __restrict__ wav, const float* __restrict__ wbq,
                               const float* __restrict__ wbk, const float* __restrict__ wbv)
{
    int idx = blockIdx.x * blockDim.x + threadIdx.x;
    if (idx >= NPROJ_PAD * (HID_ / 4)) return;
    int row = idx >> 9;
    int c   = (idx & 511) << 2;
    float4 v = make_float4(0.f, 0.f, 0.f, 0.f);
    if (row < NPROJ) {
        const float* src; int r;
        if      (row < OFF_AK) { src = waq; r = row;          }
        else if (row < OFF_AV) { src = wak; r = row - OFF_AK; }
        else if (row < OFF_BQ) { src = wav; r = row - OFF_AV; }
        else if (row < OFF_BK) { src = wbq; r = row - OFF_BQ; }
        else if (row < OFF_BV) { src = wbk; r = row - OFF_BK; }
        else                   { src = wbv; r = row - OFF_BV; }
        v = *(const float4*)(src + (size_t)r * HID_ + c);
    }
    __nv_bfloat16 h[4], l[4];
    split2(v.x, h[0], l[0]); split2(v.y, h[1], l[1]);
    split2(v.z, h[2], l[2]); split2(v.w, h[3], l[3]);
    size_t base = (size_t)row * KS_ + c;
    *(uint2*)(g_Ws + base)              = *(uint2*)h;
    *(uint2*)(g_Ws + base + HID_)       = *(uint2*)h;
    *(uint2*)(g_Ws + base + 2*HID_)     = *(uint2*)l;
}

// ---------------- HMMA bf16 GEMM (NT) with cp.async double-buffer ----------------
#define BK_ 32
#define LDA_ 40

__global__ __launch_bounds__(256, 2)
void gemm_bf16(const __nv_bfloat16* __restrict__ A, const __nv_bfloat16* __restrict__ Bm,
               float* __restrict__ C, int Nreal, int ldc, int Kp)
{
    __shared__ __align__(16) __nv_bfloat16 sAB[2][2][128][LDA_];

    const int tid  = threadIdx.x;
    const int lane = tid & 31;
    const int wid  = tid >> 5;
    const int wm   = wid & 3;
    const int wn   = wid >> 2;
    const int bm   = blockIdx.y * 128;
    const int bn   = blockIdx.x * 128;

    const int lrow = tid >> 1;
    const int lseg = (tid & 1) * 16;
    const __nv_bfloat16* arow = A  + (size_t)(bm + lrow) * Kp + lseg;
    const __nv_bfloat16* brow = Bm + (size_t)(bn + lrow) * Kp + lseg;

    float acc[2][8][4];
    #pragma unroll
    for (int i = 0; i < 2; i++)
        #pragma unroll
        for (int j = 0; j < 8; j++)
            #pragma unroll
            for (int q = 0; q < 4; q++) acc[i][j][q] = 0.f;

    const int iters = Kp / BK_;

    auto issue = [&](int it, int bi) {
        const __nv_bfloat16* as = arow + it * BK_;
        const __nv_bfloat16* bs = brow + it * BK_;
        uint32_t da = smem_u32(&sAB[bi][0][lrow][lseg]);
        uint32_t db = smem_u32(&sAB[bi][1][lrow][lseg]);
        CP16(da,      as);
        CP16(da + 16, as + 8);
        CP16(db,      bs);
        CP16(db + 16, bs + 8);
        CP_COMMIT();
    };

    issue(0, 0);
    CP_WAIT0();
    __syncthreads();

    const int arow16 = lane & 15;
    const int akoff  = (lane >> 4) << 3;
    const int brow8  = (lane & 7) + ((lane >> 4) << 3);
    const int bkoff  = ((lane >> 3) & 1) << 3;

    for (int it = 0; it < iters; it++) {
        const int cur = it & 1;
        const bool pf = (it + 1 < iters);
        if (pf) issue(it + 1, cur ^ 1);

        #pragma unroll
        for (int ks = 0; ks < 2; ks++) {
            const int k0 = ks * 16;
            uint32_t ar[2][4];
            #pragma unroll
            for (int mf = 0; mf < 2; mf++)
                ldmx4(ar[mf], smem_u32(&sAB[cur][0][wm * 32 + mf * 16 + arow16][k0 + akoff]));
            uint32_t br[8][2];
            #pragma unroll
            for (int nf2 = 0; nf2 < 4; nf2++) {
                uint32_t r[4];
                ldmx4(r, smem_u32(&sAB[cur][1][wn * 64 + nf2 * 16 + brow8][k0 + bkoff]));
                br[2*nf2][0] = r[0]; br[2*nf2][1] = r[1];
                br[2*nf2+1][0] = r[2]; br[2*nf2+1][1] = r[3];
            }
            #pragma unroll
            for (int mf = 0; mf < 2; mf++)
                #pragma unroll
                for (int nf = 0; nf < 8; nf++)
                    mma16816(acc[mf][nf], ar[mf], br[nf]);
        }

        if (pf) {
            CP_WAIT0();
            __syncthreads();
        }
    }

    #pragma unroll
    for (int mf = 0; mf < 2; mf++) {
        const int grow = bm + wm * 32 + mf * 16 + (lane >> 2);
        #pragma unroll
        for (int nf = 0; nf < 8; nf++) {
            const int gcol = bn + wn * 64 + nf * 8 + (lane & 3) * 2;
            if (gcol < Nreal) {
                *(float2*)(C + (size_t)grow * ldc + gcol) =
                    make_float2(acc[mf][nf][0], acc[mf][nf][1]);
                *(float2*)(C + (size_t)(grow + 8) * ldc + gcol) =
                    make_float2(acc[mf][nf][2], acc[mf][nf][3]);
            }
        }
    }
}

// ---------------- RoPE + rank contraction -> split bf16 q,k,v [b][h][s][d] ----------------
__global__ void rope_contract_kernel(const float* __restrict__ cosb, const float* __restrict__ sinb)
{
    int token = blockIdx.x;
    int b = token / S_;
    int s = token % S_;
    const float* y = g_Y + (size_t)token * NPROJ;
    int d = threadIdx.x;

    __shared__ float sA[160];
    for (int i = d; i < 160; i += 128) sA[i] = y[i];
    __syncthreads();

    int dh = d & 63;
    float c  = cosb[s * 64 + dh];
    float sn = sinb[s * 64 + dh];
    bool hi = (d >= 64);

    float bq[QR_], bk[KR_], bv[VR_];
    #pragma unroll
    for (int r = 0; r < QR_; r++) {
        float x1 = y[OFF_BQ + r * HD_ + dh];
        float x2 = y[OFF_BQ + r * HD_ + 64 + dh];
        bq[r] = hi ? (x1 * sn + x2 * c) : (x1 * c - x2 * sn);
    }
    #pragma unroll
    for (int r = 0; r < KR_; r++) {
        float x1 = y[OFF_BK + r * HD_ + dh];
        float x2 = y[OFF_BK + r * HD_ + 64 + dh];
        bk[r] = hi ? (x1 * sn + x2 * c) : (x1 * c - x2 * sn);
    }
    #pragma unroll
    for (int r = 0; r < VR_; r++) bv[r] = y[OFF_BV + r * HD_ + d];

    #pragma unroll
    for (int h = 0; h < NH_; h++) {
        float accq = 0.f, acck = 0.f, accv = 0.f;
        #pragma unroll
        for (int r = 0; r < QR_; r++) accq += sA[h * QR_ + r] * bq[r];
        #pragma unroll
        for (int r = 0; r < KR_; r++) acck += sA[96 + h * KR_ + r] * bk[r];
        #pragma unroll
        for (int r = 0; r < VR_; r++) accv += sA[128 + h * VR_ + r] * bv[r];
        size_t o = (((size_t)b * NH_ + h) * S_ + s) * HD_ + d;
        __nv_bfloat16 hh, ll;
        split2(accq * (SCALING_F / (float)QR_), hh, ll);
        g_qh[o] = hh; g_ql[o] = ll;
        split2(acck * (1.f / (float)KR_), hh, ll);
        g_kh[o] = hh; g_kl[o] = ll;
        split2(accv * (1.f / (float)VR_), hh, ll);
        g_vh[o] = hh; g_vl[o] = ll;
    }
}

// ---------------- Flash attention v2: register softmax + P-fragments + cp.async KV ----------------
// 8 warps: wq = wid&3 (16 q-rows each), wk = wid>>2 (kv-half of each 64-kv tile).
// Warp computes QK for its 16x32 sub-tile, then PV with k = its 32 kv positions over
// all 128 output cols; epilogue reduces the two wk halves.
#define AQ_LD  136                      // bf16 row stride (272B)
#define BUFB   (64*AQ_LD*2)             // one K/V buffer: 17408 B
#define RED_LD 132                      // fp32 row stride for epilogue reduce
#define SM_QH  0
#define SM_QL  (SM_QH + BUFB)
#define SM_KH  (SM_QL + BUFB)           // [2] buffers
#define SM_KL  (SM_KH + 2*BUFB)
#define SM_VH  (SM_KL + 2*BUFB)
#define SM_VL  (SM_VH + 2*BUFB)
#define SM_MX  (SM_VL + 2*BUFB)         // float[2][64]
#define SM_LP  (SM_MX + 512)            // float[64]
#define ATT_SMEM_BYTES (SM_LP + 256)    // 174848
// epilogue red buffer reuses SM_KH region: 64*RED_LD*4 = 33792 <= 2*BUFB

__global__ __launch_bounds__(256, 1)
void attn_kernel(const float* __restrict__ mask)
{
    extern __shared__ char smc[];
    const uint32_t smb = smem_u32(smc);

    const int tid  = threadIdx.x;
    const int lane = tid & 31;
    const int wid  = tid >> 5;
    const int wq   = wid & 3;
    const int wk   = wid >> 2;
    const int q0   = blockIdx.x * 64;
    const int h    = blockIdx.y;
    const int b    = blockIdx.z;

    const size_t headbase = ((size_t)b * NH_ + h) * S_ * HD_;

    // cp.async issue of one KV tile (hi/lo K and V) into buffer bi
    const int crow = tid >> 2;
    const int ccg  = (tid & 3) * 32;
    auto issue_kv = [&](int kv0, int bi) {
        const size_t go = headbase + (size_t)(kv0 + crow) * HD_ + ccg;
        const uint32_t so = (uint32_t)(crow * AQ_LD + ccg) * 2 + bi * BUFB;
        #pragma unroll
        for (int j = 0; j < 4; j++) {
            CP16(smb + SM_KH + so + j*16, g_kh + go + j*8);
            CP16(smb + SM_KL + so + j*16, g_kl + go + j*8);
            CP16(smb + SM_VH + so + j*16, g_vh + go + j*8);
            CP16(smb + SM_VL + so + j*16, g_vl + go + j*8);
        }
        CP_COMMIT();
    };

    issue_kv(0, 0);

    // Q tile load (direct)
    {
        const size_t go = headbase + (size_t)(q0 + crow) * HD_ + ccg;
        __nv_bfloat16* Qh_s = (__nv_bfloat16*)(smc + SM_QH);
        __nv_bfloat16* Ql_s = (__nv_bfloat16*)(smc + SM_QL);
        #pragma unroll
        for (int j = 0; j < 4; j++) {
            *(uint4*)&Qh_s[crow * AQ_LD + ccg + j*8] = *(const uint4*)(g_qh + go + j*8);
            *(uint4*)&Ql_s[crow * AQ_LD + ccg + j*8] = *(const uint4*)(g_ql + go + j*8);
        }
    }
    CP_WAIT0();
    __syncthreads();

    float acc[16][4];
    #pragma unroll
    for (int i = 0; i < 16; i++)
        #pragma unroll
        for (int j = 0; j < 4; j++) acc[i][j] = 0.f;
    float lp0 = 0.f, lp1 = 0.f;
    float mold0 = -INFINITY, mold1 = -INFINITY;

    const int arow  = lane & 15;
    const int akoff = (lane >> 4) << 3;
    const int brow8 = (lane & 7) + ((lane >> 4) << 3);
    const int bkoff = ((lane >> 3) & 1) << 3;
    const int rl0   = wq * 16 + (lane >> 2);     // local q row (and +8)
    float* mx  = (float*)(smc + SM_MX);          // [2][64]
    const float* maskrow0 = mask + ((size_t)b * S_ + q0 + rl0) * S_ + wk * 32 + (lane & 3) * 2;
    const float* maskrow1 = maskrow0 + (size_t)8 * S_;

    for (int t = 0; t < S_ / 64; t++) {
        const int kv0 = t * 64;
        const int cur = t & 1;
        const bool pf = (t + 1 < S_ / 64);
        if (pf) issue_kv(kv0 + 64, cur ^ 1);

        const uint32_t kh = smb + SM_KH + cur * BUFB;
        const uint32_t kl = smb + SM_KL + cur * BUFB;
        const uint32_t vh = smb + SM_VH + cur * BUFB;
        const uint32_t vl = smb + SM_VL + cur * BUFB;
        const uint32_t qh = smb + SM_QH;
        const uint32_t ql = smb + SM_QL;

        // ---- QK^T (3-term split): 16 x 32 per warp -> sc[4 n8-blocks][4] ----
        float sc[4][4];
        #pragma unroll
        for (int i = 0; i < 4; i++)
            #pragma unroll
            for (int j = 0; j < 4; j++) sc[i][j] = 0.f;

        #pragma unroll
        for (int k0 = 0; k0 < 128; k0 += 16) {
            uint32_t ah[4], al[4];
            const uint32_t aoff = ((wq * 16 + arow) * AQ_LD + k0 + akoff) * 2;
            ldmx4(ah, qh + aoff);
            ldmx4(al, ql + aoff);
            #pragma unroll
            for (int nb = 0; nb < 2; nb++) {
                uint32_t bh[4], bl[4];
                const uint32_t boff = ((wk * 32 + nb * 16 + brow8) * AQ_LD + k0 + bkoff) * 2;
                ldmx4(bh, kh + boff);
                ldmx4(bl, kl + boff);
                mma16816(sc[nb*2],   ah, bh);   mma16816(sc[nb*2+1], ah, bh + 2);
                mma16816(sc[nb*2],   al, bh);   mma16816(sc[nb*2+1], al, bh + 2);
                mma16816(sc[nb*2],   ah, bl);   mma16816(sc[nb*2+1], ah, bl + 2);
            }
        }

        // ---- add mask + per-warp row max ----
        float mr0 = -INFINITY, mr1 = -INFINITY;
        #pragma unroll
        for (int i = 0; i < 4; i++) {
            float2 m0 = *(const float2*)(maskrow0 + kv0 + i * 8);
            float2 m1 = *(const float2*)(maskrow1 + kv0 + i * 8);
            sc[i][0] += m0.x; sc[i][1] += m0.y;
            sc[i][2] += m1.x; sc[i][3] += m1.y;
            mr0 = fmaxf(mr0, fmaxf(sc[i][0], sc[i][1]));
            mr1 = fmaxf(mr1, fmaxf(sc[i][2], sc[i][3]));
        }
        mr0 = fmaxf(mr0, __shfl_xor_sync(0xffffffffu, mr0, 1));
        mr0 = fmaxf(mr0, __shfl_xor_sync(0xffffffffu, mr0, 2));
        mr1 = fmaxf(mr1, __shfl_xor_sync(0xffffffffu, mr1, 1));
        mr1 = fmaxf(mr1, __shfl_xor_sync(0xffffffffu, mr1, 2));
        if ((lane & 3) == 0) {
            mx[wk * 64 + rl0]     = mr0;
            mx[wk * 64 + rl0 + 8] = mr1;
        }
        __syncthreads();

        // ---- combined max, exp, l update, acc rescale ----
        const float M0 = fmaxf(mx[rl0],     mx[64 + rl0]);
        const float M1 = fmaxf(mx[rl0 + 8], mx[64 + rl0 + 8]);
        const float mnew0 = fmaxf(mold0, M0);
        const float mnew1 = fmaxf(mold1, M1);
        const float f0 = __expf(mold0 - mnew0);
        const float f1 = __expf(mold1 - mnew1);
        mold0 = mnew0; mold1 = mnew1;
        float s0 = 0.f, s1 = 0.f;
        #pragma unroll
        for (int i = 0; i < 4; i++) {
            sc[i][0] = __expf(sc[i][0] - mnew0);
            sc[i][1] = __expf(sc[i][1] - mnew0);
            sc[i][2] = __expf(sc[i][2] - mnew1);
            sc[i][3] = __expf(sc[i][3] - mnew1);
            s0 += sc[i][0] + sc[i][1];
            s1 += sc[i][2] + sc[i][3];
        }
        s0 += __shfl_xor_sync(0xffffffffu, s0, 1);
        s0 += __shfl_xor_sync(0xffffffffu, s0, 2);
        s1 += __shfl_xor_sync(0xffffffffu, s1, 1);
        s1 += __shfl_xor_sync(0xffffffffu, s1, 2);
        lp0 = lp0 * f0 + s0;
        lp1 = lp1 * f1 + s1;
        #pragma unroll
        for (int i = 0; i < 16; i++) {
            acc[i][0] *= f0; acc[i][1] *= f0;
            acc[i][2] *= f1; acc[i][3] *= f1;
        }

        // ---- PV: P from registers (C-frag == A-frag), k = this warp's 32 kv ----
        #pragma unroll
        for (int ks = 0; ks < 2; ks++) {
            uint32_t aPh[4], aPl[4];
            packsplit(sc[ks*2][0],   sc[ks*2][1],   aPh[0], aPl[0]);
            packsplit(sc[ks*2][2],   sc[ks*2][3],   aPh[1], aPl[1]);
            packsplit(sc[ks*2+1][0], sc[ks*2+1][1], aPh[2], aPl[2]);
            packsplit(sc[ks*2+1][2], sc[ks*2+1][3], aPh[3], aPl[3]);
            #pragma unroll
            for (int nb = 0; nb < 8; nb++) {
                uint32_t vfh[4], vfl[4];
                const uint32_t voff = ((wk * 32 + ks * 16 + arow) * AQ_LD + nb * 16 + akoff) * 2;
                ldmx4t(vfh, vh + voff);
                ldmx4t(vfl, vl + voff);
                mma16816(acc[nb*2],   aPh, vfh);   mma16816(acc[nb*2+1], aPh, vfh + 2);
                mma16816(acc[nb*2],   aPl, vfh);   mma16816(acc[nb*2+1], aPl, vfh + 2);
                mma16816(acc[nb*2],   aPh, vfl);   mma16816(acc[nb*2+1], aPh, vfl + 2);
            }
        }

        if (pf) CP_WAIT0();
        __syncthreads();
    }

    // ---- epilogue: reduce wk halves, normalize, write [hi|lo|hi] ----
    float* red = (float*)(smc + SM_KH);   // [64][RED_LD] fp32, reuses KV smem
    float* lpr = (float*)(smc + SM_LP);   // [64]
    if (wk == 1) {
        #pragma unroll
        for (int ni = 0; ni < 16; ni++) {
            const int col = (ni >> 1) * 16 + (ni & 1) * 8 + (lane & 3) * 2;
            *(float2*)&red[rl0 * RED_LD + col]       = make_float2(acc[ni][0], acc[ni][1]);
            *(float2*)&red[(rl0 + 8) * RED_LD + col] = make_float2(acc[ni][2], acc[ni][3]);
        }
        if ((lane & 3) == 0) { lpr[rl0] = lp0; lpr[rl0 + 8] = lp1; }
    }
    __syncthreads();
    if (wk == 0) {
        const float inv0 = 1.f / (lp0 + lpr[rl0]);
        const float inv1 = 1.f / (lp1 + lpr[rl0 + 8]);
        const size_t row0 = ((size_t)b * S_ + q0 + rl0) * KS_ + h * HD_;
        const size_t row1 = ((size_t)b * S_ + q0 + rl0 + 8) * KS_ + h * HD_;
        #pragma unroll
        for (int ni = 0; ni < 16; ni++) {
            const int col = (ni >> 1) * 16 + (ni & 1) * 8 + (lane & 3) * 2;
            float o0 = (acc[ni][0] + red[rl0 * RED_LD + col])           * inv0;
            float o1 = (acc[ni][1] + red[rl0 * RED_LD + col + 1])       * inv0;
            float o2 = (acc[ni][2] + red[(rl0 + 8) * RED_LD + col])     * inv1;
            float o3 = (acc[ni][3] + red[(rl0 + 8) * RED_LD + col + 1]) * inv1;
            uint32_t ph, pl;
            packsplit(o0, o1, ph, pl);
            *(uint32_t*)(g_Os + row0 + col)          = ph;
            *(uint32_t*)(g_Os + row0 + col + HID_)   = pl;
            *(uint32_t*)(g_Os + row0 + col + 2*HID_) = ph;
            packsplit(o2, o3, ph, pl);
            *(uint32_t*)(g_Os + row1 + col)          = ph;
            *(uint32_t*)(g_Os + row1 + col + HID_)   = pl;
            *(uint32_t*)(g_Os + row1 + col + 2*HID_) = ph;
        }
    }
}

// ---------------- Host launcher ----------------
extern "C" void kernel_launch(void* const* d_in, const int* in_sizes, int n_in,
                              void* d_out, int out_size)
{
    const float* x    = (const float*)d_in[0];
    const float* cosb = (const float*)d_in[1];
    const float* sinb = (const float*)d_in[2];
    // d_in[3] = kv_write_indices (unused by reference)
    const float* mask = (const float*)d_in[4];
    const float* waq  = (const float*)d_in[5];
    const float* wak  = (const float*)d_in[6];
    const float* wav  = (const float*)d_in[7];
    const float* wbq  = (const float*)d_in[8];
    const float* wbk  = (const float*)d_in[9];
    const float* wbv  = (const float*)d_in[10];
    const float* wo   = (const float*)d_in[11];
    float* out = (float*)d_out;

    __nv_bfloat16 *pXs, *pWs, *pWos, *pOs;
    float *pY;
    cudaGetSymbolAddress((void**)&pXs,  g_Xs);
    cudaGetSymbolAddress((void**)&pWs,  g_Ws);
    cudaGetSymbolAddress((void**)&pWos, g_Wos);
    cudaGetSymbolAddress((void**)&pOs,  g_Os);
    cudaGetSymbolAddress((void**)&pY,   g_Y);

    // 1) conversions
    split_fp32<<<(M_ * (HID_/4) + 255)/256, 256>>>(x, pXs, M_, HID_, 0);
    concat_w_split<<<(NPROJ_PAD * (HID_/4) + 255)/256, 256>>>(waq, wak, wav, wbq, wbk, wbv);
    split_fp32<<<(HID_ * (HID_/4) + 255)/256, 256>>>(wo, pWos, HID_, HID_, 1);

    // 2) projection GEMM
    gemm_bf16<<<dim3(NPROJ_PAD/128, M_/128), 256>>>(pXs, pWs, pY, NPROJ, NPROJ, KS_);

    // 3) RoPE + contraction
    rope_contract_kernel<<<M_, 128>>>(cosb, sinb);

    // 4) attention
    cudaFuncSetAttribute(attn_kernel, cudaFuncAttributeMaxDynamicSharedMemorySize, ATT_SMEM_BYTES);
    attn_kernel<<<dim3(S_/64, NH_, B_), 256, ATT_SMEM_BYTES>>>(mask);

    // 5) output GEMM
    gemm_bf16<<<dim3(HID_/128, M_/128), 256>>>(pOs, pWos, out, HID_, HID_, KS_);
}

// round 10
// speedup vs baseline: 5.0330x; 1.1211x over previous
#include <cuda_runtime.h>
#include <cuda_bf16.h>
#include <math.h>
#include <stdint.h>

// ---------------- Problem constants ----------------
#define B_    2
#define S_    2048
#define HID_  2048
#define NH_   16
#define HD_   128
#define QR_   6
#define KR_   2
#define VR_   2
#define M_    (B_*S_)          // 4096 tokens
#define NPROJ 1440
#define NPROJ_PAD 1536
#define KS_   (3*HID_)         // 6144: A=[hi|lo|hi], B=[hi|hi|lo]
#define SCALING_F 0.08838834764831845f  // 128^-0.5

// Y row layout offsets
#define OFF_AQ 0
#define OFF_AK 96
#define OFF_AV 128
#define OFF_BQ 160
#define OFF_BK 928
#define OFF_BV 1184

// ---------------- Scratch (device globals; no allocation allowed) ----------------
__device__ __nv_bfloat16 g_Xs [(size_t)M_ * KS_];        // hidden [hi|lo|hi]
__device__ __nv_bfloat16 g_Ws [(size_t)NPROJ_PAD * KS_]; // Wcat  [hi|hi|lo]
__device__ __nv_bfloat16 g_Wos[(size_t)HID_ * KS_];      // W_o   [hi|hi|lo]
__device__ __nv_bfloat16 g_Os [(size_t)M_ * KS_];        // attn out [hi|lo|hi]
__device__ float g_Y[(size_t)M_ * NPROJ];                // projections fp32
__device__ __nv_bfloat16 g_qh[(size_t)B_*NH_*S_*HD_];    // [b][h][s][d] split bf16
__device__ __nv_bfloat16 g_ql[(size_t)B_*NH_*S_*HD_];
__device__ __nv_bfloat16 g_kh[(size_t)B_*NH_*S_*HD_];
__device__ __nv_bfloat16 g_kl[(size_t)B_*NH_*S_*HD_];
__device__ __nv_bfloat16 g_vh[(size_t)B_*NH_*S_*HD_];
__device__ __nv_bfloat16 g_vl[(size_t)B_*NH_*S_*HD_];

// ---------------- helpers ----------------
__device__ __forceinline__ uint32_t smem_u32(const void* p) {
    uint32_t a;
    asm("{ .reg .u64 t; cvta.to.shared.u64 t, %1; cvt.u32.u64 %0, t; }" : "=r"(a) : "l"(p));
    return a;
}
__device__ __forceinline__ void split2(float x, __nv_bfloat16& h, __nv_bfloat16& l) {
    h = __float2bfloat16_rn(x);
    l = __float2bfloat16_rn(x - __bfloat162float(h));
}
__device__ __forceinline__ void packsplit(float a, float b, uint32_t& ph, uint32_t& pl) {
    __nv_bfloat16 ha, la, hb, lb;
    split2(a, ha, la); split2(b, hb, lb);
    __nv_bfloat162 H; H.x = ha; H.y = hb;
    __nv_bfloat162 L; L.x = la; L.y = lb;
    ph = *(uint32_t*)&H; pl = *(uint32_t*)&L;
}
__device__ __forceinline__ void ldmx4(uint32_t* r, uint32_t addr) {
    asm volatile("ldmatrix.sync.aligned.m8n8.x4.shared.b16 {%0,%1,%2,%3}, [%4];"
                 : "=r"(r[0]), "=r"(r[1]), "=r"(r[2]), "=r"(r[3]) : "r"(addr));
}
__device__ __forceinline__ void ldmx4t(uint32_t* r, uint32_t addr) {
    asm volatile("ldmatrix.sync.aligned.m8n8.x4.trans.shared.b16 {%0,%1,%2,%3}, [%4];"
                 : "=r"(r[0]), "=r"(r[1]), "=r"(r[2]), "=r"(r[3]) : "r"(addr));
}
__device__ __forceinline__ void mma16816(float* c, const uint32_t* a, const uint32_t* b) {
    asm volatile(
        "mma.sync.aligned.m16n8k16.row.col.f32.bf16.bf16.f32 "
        "{%0,%1,%2,%3}, {%4,%5,%6,%7}, {%8,%9}, {%0,%1,%2,%3};"
        : "+f"(c[0]), "+f"(c[1]), "+f"(c[2]), "+f"(c[3])
        : "r"(a[0]), "r"(a[1]), "r"(a[2]), "r"(a[3]), "r"(b[0]), "r"(b[1]));
}
#define CP16(dst, src) \
    asm volatile("cp.async.cg.shared.global [%0], [%1], 16;" \
                 :: "r"(dst), "l"((size_t)__cvta_generic_to_global(src)) : "memory")
#define CP_COMMIT() asm volatile("cp.async.commit_group;" ::: "memory")
#define CP_WAIT0()  asm volatile("cp.async.wait_group 0;" ::: "memory")
#define CP_WAIT2()  asm volatile("cp.async.wait_group 2;" ::: "memory")

// ---------------- Kernel: split fp32 -> 3-segment bf16 along K ----------------
__global__ void split_fp32(const float* __restrict__ src, __nv_bfloat16* __restrict__ dst,
                           int rows, int cols, int mode)
{
    int idx = blockIdx.x * blockDim.x + threadIdx.x;
    int c4n = cols >> 2;
    if (idx >= rows * c4n) return;
    int r  = idx / c4n;
    int c  = (idx - r * c4n) << 2;
    float4 v = *(const float4*)(src + (size_t)r * cols + c);
    __nv_bfloat16 h[4], l[4];
    split2(v.x, h[0], l[0]); split2(v.y, h[1], l[1]);
    split2(v.z, h[2], l[2]); split2(v.w, h[3], l[3]);
    size_t base = (size_t)r * (3 * cols) + c;
    if (mode == 0) {
        *(uint2*)(dst + base)            = *(uint2*)h;
        *(uint2*)(dst + base + cols)     = *(uint2*)l;
        *(uint2*)(dst + base + 2*cols)   = *(uint2*)h;
    } else {
        *(uint2*)(dst + base)            = *(uint2*)h;
        *(uint2*)(dst + base + cols)     = *(uint2*)h;
        *(uint2*)(dst + base + 2*cols)   = *(uint2*)l;
    }
}

// ---------------- Kernel: concat 6 weight mats + split -> g_Ws (B layout) ----------------
__global__ void concat_w_split(const float* __restrict__ waq, const float* __restrict__ wak,
                               const float* __restrict__ wav, const float* __restrict__ wbq,
                               const float* __restrict__ wbk, const float* __restrict__ wbv)
{
    int idx = blockIdx.x * blockDim.x + threadIdx.x;
    if (idx >= NPROJ_PAD * (HID_ / 4)) return;
    int row = idx >> 9;
    int c   = (idx & 511) << 2;
    float4 v = make_float4(0.f, 0.f, 0.f, 0.f);
    if (row < NPROJ) {
        const float* src; int r;
        if      (row < OFF_AK) { src = waq; r = row;          }
        else if (row < OFF_AV) { src = wak; r = row - OFF_AK; }
        else if (row < OFF_BQ) { src = wav; r = row - OFF_AV; }
        else if (row < OFF_BK) { src = wbq; r = row - OFF_BQ; }
        else if (row < OFF_BV) { src = wbk; r = row - OFF_BK; }
        else                   { src = wbv; r = row - OFF_BV; }
        v = *(const float4*)(src + (size_t)r * HID_ + c);
    }
    __nv_bfloat16 h[4], l[4];
    split2(v.x, h[0], l[0]); split2(v.y, h[1], l[1]);
    split2(v.z, h[2], l[2]); split2(v.w, h[3], l[3]);
    size_t base = (size_t)row * KS_ + c;
    *(uint2*)(g_Ws + base)              = *(uint2*)h;
    *(uint2*)(g_Ws + base + HID_)       = *(uint2*)h;
    *(uint2*)(g_Ws + base + 2*HID_)     = *(uint2*)l;
}

// ---------------- HMMA bf16 GEMM (NT), 4-stage cp.async pipeline ----------------
#define BK_ 32
#define LDA_ 40
#define GSTAGES 4
#define GEMM_SMEM (GSTAGES * 2 * 128 * LDA_ * 2)   // 81920 B

__global__ __launch_bounds__(256, 2)
void gemm_bf16(const __nv_bfloat16* __restrict__ A, const __nv_bfloat16* __restrict__ Bm,
               float* __restrict__ C, int Nreal, int ldc, int Kp)
{
    extern __shared__ char gsm[];
    __nv_bfloat16* sAB = (__nv_bfloat16*)gsm;   // [stage][2][128][LDA_]

    const int tid  = threadIdx.x;
    const int lane = tid & 31;
    const int wid  = tid >> 5;
    const int wm   = wid & 3;
    const int wn   = wid >> 2;
    const int bm   = blockIdx.y * 128;
    const int bn   = blockIdx.x * 128;

    const int lrow = tid >> 1;
    const int lseg = (tid & 1) * 16;
    const __nv_bfloat16* arow = A  + (size_t)(bm + lrow) * Kp + lseg;
    const __nv_bfloat16* brow = Bm + (size_t)(bn + lrow) * Kp + lseg;

    float acc[2][8][4];
    #pragma unroll
    for (int i = 0; i < 2; i++)
        #pragma unroll
        for (int j = 0; j < 8; j++)
            #pragma unroll
            for (int q = 0; q < 4; q++) acc[i][j][q] = 0.f;

    const int iters = Kp / BK_;

    auto issue = [&](int it, int bi) {
        const __nv_bfloat16* as = arow + it * BK_;
        const __nv_bfloat16* bs = brow + it * BK_;
        uint32_t da = smem_u32(&sAB[((bi*2 + 0)*128 + lrow)*LDA_ + lseg]);
        uint32_t db = smem_u32(&sAB[((bi*2 + 1)*128 + lrow)*LDA_ + lseg]);
        CP16(da,      as);
        CP16(da + 16, as + 8);
        CP16(db,      bs);
        CP16(db + 16, bs + 8);
        CP_COMMIT();
    };

    issue(0, 0);
    issue(1, 1);
    issue(2, 2);

    const int arow16 = lane & 15;
    const int akoff  = (lane >> 4) << 3;
    const int brow8  = (lane & 7) + ((lane >> 4) << 3);
    const int bkoff  = ((lane >> 3) & 1) << 3;

    for (int it = 0; it < iters; it++) {
        const int cur = it & 3;
        CP_WAIT2();            // copy for iter `it` complete (cadence kept by empty commits)
        __syncthreads();       // all warps done with buffer (it-1)&3 before overwrite
        if (it + 3 < iters) issue(it + 3, (it + 3) & 3);
        else CP_COMMIT();      // keep group cadence so WAIT2 always retires current

        #pragma unroll
        for (int ks = 0; ks < 2; ks++) {
            const int k0 = ks * 16;
            uint32_t ar[2][4];
            #pragma unroll
            for (int mf = 0; mf < 2; mf++)
                ldmx4(ar[mf], smem_u32(&sAB[((cur*2 + 0)*128 + wm*32 + mf*16 + arow16)*LDA_ + k0 + akoff]));
            uint32_t br[8][2];
            #pragma unroll
            for (int nf2 = 0; nf2 < 4; nf2++) {
                uint32_t r[4];
                ldmx4(r, smem_u32(&sAB[((cur*2 + 1)*128 + wn*64 + nf2*16 + brow8)*LDA_ + k0 + bkoff]));
                br[2*nf2][0] = r[0]; br[2*nf2][1] = r[1];
                br[2*nf2+1][0] = r[2]; br[2*nf2+1][1] = r[3];
            }
            #pragma unroll
            for (int mf = 0; mf < 2; mf++)
                #pragma unroll
                for (int nf = 0; nf < 8; nf++)
                    mma16816(acc[mf][nf], ar[mf], br[nf]);
        }
    }

    #pragma unroll
    for (int mf = 0; mf < 2; mf++) {
        const int grow = bm + wm * 32 + mf * 16 + (lane >> 2);
        #pragma unroll
        for (int nf = 0; nf < 8; nf++) {
            const int gcol = bn + wn * 64 + nf * 8 + (lane & 3) * 2;
            if (gcol < Nreal) {
                *(float2*)(C + (size_t)grow * ldc + gcol) =
                    make_float2(acc[mf][nf][0], acc[mf][nf][1]);
                *(float2*)(C + (size_t)(grow + 8) * ldc + gcol) =
                    make_float2(acc[mf][nf][2], acc[mf][nf][3]);
            }
        }
    }
}

// ---------------- RoPE + rank contraction -> split bf16 q,k,v [b][h][s][d] ----------------
__global__ void rope_contract_kernel(const float* __restrict__ cosb, const float* __restrict__ sinb)
{
    int token = blockIdx.x;
    int b = token / S_;
    int s = token % S_;
    const float* y = g_Y + (size_t)token * NPROJ;
    int d = threadIdx.x;

    __shared__ float sA[160];
    for (int i = d; i < 160; i += 128) sA[i] = y[i];
    __syncthreads();

    int dh = d & 63;
    float c  = cosb[s * 64 + dh];
    float sn = sinb[s * 64 + dh];
    bool hi = (d >= 64);

    float bq[QR_], bk[KR_], bv[VR_];
    #pragma unroll
    for (int r = 0; r < QR_; r++) {
        float x1 = y[OFF_BQ + r * HD_ + dh];
        float x2 = y[OFF_BQ + r * HD_ + 64 + dh];
        bq[r] = hi ? (x1 * sn + x2 * c) : (x1 * c - x2 * sn);
    }
    #pragma unroll
    for (int r = 0; r < KR_; r++) {
        float x1 = y[OFF_BK + r * HD_ + dh];
        float x2 = y[OFF_BK + r * HD_ + 64 + dh];
        bk[r] = hi ? (x1 * sn + x2 * c) : (x1 * c - x2 * sn);
    }
    #pragma unroll
    for (int r = 0; r < VR_; r++) bv[r] = y[OFF_BV + r * HD_ + d];

    #pragma unroll
    for (int h = 0; h < NH_; h++) {
        float accq = 0.f, acck = 0.f, accv = 0.f;
        #pragma unroll
        for (int r = 0; r < QR_; r++) accq += sA[h * QR_ + r] * bq[r];
        #pragma unroll
        for (int r = 0; r < KR_; r++) acck += sA[96 + h * KR_ + r] * bk[r];
        #pragma unroll
        for (int r = 0; r < VR_; r++) accv += sA[128 + h * VR_ + r] * bv[r];
        size_t o = (((size_t)b * NH_ + h) * S_ + s) * HD_ + d;
        __nv_bfloat16 hh, ll;
        split2(accq * (SCALING_F / (float)QR_), hh, ll);
        g_qh[o] = hh; g_ql[o] = ll;
        split2(acck * (1.f / (float)KR_), hh, ll);
        g_kh[o] = hh; g_kl[o] = ll;
        split2(accv * (1.f / (float)VR_), hh, ll);
        g_vh[o] = hh; g_vl[o] = ll;
    }
}

// ---------------- Flash attention v3: 128-row q-tiles, warp-private softmax ----------------
// 8 warps, warp w owns q-rows [w*16, w*16+16). QK over full 64-kv tile per warp;
// PV with k=64. No cross-warp reductions; one __syncthreads per tile (buffers).
#define AQ_LD  136                      // bf16 row stride (272B)
#define QBUFB  (128*AQ_LD*2)            // Q buffer (hi or lo): 34816 B
#define BUFB   (64*AQ_LD*2)             // one K/V buffer: 17408 B
#define SM_QH  0
#define SM_QL  (SM_QH + QBUFB)
#define SM_KH  (SM_QL + QBUFB)          // [2] buffers
#define SM_KL  (SM_KH + 2*BUFB)
#define SM_VH  (SM_KL + 2*BUFB)
#define SM_VL  (SM_VH + 2*BUFB)
#define ATT_SMEM_BYTES (SM_VL + 2*BUFB) // 208896 B

__global__ __launch_bounds__(256, 1)
void attn_kernel(const float* __restrict__ mask)
{
    extern __shared__ char smc[];
    const uint32_t smb = smem_u32(smc);

    const int tid  = threadIdx.x;
    const int lane = tid & 31;
    const int wid  = tid >> 5;
    const int q0   = blockIdx.x * 128;
    const int h    = blockIdx.y;
    const int b    = blockIdx.z;

    const size_t headbase = ((size_t)b * NH_ + h) * S_ * HD_;

    // KV cp.async: 256 threads cover 64 rows x 128 cols x 4 arrays
    const int crow = tid >> 2;
    const int ccg  = (tid & 3) * 32;
    auto issue_kv = [&](int kv0, int bi) {
        const size_t go = headbase + (size_t)(kv0 + crow) * HD_ + ccg;
        const uint32_t so = (uint32_t)(crow * AQ_LD + ccg) * 2 + bi * BUFB;
        #pragma unroll
        for (int j = 0; j < 4; j++) {
            CP16(smb + SM_KH + so + j*16, g_kh + go + j*8);
            CP16(smb + SM_KL + so + j*16, g_kl + go + j*8);
            CP16(smb + SM_VH + so + j*16, g_vh + go + j*8);
            CP16(smb + SM_VL + so + j*16, g_vl + go + j*8);
        }
        CP_COMMIT();
    };

    issue_kv(0, 0);

    // Q tile: 128 rows x 128 cols, hi+lo (direct loads)
    {
        const int qrow = tid >> 1;
        const int qcg  = (tid & 1) * 64;
        const size_t go = headbase + (size_t)(q0 + qrow) * HD_ + qcg;
        __nv_bfloat16* Qh_s = (__nv_bfloat16*)(smc + SM_QH);
        __nv_bfloat16* Ql_s = (__nv_bfloat16*)(smc + SM_QL);
        #pragma unroll
        for (int j = 0; j < 8; j++) {
            *(uint4*)&Qh_s[qrow * AQ_LD + qcg + j*8] = *(const uint4*)(g_qh + go + j*8);
            *(uint4*)&Ql_s[qrow * AQ_LD + qcg + j*8] = *(const uint4*)(g_ql + go + j*8);
        }
    }
    CP_WAIT0();
    __syncthreads();

    float acc[16][4];
    #pragma unroll
    for (int i = 0; i < 16; i++)
        #pragma unroll
        for (int j = 0; j < 4; j++) acc[i][j] = 0.f;
    float lp0 = 0.f, lp1 = 0.f;
    float mold0 = -INFINITY, mold1 = -INFINITY;

    const int arow  = lane & 15;
    const int akoff = (lane >> 4) << 3;
    const int brow8 = (lane & 7) + ((lane >> 4) << 3);
    const int bkoff = ((lane >> 3) & 1) << 3;
    const int rl0   = wid * 16 + (lane >> 2);    // local q row (and +8)
    const float* maskrow0 = mask + ((size_t)b * S_ + q0 + rl0) * S_ + (lane & 3) * 2;
    const float* maskrow1 = maskrow0 + (size_t)8 * S_;

    for (int t = 0; t < S_ / 64; t++) {
        const int kv0 = t * 64;
        const int cur = t & 1;
        const bool pf = (t + 1 < S_ / 64);
        if (pf) issue_kv(kv0 + 64, cur ^ 1);

        const uint32_t kh = smb + SM_KH + cur * BUFB;
        const uint32_t kl = smb + SM_KL + cur * BUFB;
        const uint32_t vh = smb + SM_VH + cur * BUFB;
        const uint32_t vl = smb + SM_VL + cur * BUFB;
        const uint32_t qh = smb + SM_QH;
        const uint32_t ql = smb + SM_QL;

        // ---- QK^T (3-term split): 16 x 64 per warp -> sc[8 n8-blocks][4] ----
        float sc[8][4];
        #pragma unroll
        for (int i = 0; i < 8; i++)
            #pragma unroll
            for (int j = 0; j < 4; j++) sc[i][j] = 0.f;

        #pragma unroll
        for (int k0 = 0; k0 < 128; k0 += 16) {
            uint32_t ah[4], al[4];
            const uint32_t aoff = ((wid * 16 + arow) * AQ_LD + k0 + akoff) * 2;
            ldmx4(ah, qh + aoff);
            ldmx4(al, ql + aoff);
            #pragma unroll
            for (int nb = 0; nb < 4; nb++) {
                uint32_t bh[4], bl[4];
                const uint32_t boff = ((nb * 16 + brow8) * AQ_LD + k0 + bkoff) * 2;
                ldmx4(bh, kh + boff);
                ldmx4(bl, kl + boff);
                mma16816(sc[nb*2],   ah, bh);   mma16816(sc[nb*2+1], ah, bh + 2);
                mma16816(sc[nb*2],   al, bh);   mma16816(sc[nb*2+1], al, bh + 2);
                mma16816(sc[nb*2],   ah, bl);   mma16816(sc[nb*2+1], ah, bl + 2);
            }
        }

        // ---- add mask + warp-local row max ----
        float mr0 = -INFINITY, mr1 = -INFINITY;
        #pragma unroll
        for (int i = 0; i < 8; i++) {
            float2 m0 = *(const float2*)(maskrow0 + kv0 + i * 8);
            float2 m1 = *(const float2*)(maskrow1 + kv0 + i * 8);
            sc[i][0] += m0.x; sc[i][1] += m0.y;
            sc[i][2] += m1.x; sc[i][3] += m1.y;
            mr0 = fmaxf(mr0, fmaxf(sc[i][0], sc[i][1]));
            mr1 = fmaxf(mr1, fmaxf(sc[i][2], sc[i][3]));
        }
        mr0 = fmaxf(mr0, __shfl_xor_sync(0xffffffffu, mr0, 1));
        mr0 = fmaxf(mr0, __shfl_xor_sync(0xffffffffu, mr0, 2));
        mr1 = fmaxf(mr1, __shfl_xor_sync(0xffffffffu, mr1, 1));
        mr1 = fmaxf(mr1, __shfl_xor_sync(0xffffffffu, mr1, 2));

        // ---- softmax update (warp-private) ----
        const float mnew0 = fmaxf(mold0, mr0);
        const float mnew1 = fmaxf(mold1, mr1);
        const float f0 = __expf(mold0 - mnew0);
        const float f1 = __expf(mold1 - mnew1);
        mold0 = mnew0; mold1 = mnew1;
        float s0 = 0.f, s1 = 0.f;
        #pragma unroll
        for (int i = 0; i < 8; i++) {
            sc[i][0] = __expf(sc[i][0] - mnew0);
            sc[i][1] = __expf(sc[i][1] - mnew0);
            sc[i][2] = __expf(sc[i][2] - mnew1);
            sc[i][3] = __expf(sc[i][3] - mnew1);
            s0 += sc[i][0] + sc[i][1];
            s1 += sc[i][2] + sc[i][3];
        }
        s0 += __shfl_xor_sync(0xffffffffu, s0, 1);
        s0 += __shfl_xor_sync(0xffffffffu, s0, 2);
        s1 += __shfl_xor_sync(0xffffffffu, s1, 1);
        s1 += __shfl_xor_sync(0xffffffffu, s1, 2);
        lp0 = lp0 * f0 + s0;
        lp1 = lp1 * f1 + s1;
        #pragma unroll
        for (int i = 0; i < 16; i++) {
            acc[i][0] *= f0; acc[i][1] *= f0;
            acc[i][2] *= f1; acc[i][3] *= f1;
        }

        // ---- PV: P from registers (C-frag == A-frag), k = 64 ----
        #pragma unroll
        for (int ks = 0; ks < 4; ks++) {
            uint32_t aPh[4], aPl[4];
            packsplit(sc[ks*2][0],   sc[ks*2][1],   aPh[0], aPl[0]);
            packsplit(sc[ks*2][2],   sc[ks*2][3],   aPh[1], aPl[1]);
            packsplit(sc[ks*2+1][0], sc[ks*2+1][1], aPh[2], aPl[2]);
            packsplit(sc[ks*2+1][2], sc[ks*2+1][3], aPh[3], aPl[3]);
            #pragma unroll
            for (int nb = 0; nb < 8; nb++) {
                uint32_t vfh[4], vfl[4];
                const uint32_t voff = ((ks * 16 + arow) * AQ_LD + nb * 16 + akoff) * 2;
                ldmx4t(vfh, vh + voff);
                ldmx4t(vfl, vl + voff);
                mma16816(acc[nb*2],   aPh, vfh);   mma16816(acc[nb*2+1], aPh, vfh + 2);
                mma16816(acc[nb*2],   aPl, vfh);   mma16816(acc[nb*2+1], aPl, vfh + 2);
                mma16816(acc[nb*2],   aPh, vfl);   mma16816(acc[nb*2+1], aPh, vfl + 2);
            }
        }

        if (pf) CP_WAIT0();
        __syncthreads();   // all warps done reading buffer cur before next-iter overwrite
    }

    // ---- epilogue: normalize, write [hi|lo|hi] (warp-private rows) ----
    {
        const float inv0 = 1.f / lp0;
        const float inv1 = 1.f / lp1;
        const size_t row0 = ((size_t)b * S_ + q0 + rl0) * KS_ + h * HD_;
        const size_t row1 = ((size_t)b * S_ + q0 + rl0 + 8) * KS_ + h * HD_;
        #pragma unroll
        for (int ni = 0; ni < 16; ni++) {
            const int col = ni * 8 + (lane & 3) * 2;
            uint32_t ph, pl;
            packsplit(acc[ni][0] * inv0, acc[ni][1] * inv0, ph, pl);
            *(uint32_t*)(g_Os + row0 + col)          = ph;
            *(uint32_t*)(g_Os + row0 + col + HID_)   = pl;
            *(uint32_t*)(g_Os + row0 + col + 2*HID_) = ph;
            packsplit(acc[ni][2] * inv1, acc[ni][3] * inv1, ph, pl);
            *(uint32_t*)(g_Os + row1 + col)          = ph;
            *(uint32_t*)(g_Os + row1 + col + HID_)   = pl;
            *(uint32_t*)(g_Os + row1 + col + 2*HID_) = ph;
        }
    }
}

// ---------------- Host launcher ----------------
extern "C" void kernel_launch(void* const* d_in, const int* in_sizes, int n_in,
                              void* d_out, int out_size)
{
    const float* x    = (const float*)d_in[0];
    const float* cosb = (const float*)d_in[1];
    const float* sinb = (const float*)d_in[2];
    // d_in[3] = kv_write_indices (unused by reference)
    const float* mask = (const float*)d_in[4];
    const float* waq  = (const float*)d_in[5];
    const float* wak  = (const float*)d_in[6];
    const float* wav  = (const float*)d_in[7];
    const float* wbq  = (const float*)d_in[8];
    const float* wbk  = (const float*)d_in[9];
    const float* wbv  = (const float*)d_in[10];
    const float* wo   = (const float*)d_in[11];
    float* out = (float*)d_out;

    __nv_bfloat16 *pXs, *pWs, *pWos, *pOs;
    float *pY;
    cudaGetSymbolAddress((void**)&pXs,  g_Xs);
    cudaGetSymbolAddress((void**)&pWs,  g_Ws);
    cudaGetSymbolAddress((void**)&pWos, g_Wos);
    cudaGetSymbolAddress((void**)&pOs,  g_Os);
    cudaGetSymbolAddress((void**)&pY,   g_Y);

    // 1) conversions
    split_fp32<<<(M_ * (HID_/4) + 255)/256, 256>>>(x, pXs, M_, HID_, 0);
    concat_w_split<<<(NPROJ_PAD * (HID_/4) + 255)/256, 256>>>(waq, wak, wav, wbq, wbk, wbv);
    split_fp32<<<(HID_ * (HID_/4) + 255)/256, 256>>>(wo, pWos, HID_, HID_, 1);

    // 2) projection GEMM (4-stage pipeline)
    cudaFuncSetAttribute(gemm_bf16, cudaFuncAttributeMaxDynamicSharedMemorySize, GEMM_SMEM);
    gemm_bf16<<<dim3(NPROJ_PAD/128, M_/128), 256, GEMM_SMEM>>>(pXs, pWs, pY, NPROJ, NPROJ, KS_);

    // 3) RoPE + contraction
    rope_contract_kernel<<<M_, 128>>>(cosb, sinb);

    // 4) attention (128-row q-tiles, warp-private softmax)
    cudaFuncSetAttribute(attn_kernel, cudaFuncAttributeMaxDynamicSharedMemorySize, ATT_SMEM_BYTES);
    attn_kernel<<<dim3(S_/128, NH_, B_), 256, ATT_SMEM_BYTES>>>(mask);

    // 5) output GEMM
    gemm_bf16<<<dim3(HID_/128, M_/128), 256, GEMM_SMEM>>>(pOs, pWos, out, HID_, HID_, KS_);
}

// round 11
// speedup vs baseline: 6.0943x; 1.2109x over previous
#include <cuda_runtime.h>
#include <cuda_bf16.h>
#include <cuda_fp16.h>
#include <math.h>
#include <stdint.h>

// ---------------- Problem constants ----------------
#define B_    2
#define S_    2048
#define HID_  2048
#define NH_   16
#define HD_   128
#define QR_   6
#define KR_   2
#define VR_   2
#define M_    (B_*S_)          // 4096 tokens
#define NPROJ 1440
#define NPROJ_PAD 1536
#define KS2_  (2*HID_)         // 4096: fp16 2-term split  A=[hi|lo], B=[hi|hi]
#define SCALING_F 0.08838834764831845f  // 128^-0.5

// Y row layout offsets
#define OFF_AQ 0
#define OFF_AK 96
#define OFF_AV 128
#define OFF_BQ 160
#define OFF_BK 928
#define OFF_BV 1184

// ---------------- Scratch (device globals; no allocation allowed) ----------------
__device__ __half g_Xs [(size_t)M_ * KS2_];        // hidden [hi|lo] fp16
__device__ __half g_Ws [(size_t)NPROJ_PAD * KS2_]; // Wcat  [hi|hi] fp16
__device__ __half g_Wos[(size_t)HID_ * KS2_];      // W_o   [hi|hi] fp16
__device__ __half g_Os [(size_t)M_ * KS2_];        // attn out [hi|lo] fp16
__device__ float g_Y[(size_t)M_ * NPROJ];          // projections fp32
__device__ __nv_bfloat16 g_qh[(size_t)B_*NH_*S_*HD_];  // attention operands (bf16 split)
__device__ __nv_bfloat16 g_ql[(size_t)B_*NH_*S_*HD_];
__device__ __nv_bfloat16 g_kh[(size_t)B_*NH_*S_*HD_];
__device__ __nv_bfloat16 g_kl[(size_t)B_*NH_*S_*HD_];
__device__ __nv_bfloat16 g_vh[(size_t)B_*NH_*S_*HD_];
__device__ __nv_bfloat16 g_vl[(size_t)B_*NH_*S_*HD_];

// ---------------- helpers ----------------
__device__ __forceinline__ uint32_t smem_u32(const void* p) {
    uint32_t a;
    asm("{ .reg .u64 t; cvta.to.shared.u64 t, %1; cvt.u32.u64 %0, t; }" : "=r"(a) : "l"(p));
    return a;
}
__device__ __forceinline__ void split2(float x, __nv_bfloat16& h, __nv_bfloat16& l) {
    h = __float2bfloat16_rn(x);
    l = __float2bfloat16_rn(x - __bfloat162float(h));
}
__device__ __forceinline__ void split2h(float x, __half& h, __half& l) {
    h = __float2half_rn(x);
    l = __float2half_rn(x - __half2float(h));
}
__device__ __forceinline__ void packsplit(float a, float b, uint32_t& ph, uint32_t& pl) {
    __nv_bfloat16 ha, la, hb, lb;
    split2(a, ha, la); split2(b, hb, lb);
    __nv_bfloat162 H; H.x = ha; H.y = hb;
    __nv_bfloat162 L; L.x = la; L.y = lb;
    ph = *(uint32_t*)&H; pl = *(uint32_t*)&L;
}
__device__ __forceinline__ void packsplit_h(float a, float b, uint32_t& ph, uint32_t& pl) {
    __half ha, la, hb, lb;
    split2h(a, ha, la); split2h(b, hb, lb);
    __half2 H; H.x = ha; H.y = hb;
    __half2 L; L.x = la; L.y = lb;
    ph = *(uint32_t*)&H; pl = *(uint32_t*)&L;
}
__device__ __forceinline__ void ldmx4(uint32_t* r, uint32_t addr) {
    asm volatile("ldmatrix.sync.aligned.m8n8.x4.shared.b16 {%0,%1,%2,%3}, [%4];"
                 : "=r"(r[0]), "=r"(r[1]), "=r"(r[2]), "=r"(r[3]) : "r"(addr));
}
__device__ __forceinline__ void ldmx4t(uint32_t* r, uint32_t addr) {
    asm volatile("ldmatrix.sync.aligned.m8n8.x4.trans.shared.b16 {%0,%1,%2,%3}, [%4];"
                 : "=r"(r[0]), "=r"(r[1]), "=r"(r[2]), "=r"(r[3]) : "r"(addr));
}
__device__ __forceinline__ void mma16816(float* c, const uint32_t* a, const uint32_t* b) {
    asm volatile(
        "mma.sync.aligned.m16n8k16.row.col.f32.bf16.bf16.f32 "
        "{%0,%1,%2,%3}, {%4,%5,%6,%7}, {%8,%9}, {%0,%1,%2,%3};"
        : "+f"(c[0]), "+f"(c[1]), "+f"(c[2]), "+f"(c[3])
        : "r"(a[0]), "r"(a[1]), "r"(a[2]), "r"(a[3]), "r"(b[0]), "r"(b[1]));
}
__device__ __forceinline__ void mma16816h(float* c, const uint32_t* a, const uint32_t* b) {
    asm volatile(
        "mma.sync.aligned.m16n8k16.row.col.f32.f16.f16.f32 "
        "{%0,%1,%2,%3}, {%4,%5,%6,%7}, {%8,%9}, {%0,%1,%2,%3};"
        : "+f"(c[0]), "+f"(c[1]), "+f"(c[2]), "+f"(c[3])
        : "r"(a[0]), "r"(a[1]), "r"(a[2]), "r"(a[3]), "r"(b[0]), "r"(b[1]));
}
#define CP16(dst, src) \
    asm volatile("cp.async.cg.shared.global [%0], [%1], 16;" \
                 :: "r"(dst), "l"((size_t)__cvta_generic_to_global(src)) : "memory")
#define CP_COMMIT() asm volatile("cp.async.commit_group;" ::: "memory")
#define CP_WAIT0()  asm volatile("cp.async.wait_group 0;" ::: "memory")
#define CP_WAIT2()  asm volatile("cp.async.wait_group 2;" ::: "memory")

// ---------------- Kernel: split fp32 -> fp16 2-seg along K ----------------
// mode 0 (A-operand): [hi | lo]    mode 1 (B-operand): [hi | hi]
__global__ void split_fp16(const float* __restrict__ src, __half* __restrict__ dst,
                           int rows, int cols, int mode)
{
    int idx = blockIdx.x * blockDim.x + threadIdx.x;
    int c4n = cols >> 2;
    if (idx >= rows * c4n) return;
    int r  = idx / c4n;
    int c  = (idx - r * c4n) << 2;
    float4 v = *(const float4*)(src + (size_t)r * cols + c);
    __half h[4], l[4];
    split2h(v.x, h[0], l[0]); split2h(v.y, h[1], l[1]);
    split2h(v.z, h[2], l[2]); split2h(v.w, h[3], l[3]);
    size_t base = (size_t)r * (2 * cols) + c;
    *(uint2*)(dst + base) = *(uint2*)h;
    if (mode == 0) *(uint2*)(dst + base + cols) = *(uint2*)l;
    else           *(uint2*)(dst + base + cols) = *(uint2*)h;
}

// ---------------- Kernel: concat 6 weight mats + fp16 split -> g_Ws [1536][4096] (B layout) ----------------
__global__ void concat_w_split(const float* __restrict__ waq, const float* __restrict__ wak,
                               const float* __restrict__ wav, const float* __restrict__ wbq,
                               const float* __restrict__ wbk, const float* __restrict__ wbv)
{
    int idx = blockIdx.x * blockDim.x + threadIdx.x;
    if (idx >= NPROJ_PAD * (HID_ / 4)) return;
    int row = idx >> 9;
    int c   = (idx & 511) << 2;
    float4 v = make_float4(0.f, 0.f, 0.f, 0.f);
    if (row < NPROJ) {
        const float* src; int r;
        if      (row < OFF_AK) { src = waq; r = row;          }
        else if (row < OFF_AV) { src = wak; r = row - OFF_AK; }
        else if (row < OFF_BQ) { src = wav; r = row - OFF_AV; }
        else if (row < OFF_BK) { src = wbq; r = row - OFF_BQ; }
        else if (row < OFF_BV) { src = wbk; r = row - OFF_BK; }
        else                   { src = wbv; r = row - OFF_BV; }
        v = *(const float4*)(src + (size_t)r * HID_ + c);
    }
    __half h[4];
    h[0] = __float2half_rn(v.x); h[1] = __float2half_rn(v.y);
    h[2] = __float2half_rn(v.z); h[3] = __float2half_rn(v.w);
    size_t base = (size_t)row * KS2_ + c;
    *(uint2*)(g_Ws + base)        = *(uint2*)h;   // hi
    *(uint2*)(g_Ws + base + HID_) = *(uint2*)h;   // hi (pairs with A's lo segment)
}

// ---------------- HMMA fp16 GEMM (NT), 4-stage cp.async pipeline ----------------
#define BK_ 32
#define LDA_ 40
#define GSTAGES 4
#define GEMM_SMEM (GSTAGES * 2 * 128 * LDA_ * 2)   // 81920 B

__global__ __launch_bounds__(256, 2)
void gemm_fp16(const __half* __restrict__ A, const __half* __restrict__ Bm,
               float* __restrict__ C, int Nreal, int ldc, int Kp)
{
    extern __shared__ char gsm[];
    __half* sAB = (__half*)gsm;   // [stage][2][128][LDA_]

    const int tid  = threadIdx.x;
    const int lane = tid & 31;
    const int wid  = tid >> 5;
    const int wm   = wid & 3;
    const int wn   = wid >> 2;
    const int bm   = blockIdx.y * 128;
    const int bn   = blockIdx.x * 128;

    const int lrow = tid >> 1;
    const int lseg = (tid & 1) * 16;
    const __half* arow = A  + (size_t)(bm + lrow) * Kp + lseg;
    const __half* brow = Bm + (size_t)(bn + lrow) * Kp + lseg;

    float acc[2][8][4];
    #pragma unroll
    for (int i = 0; i < 2; i++)
        #pragma unroll
        for (int j = 0; j < 8; j++)
            #pragma unroll
            for (int q = 0; q < 4; q++) acc[i][j][q] = 0.f;

    const int iters = Kp / BK_;

    auto issue = [&](int it, int bi) {
        const __half* as = arow + it * BK_;
        const __half* bs = brow + it * BK_;
        uint32_t da = smem_u32(&sAB[((bi*2 + 0)*128 + lrow)*LDA_ + lseg]);
        uint32_t db = smem_u32(&sAB[((bi*2 + 1)*128 + lrow)*LDA_ + lseg]);
        CP16(da,      as);
        CP16(da + 16, as + 8);
        CP16(db,      bs);
        CP16(db + 16, bs + 8);
        CP_COMMIT();
    };

    issue(0, 0);
    issue(1, 1);
    issue(2, 2);

    const int arow16 = lane & 15;
    const int akoff  = (lane >> 4) << 3;
    const int brow8  = (lane & 7) + ((lane >> 4) << 3);
    const int bkoff  = ((lane >> 3) & 1) << 3;

    for (int it = 0; it < iters; it++) {
        const int cur = it & 3;
        CP_WAIT2();
        __syncthreads();
        if (it + 3 < iters) issue(it + 3, (it + 3) & 3);
        else CP_COMMIT();   // keep group cadence

        #pragma unroll
        for (int ks = 0; ks < 2; ks++) {
            const int k0 = ks * 16;
            uint32_t ar[2][4];
            #pragma unroll
            for (int mf = 0; mf < 2; mf++)
                ldmx4(ar[mf], smem_u32(&sAB[((cur*2 + 0)*128 + wm*32 + mf*16 + arow16)*LDA_ + k0 + akoff]));
            uint32_t br[8][2];
            #pragma unroll
            for (int nf2 = 0; nf2 < 4; nf2++) {
                uint32_t r[4];
                ldmx4(r, smem_u32(&sAB[((cur*2 + 1)*128 + wn*64 + nf2*16 + brow8)*LDA_ + k0 + bkoff]));
                br[2*nf2][0] = r[0]; br[2*nf2][1] = r[1];
                br[2*nf2+1][0] = r[2]; br[2*nf2+1][1] = r[3];
            }
            #pragma unroll
            for (int mf = 0; mf < 2; mf++)
                #pragma unroll
                for (int nf = 0; nf < 8; nf++)
                    mma16816h(acc[mf][nf], ar[mf], br[nf]);
        }
    }

    #pragma unroll
    for (int mf = 0; mf < 2; mf++) {
        const int grow = bm + wm * 32 + mf * 16 + (lane >> 2);
        #pragma unroll
        for (int nf = 0; nf < 8; nf++) {
            const int gcol = bn + wn * 64 + nf * 8 + (lane & 3) * 2;
            if (gcol < Nreal) {
                *(float2*)(C + (size_t)grow * ldc + gcol) =
                    make_float2(acc[mf][nf][0], acc[mf][nf][1]);
                *(float2*)(C + (size_t)(grow + 8) * ldc + gcol) =
                    make_float2(acc[mf][nf][2], acc[mf][nf][3]);
            }
        }
    }
}

// ---------------- RoPE + rank contraction -> split bf16 q,k,v [b][h][s][d] ----------------
__global__ void rope_contract_kernel(const float* __restrict__ cosb, const float* __restrict__ sinb)
{
    int token = blockIdx.x;
    int b = token / S_;
    int s = token % S_;
    const float* y = g_Y + (size_t)token * NPROJ;
    int d = threadIdx.x;

    __shared__ float sA[160];
    for (int i = d; i < 160; i += 128) sA[i] = y[i];
    __syncthreads();

    int dh = d & 63;
    float c  = cosb[s * 64 + dh];
    float sn = sinb[s * 64 + dh];
    bool hi = (d >= 64);

    float bq[QR_], bk[KR_], bv[VR_];
    #pragma unroll
    for (int r = 0; r < QR_; r++) {
        float x1 = y[OFF_BQ + r * HD_ + dh];
        float x2 = y[OFF_BQ + r * HD_ + 64 + dh];
        bq[r] = hi ? (x1 * sn + x2 * c) : (x1 * c - x2 * sn);
    }
    #pragma unroll
    for (int r = 0; r < KR_; r++) {
        float x1 = y[OFF_BK + r * HD_ + dh];
        float x2 = y[OFF_BK + r * HD_ + 64 + dh];
        bk[r] = hi ? (x1 * sn + x2 * c) : (x1 * c - x2 * sn);
    }
    #pragma unroll
    for (int r = 0; r < VR_; r++) bv[r] = y[OFF_BV + r * HD_ + d];

    #pragma unroll
    for (int h = 0; h < NH_; h++) {
        float accq = 0.f, acck = 0.f, accv = 0.f;
        #pragma unroll
        for (int r = 0; r < QR_; r++) accq += sA[h * QR_ + r] * bq[r];
        #pragma unroll
        for (int r = 0; r < KR_; r++) acck += sA[96 + h * KR_ + r] * bk[r];
        #pragma unroll
        for (int r = 0; r < VR_; r++) accv += sA[128 + h * VR_ + r] * bv[r];
        size_t o = (((size_t)b * NH_ + h) * S_ + s) * HD_ + d;
        __nv_bfloat16 hh, ll;
        split2(accq * (SCALING_F / (float)QR_), hh, ll);
        g_qh[o] = hh; g_ql[o] = ll;
        split2(acck * (1.f / (float)KR_), hh, ll);
        g_kh[o] = hh; g_kl[o] = ll;
        split2(accv * (1.f / (float)VR_), hh, ll);
        g_vh[o] = hh; g_vl[o] = ll;
    }
}

// ---------------- Flash attention v3 (bf16 3-term, 128-row q-tiles, warp-private softmax) ----------------
#define AQ_LD  136                      // bf16 row stride (272B)
#define QBUFB  (128*AQ_LD*2)            // Q buffer (hi or lo): 34816 B
#define BUFB   (64*AQ_LD*2)             // one K/V buffer: 17408 B
#define SM_QH  0
#define SM_QL  (SM_QH + QBUFB)
#define SM_KH  (SM_QL + QBUFB)          // [2] buffers
#define SM_KL  (SM_KH + 2*BUFB)
#define SM_VH  (SM_KL + 2*BUFB)
#define SM_VL  (SM_VH + 2*BUFB)
#define ATT_SMEM_BYTES (SM_VL + 2*BUFB) // 208896 B

__global__ __launch_bounds__(256, 1)
void attn_kernel(const float* __restrict__ mask)
{
    extern __shared__ char smc[];
    const uint32_t smb = smem_u32(smc);

    const int tid  = threadIdx.x;
    const int lane = tid & 31;
    const int wid  = tid >> 5;
    const int q0   = blockIdx.x * 128;
    const int h    = blockIdx.y;
    const int b    = blockIdx.z;

    const size_t headbase = ((size_t)b * NH_ + h) * S_ * HD_;

    const int crow = tid >> 2;
    const int ccg  = (tid & 3) * 32;
    auto issue_kv = [&](int kv0, int bi) {
        const size_t go = headbase + (size_t)(kv0 + crow) * HD_ + ccg;
        const uint32_t so = (uint32_t)(crow * AQ_LD + ccg) * 2 + bi * BUFB;
        #pragma unroll
        for (int j = 0; j < 4; j++) {
            CP16(smb + SM_KH + so + j*16, g_kh + go + j*8);
            CP16(smb + SM_KL + so + j*16, g_kl + go + j*8);
            CP16(smb + SM_VH + so + j*16, g_vh + go + j*8);
            CP16(smb + SM_VL + so + j*16, g_vl + go + j*8);
        }
        CP_COMMIT();
    };

    issue_kv(0, 0);

    {
        const int qrow = tid >> 1;
        const int qcg  = (tid & 1) * 64;
        const size_t go = headbase + (size_t)(q0 + qrow) * HD_ + qcg;
        __nv_bfloat16* Qh_s = (__nv_bfloat16*)(smc + SM_QH);
        __nv_bfloat16* Ql_s = (__nv_bfloat16*)(smc + SM_QL);
        #pragma unroll
        for (int j = 0; j < 8; j++) {
            *(uint4*)&Qh_s[qrow * AQ_LD + qcg + j*8] = *(const uint4*)(g_qh + go + j*8);
            *(uint4*)&Ql_s[qrow * AQ_LD + qcg + j*8] = *(const uint4*)(g_ql + go + j*8);
        }
    }
    CP_WAIT0();
    __syncthreads();

    float acc[16][4];
    #pragma unroll
    for (int i = 0; i < 16; i++)
        #pragma unroll
        for (int j = 0; j < 4; j++) acc[i][j] = 0.f;
    float lp0 = 0.f, lp1 = 0.f;
    float mold0 = -INFINITY, mold1 = -INFINITY;

    const int arow  = lane & 15;
    const int akoff = (lane >> 4) << 3;
    const int brow8 = (lane & 7) + ((lane >> 4) << 3);
    const int bkoff = ((lane >> 3) & 1) << 3;
    const int rl0   = wid * 16 + (lane >> 2);
    const float* maskrow0 = mask + ((size_t)b * S_ + q0 + rl0) * S_ + (lane & 3) * 2;
    const float* maskrow1 = maskrow0 + (size_t)8 * S_;

    for (int t = 0; t < S_ / 64; t++) {
        const int kv0 = t * 64;
        const int cur = t & 1;
        const bool pf = (t + 1 < S_ / 64);
        if (pf) issue_kv(kv0 + 64, cur ^ 1);

        const uint32_t kh = smb + SM_KH + cur * BUFB;
        const uint32_t kl = smb + SM_KL + cur * BUFB;
        const uint32_t vh = smb + SM_VH + cur * BUFB;
        const uint32_t vl = smb + SM_VL + cur * BUFB;
        const uint32_t qh = smb + SM_QH;
        const uint32_t ql = smb + SM_QL;

        float sc[8][4];
        #pragma unroll
        for (int i = 0; i < 8; i++)
            #pragma unroll
            for (int j = 0; j < 4; j++) sc[i][j] = 0.f;

        #pragma unroll
        for (int k0 = 0; k0 < 128; k0 += 16) {
            uint32_t ah[4], al[4];
            const uint32_t aoff = ((wid * 16 + arow) * AQ_LD + k0 + akoff) * 2;
            ldmx4(ah, qh + aoff);
            ldmx4(al, ql + aoff);
            #pragma unroll
            for (int nb = 0; nb < 4; nb++) {
                uint32_t bh[4], bl[4];
                const uint32_t boff = ((nb * 16 + brow8) * AQ_LD + k0 + bkoff) * 2;
                ldmx4(bh, kh + boff);
                ldmx4(bl, kl + boff);
                mma16816(sc[nb*2],   ah, bh);   mma16816(sc[nb*2+1], ah, bh + 2);
                mma16816(sc[nb*2],   al, bh);   mma16816(sc[nb*2+1], al, bh + 2);
                mma16816(sc[nb*2],   ah, bl);   mma16816(sc[nb*2+1], ah, bl + 2);
            }
        }

        float mr0 = -INFINITY, mr1 = -INFINITY;
        #pragma unroll
        for (int i = 0; i < 8; i++) {
            float2 m0 = *(const float2*)(maskrow0 + kv0 + i * 8);
            float2 m1 = *(const float2*)(maskrow1 + kv0 + i * 8);
            sc[i][0] += m0.x; sc[i][1] += m0.y;
            sc[i][2] += m1.x; sc[i][3] += m1.y;
            mr0 = fmaxf(mr0, fmaxf(sc[i][0], sc[i][1]));
            mr1 = fmaxf(mr1, fmaxf(sc[i][2], sc[i][3]));
        }
        mr0 = fmaxf(mr0, __shfl_xor_sync(0xffffffffu, mr0, 1));
        mr0 = fmaxf(mr0, __shfl_xor_sync(0xffffffffu, mr0, 2));
        mr1 = fmaxf(mr1, __shfl_xor_sync(0xffffffffu, mr1, 1));
        mr1 = fmaxf(mr1, __shfl_xor_sync(0xffffffffu, mr1, 2));

        const float mnew0 = fmaxf(mold0, mr0);
        const float mnew1 = fmaxf(mold1, mr1);
        const float f0 = __expf(mold0 - mnew0);
        const float f1 = __expf(mold1 - mnew1);
        mold0 = mnew0; mold1 = mnew1;
        float s0 = 0.f, s1 = 0.f;
        #pragma unroll
        for (int i = 0; i < 8; i++) {
            sc[i][0] = __expf(sc[i][0] - mnew0);
            sc[i][1] = __expf(sc[i][1] - mnew0);
            sc[i][2] = __expf(sc[i][2] - mnew1);
            sc[i][3] = __expf(sc[i][3] - mnew1);
            s0 += sc[i][0] + sc[i][1];
            s1 += sc[i][2] + sc[i][3];
        }
        s0 += __shfl_xor_sync(0xffffffffu, s0, 1);
        s0 += __shfl_xor_sync(0xffffffffu, s0, 2);
        s1 += __shfl_xor_sync(0xffffffffu, s1, 1);
        s1 += __shfl_xor_sync(0xffffffffu, s1, 2);
        lp0 = lp0 * f0 + s0;
        lp1 = lp1 * f1 + s1;
        #pragma unroll
        for (int i = 0; i < 16; i++) {
            acc[i][0] *= f0; acc[i][1] *= f0;
            acc[i][2] *= f1; acc[i][3] *= f1;
        }

        #pragma unroll
        for (int ks = 0; ks < 4; ks++) {
            uint32_t aPh[4], aPl[4];
            packsplit(sc[ks*2][0],   sc[ks*2][1],   aPh[0], aPl[0]);
            packsplit(sc[ks*2][2],   sc[ks*2][3],   aPh[1], aPl[1]);
            packsplit(sc[ks*2+1][0], sc[ks*2+1][1], aPh[2], aPl[2]);
            packsplit(sc[ks*2+1][2], sc[ks*2+1][3], aPh[3], aPl[3]);
            #pragma unroll
            for (int nb = 0; nb < 8; nb++) {
                uint32_t vfh[4], vfl[4];
                const uint32_t voff = ((ks * 16 + arow) * AQ_LD + nb * 16 + akoff) * 2;
                ldmx4t(vfh, vh + voff);
                ldmx4t(vfl, vl + voff);
                mma16816(acc[nb*2],   aPh, vfh);   mma16816(acc[nb*2+1], aPh, vfh + 2);
                mma16816(acc[nb*2],   aPl, vfh);   mma16816(acc[nb*2+1], aPl, vfh + 2);
                mma16816(acc[nb*2],   aPh, vfl);   mma16816(acc[nb*2+1], aPh, vfl + 2);
            }
        }

        if (pf) CP_WAIT0();
        __syncthreads();
    }

    // ---- epilogue: normalize, write fp16 [hi|lo] into g_Os (A-layout for gemm2) ----
    {
        const float inv0 = 1.f / lp0;
        const float inv1 = 1.f / lp1;
        const size_t row0 = ((size_t)b * S_ + q0 + rl0) * KS2_ + h * HD_;
        const size_t row1 = ((size_t)b * S_ + q0 + rl0 + 8) * KS2_ + h * HD_;
        #pragma unroll
        for (int ni = 0; ni < 16; ni++) {
            const int col = ni * 8 + (lane & 3) * 2;
            uint32_t ph, pl;
            packsplit_h(acc[ni][0] * inv0, acc[ni][1] * inv0, ph, pl);
            *(uint32_t*)(g_Os + row0 + col)        = ph;
            *(uint32_t*)(g_Os + row0 + col + HID_) = pl;
            packsplit_h(acc[ni][2] * inv1, acc[ni][3] * inv1, ph, pl);
            *(uint32_t*)(g_Os + row1 + col)        = ph;
            *(uint32_t*)(g_Os + row1 + col + HID_) = pl;
        }
    }
}

// ---------------- Host launcher ----------------
extern "C" void kernel_launch(void* const* d_in, const int* in_sizes, int n_in,
                              void* d_out, int out_size)
{
    const float* x    = (const float*)d_in[0];
    const float* cosb = (const float*)d_in[1];
    const float* sinb = (const float*)d_in[2];
    // d_in[3] = kv_write_indices (unused by reference)
    const float* mask = (const float*)d_in[4];
    const float* waq  = (const float*)d_in[5];
    const float* wak  = (const float*)d_in[6];
    const float* wav  = (const float*)d_in[7];
    const float* wbq  = (const float*)d_in[8];
    const float* wbk  = (const float*)d_in[9];
    const float* wbv  = (const float*)d_in[10];
    const float* wo   = (const float*)d_in[11];
    float* out = (float*)d_out;

    __half *pXs, *pWs, *pWos, *pOs;
    float *pY;
    cudaGetSymbolAddress((void**)&pXs,  g_Xs);
    cudaGetSymbolAddress((void**)&pWs,  g_Ws);
    cudaGetSymbolAddress((void**)&pWos, g_Wos);
    cudaGetSymbolAddress((void**)&pOs,  g_Os);
    cudaGetSymbolAddress((void**)&pY,   g_Y);

    // 1) conversions: X (A-layout [hi|lo]), Wcat (B-layout [hi|hi]), Wo (B-layout)
    split_fp16<<<(M_ * (HID_/4) + 255)/256, 256>>>(x, pXs, M_, HID_, 0);
    concat_w_split<<<(NPROJ_PAD * (HID_/4) + 255)/256, 256>>>(waq, wak, wav, wbq, wbk, wbv);
    split_fp16<<<(HID_ * (HID_/4) + 255)/256, 256>>>(wo, pWos, HID_, HID_, 1);

    // 2) projection GEMM (fp16 2-term, K'=4096)
    cudaFuncSetAttribute(gemm_fp16, cudaFuncAttributeMaxDynamicSharedMemorySize, GEMM_SMEM);
    gemm_fp16<<<dim3(NPROJ_PAD/128, M_/128), 256, GEMM_SMEM>>>(pXs, pWs, pY, NPROJ, NPROJ, KS2_);

    // 3) RoPE + contraction (bf16 split outputs, unchanged)
    rope_contract_kernel<<<M_, 128>>>(cosb, sinb);

    // 4) attention (bf16 3-term, unchanged internals; fp16 2-seg epilogue)
    cudaFuncSetAttribute(attn_kernel, cudaFuncAttributeMaxDynamicSharedMemorySize, ATT_SMEM_BYTES);
    attn_kernel<<<dim3(S_/128, NH_, B_), 256, ATT_SMEM_BYTES>>>(mask);

    // 5) output GEMM (fp16 2-term, K'=4096)
    gemm_fp16<<<dim3(HID_/128, M_/128), 256, GEMM_SMEM>>>(pOs, pWos, out, HID_, HID_, KS2_);
}

// round 12
// speedup vs baseline: 7.4038x; 1.2149x over previous
#include <cuda_runtime.h>
#include <cuda_bf16.h>
#include <cuda_fp16.h>
#include <math.h>
#include <stdint.h>

// ---------------- Problem constants ----------------
#define B_    2
#define S_    2048
#define HID_  2048
#define NH_   16
#define HD_   128
#define QR_   6
#define KR_   2
#define VR_   2
#define M_    (B_*S_)          // 4096 tokens
#define NPROJ 1440
#define NPROJ_PAD 1536
#define KS2_  (2*HID_)         // 4096: fp16 2-term split  A=[hi|lo], B=[hi|hi]
#define SCALING_F 0.08838834764831845f  // 128^-0.5

// Y row layout offsets
#define OFF_AQ 0
#define OFF_AK 96
#define OFF_AV 128
#define OFF_BQ 160
#define OFF_BK 928
#define OFF_BV 1184

// ---------------- Scratch (device globals; no allocation allowed) ----------------
__device__ __half g_Xs [(size_t)M_ * KS2_];        // hidden [hi|lo] fp16
__device__ __half g_Ws [(size_t)NPROJ_PAD * KS2_]; // Wcat  [hi|hi] fp16
__device__ __half g_Wos[(size_t)HID_ * KS2_];      // W_o   [hi|hi] fp16
__device__ __half g_Os [(size_t)M_ * KS2_];        // attn out [hi|lo] fp16
__device__ float g_Y[(size_t)M_ * NPROJ];          // projections fp32
__device__ __half g_qh[(size_t)B_*NH_*S_*HD_];     // q hi (fp16)
__device__ __half g_ql[(size_t)B_*NH_*S_*HD_];     // q lo
__device__ __half g_kh[(size_t)B_*NH_*S_*HD_];     // k hi only
__device__ __half g_vh[(size_t)B_*NH_*S_*HD_];     // v hi only

// ---------------- helpers ----------------
__device__ __forceinline__ uint32_t smem_u32(const void* p) {
    uint32_t a;
    asm("{ .reg .u64 t; cvta.to.shared.u64 t, %1; cvt.u32.u64 %0, t; }" : "=r"(a) : "l"(p));
    return a;
}
__device__ __forceinline__ void split2h(float x, __half& h, __half& l) {
    h = __float2half_rn(x);
    l = __float2half_rn(x - __half2float(h));
}
__device__ __forceinline__ void packsplit_h(float a, float b, uint32_t& ph, uint32_t& pl) {
    __half ha, la, hb, lb;
    split2h(a, ha, la); split2h(b, hb, lb);
    __half2 H; H.x = ha; H.y = hb;
    __half2 L; L.x = la; L.y = lb;
    ph = *(uint32_t*)&H; pl = *(uint32_t*)&L;
}
__device__ __forceinline__ void ldmx4(uint32_t* r, uint32_t addr) {
    asm volatile("ldmatrix.sync.aligned.m8n8.x4.shared.b16 {%0,%1,%2,%3}, [%4];"
                 : "=r"(r[0]), "=r"(r[1]), "=r"(r[2]), "=r"(r[3]) : "r"(addr));
}
__device__ __forceinline__ void ldmx4t(uint32_t* r, uint32_t addr) {
    asm volatile("ldmatrix.sync.aligned.m8n8.x4.trans.shared.b16 {%0,%1,%2,%3}, [%4];"
                 : "=r"(r[0]), "=r"(r[1]), "=r"(r[2]), "=r"(r[3]) : "r"(addr));
}
__device__ __forceinline__ void mma16816h(float* c, const uint32_t* a, const uint32_t* b) {
    asm volatile(
        "mma.sync.aligned.m16n8k16.row.col.f32.f16.f16.f32 "
        "{%0,%1,%2,%3}, {%4,%5,%6,%7}, {%8,%9}, {%0,%1,%2,%3};"
        : "+f"(c[0]), "+f"(c[1]), "+f"(c[2]), "+f"(c[3])
        : "r"(a[0]), "r"(a[1]), "r"(a[2]), "r"(a[3]), "r"(b[0]), "r"(b[1]));
}
#define CP16(dst, src) \
    asm volatile("cp.async.cg.shared.global [%0], [%1], 16;" \
                 :: "r"(dst), "l"((size_t)__cvta_generic_to_global(src)) : "memory")
#define CP_COMMIT() asm volatile("cp.async.commit_group;" ::: "memory")
#define CP_WAIT0()  asm volatile("cp.async.wait_group 0;" ::: "memory")
#define CP_WAIT2()  asm volatile("cp.async.wait_group 2;" ::: "memory")

// ---------------- Kernel: split fp32 -> fp16 2-seg along K ----------------
// mode 0 (A-operand): [hi | lo]    mode 1 (B-operand): [hi | hi]
__global__ void split_fp16(const float* __restrict__ src, __half* __restrict__ dst,
                           int rows, int cols, int mode)
{
    int idx = blockIdx.x * blockDim.x + threadIdx.x;
    int c4n = cols >> 2;
    if (idx >= rows * c4n) return;
    int r  = idx / c4n;
    int c  = (idx - r * c4n) << 2;
    float4 v = *(const float4*)(src + (size_t)r * cols + c);
    __half h[4], l[4];
    split2h(v.x, h[0], l[0]); split2h(v.y, h[1], l[1]);
    split2h(v.z, h[2], l[2]); split2h(v.w, h[3], l[3]);
    size_t base = (size_t)r * (2 * cols) + c;
    *(uint2*)(dst + base) = *(uint2*)h;
    if (mode == 0) *(uint2*)(dst + base + cols) = *(uint2*)l;
    else           *(uint2*)(dst + base + cols) = *(uint2*)h;
}

// ---------------- Kernel: concat 6 weight mats + fp16 split -> g_Ws [1536][4096] (B layout) ----------------
__global__ void concat_w_split(const float* __restrict__ waq, const float* __restrict__ wak,
                               const float* __restrict__ wav, const float* __restrict__ wbq,
                               const float* __restrict__ wbk, const float* __restrict__ wbv)
{
    int idx = blockIdx.x * blockDim.x + threadIdx.x;
    if (idx >= NPROJ_PAD * (HID_ / 4)) return;
    int row = idx >> 9;
    int c   = (idx & 511) << 2;
    float4 v = make_float4(0.f, 0.f, 0.f, 0.f);
    if (row < NPROJ) {
        const float* src; int r;
        if      (row < OFF_AK) { src = waq; r = row;          }
        else if (row < OFF_AV) { src = wak; r = row - OFF_AK; }
        else if (row < OFF_BQ) { src = wav; r = row - OFF_AV; }
        else if (row < OFF_BK) { src = wbq; r = row - OFF_BQ; }
        else if (row < OFF_BV) { src = wbk; r = row - OFF_BK; }
        else                   { src = wbv; r = row - OFF_BV; }
        v = *(const float4*)(src + (size_t)r * HID_ + c);
    }
    __half h[4];
    h[0] = __float2half_rn(v.x); h[1] = __float2half_rn(v.y);
    h[2] = __float2half_rn(v.z); h[3] = __float2half_rn(v.w);
    size_t base = (size_t)row * KS2_ + c;
    *(uint2*)(g_Ws + base)        = *(uint2*)h;   // hi
    *(uint2*)(g_Ws + base + HID_) = *(uint2*)h;   // hi (pairs with A's lo segment)
}

// ---------------- HMMA fp16 GEMM (NT), 4-stage cp.async pipeline (verified) ----------------
#define BK_ 32
#define LDA_ 40
#define GSTAGES 4
#define GEMM_SMEM (GSTAGES * 2 * 128 * LDA_ * 2)   // 81920 B

__global__ __launch_bounds__(256, 2)
void gemm_fp16(const __half* __restrict__ A, const __half* __restrict__ Bm,
               float* __restrict__ C, int Nreal, int ldc, int Kp)
{
    extern __shared__ char gsm[];
    __half* sAB = (__half*)gsm;   // [stage][2][128][LDA_]

    const int tid  = threadIdx.x;
    const int lane = tid & 31;
    const int wid  = tid >> 5;
    const int wm   = wid & 3;
    const int wn   = wid >> 2;
    const int bm   = blockIdx.y * 128;
    const int bn   = blockIdx.x * 128;

    const int lrow = tid >> 1;
    const int lseg = (tid & 1) * 16;
    const __half* arow = A  + (size_t)(bm + lrow) * Kp + lseg;
    const __half* brow = Bm + (size_t)(bn + lrow) * Kp + lseg;

    float acc[2][8][4];
    #pragma unroll
    for (int i = 0; i < 2; i++)
        #pragma unroll
        for (int j = 0; j < 8; j++)
            #pragma unroll
            for (int q = 0; q < 4; q++) acc[i][j][q] = 0.f;

    const int iters = Kp / BK_;

    auto issue = [&](int it, int bi) {
        const __half* as = arow + it * BK_;
        const __half* bs = brow + it * BK_;
        uint32_t da = smem_u32(&sAB[((bi*2 + 0)*128 + lrow)*LDA_ + lseg]);
        uint32_t db = smem_u32(&sAB[((bi*2 + 1)*128 + lrow)*LDA_ + lseg]);
        CP16(da,      as);
        CP16(da + 16, as + 8);
        CP16(db,      bs);
        CP16(db + 16, bs + 8);
        CP_COMMIT();
    };

    issue(0, 0);
    issue(1, 1);
    issue(2, 2);

    const int arow16 = lane & 15;
    const int akoff  = (lane >> 4) << 3;
    const int brow8  = (lane & 7) + ((lane >> 4) << 3);
    const int bkoff  = ((lane >> 3) & 1) << 3;

    for (int it = 0; it < iters; it++) {
        const int cur = it & 3;
        CP_WAIT2();
        __syncthreads();
        if (it + 3 < iters) issue(it + 3, (it + 3) & 3);
        else CP_COMMIT();   // keep group cadence

        #pragma unroll
        for (int ks = 0; ks < 2; ks++) {
            const int k0 = ks * 16;
            uint32_t ar[2][4];
            #pragma unroll
            for (int mf = 0; mf < 2; mf++)
                ldmx4(ar[mf], smem_u32(&sAB[((cur*2 + 0)*128 + wm*32 + mf*16 + arow16)*LDA_ + k0 + akoff]));
            uint32_t br[8][2];
            #pragma unroll
            for (int nf2 = 0; nf2 < 4; nf2++) {
                uint32_t r[4];
                ldmx4(r, smem_u32(&sAB[((cur*2 + 1)*128 + wn*64 + nf2*16 + brow8)*LDA_ + k0 + bkoff]));
                br[2*nf2][0] = r[0]; br[2*nf2][1] = r[1];
                br[2*nf2+1][0] = r[2]; br[2*nf2+1][1] = r[3];
            }
            #pragma unroll
            for (int mf = 0; mf < 2; mf++)
                #pragma unroll
                for (int nf = 0; nf < 8; nf++)
                    mma16816h(acc[mf][nf], ar[mf], br[nf]);
        }
    }

    #pragma unroll
    for (int mf = 0; mf < 2; mf++) {
        const int grow = bm + wm * 32 + mf * 16 + (lane >> 2);
        #pragma unroll
        for (int nf = 0; nf < 8; nf++) {
            const int gcol = bn + wn * 64 + nf * 8 + (lane & 3) * 2;
            if (gcol < Nreal) {
                *(float2*)(C + (size_t)grow * ldc + gcol) =
                    make_float2(acc[mf][nf][0], acc[mf][nf][1]);
                *(float2*)(C + (size_t)(grow + 8) * ldc + gcol) =
                    make_float2(acc[mf][nf][2], acc[mf][nf][3]);
            }
        }
    }
}

// ---------------- RoPE + rank contraction -> fp16 q(hi,lo), k(hi), v(hi) ----------------
__global__ void rope_contract_kernel(const float* __restrict__ cosb, const float* __restrict__ sinb)
{
    int token = blockIdx.x;
    int b = token / S_;
    int s = token % S_;
    const float* y = g_Y + (size_t)token * NPROJ;
    int d = threadIdx.x;

    __shared__ float sA[160];
    for (int i = d; i < 160; i += 128) sA[i] = y[i];
    __syncthreads();

    int dh = d & 63;
    float c  = cosb[s * 64 + dh];
    float sn = sinb[s * 64 + dh];
    bool hi = (d >= 64);

    float bq[QR_], bk[KR_], bv[VR_];
    #pragma unroll
    for (int r = 0; r < QR_; r++) {
        float x1 = y[OFF_BQ + r * HD_ + dh];
        float x2 = y[OFF_BQ + r * HD_ + 64 + dh];
        bq[r] = hi ? (x1 * sn + x2 * c) : (x1 * c - x2 * sn);
    }
    #pragma unroll
    for (int r = 0; r < KR_; r++) {
        float x1 = y[OFF_BK + r * HD_ + dh];
        float x2 = y[OFF_BK + r * HD_ + 64 + dh];
        bk[r] = hi ? (x1 * sn + x2 * c) : (x1 * c - x2 * sn);
    }
    #pragma unroll
    for (int r = 0; r < VR_; r++) bv[r] = y[OFF_BV + r * HD_ + d];

    #pragma unroll
    for (int h = 0; h < NH_; h++) {
        float accq = 0.f, acck = 0.f, accv = 0.f;
        #pragma unroll
        for (int r = 0; r < QR_; r++) accq += sA[h * QR_ + r] * bq[r];
        #pragma unroll
        for (int r = 0; r < KR_; r++) acck += sA[96 + h * KR_ + r] * bk[r];
        #pragma unroll
        for (int r = 0; r < VR_; r++) accv += sA[128 + h * VR_ + r] * bv[r];
        size_t o = (((size_t)b * NH_ + h) * S_ + s) * HD_ + d;
        __half hh, ll;
        split2h(accq * (SCALING_F / (float)QR_), hh, ll);
        g_qh[o] = hh; g_ql[o] = ll;
        g_kh[o] = __float2half_rn(acck * (1.f / (float)KR_));
        g_vh[o] = __float2half_rn(accv * (1.f / (float)VR_));
    }
}

// ---------------- Flash attention v4: fp16 2-term, K/V hi-only ----------------
// QK = Qh*Kh + Ql*Kh ; PV = Ph*Vh + Pl*Vh  (128 MMAs/tile, KV smem halved)
#define AQ_LD  136                      // fp16 row stride (272B)
#define QBUFB  (128*AQ_LD*2)            // Q buffer (hi or lo): 34816 B
#define BUFB   (64*AQ_LD*2)             // one K/V buffer: 17408 B
#define SM_QH  0
#define SM_QL  (SM_QH + QBUFB)
#define SM_KH  (SM_QL + QBUFB)          // [2] buffers
#define SM_VH  (SM_KH + 2*BUFB)
#define ATT_SMEM_BYTES (SM_VH + 2*BUFB) // 139264 B

__global__ __launch_bounds__(256, 1)
void attn_kernel(const float* __restrict__ mask)
{
    extern __shared__ char smc[];
    const uint32_t smb = smem_u32(smc);

    const int tid  = threadIdx.x;
    const int lane = tid & 31;
    const int wid  = tid >> 5;
    const int q0   = blockIdx.x * 128;
    const int h    = blockIdx.y;
    const int b    = blockIdx.z;

    const size_t headbase = ((size_t)b * NH_ + h) * S_ * HD_;

    // KV cp.async: 256 threads cover 64 rows x 128 cols x 2 arrays
    const int crow = tid >> 2;
    const int ccg  = (tid & 3) * 32;
    auto issue_kv = [&](int kv0, int bi) {
        const size_t go = headbase + (size_t)(kv0 + crow) * HD_ + ccg;
        const uint32_t so = (uint32_t)(crow * AQ_LD + ccg) * 2 + bi * BUFB;
        #pragma unroll
        for (int j = 0; j < 4; j++) {
            CP16(smb + SM_KH + so + j*16, g_kh + go + j*8);
            CP16(smb + SM_VH + so + j*16, g_vh + go + j*8);
        }
        CP_COMMIT();
    };

    issue_kv(0, 0);

    // Q tile: 128 rows x 128 cols, hi+lo (direct loads)
    {
        const int qrow = tid >> 1;
        const int qcg  = (tid & 1) * 64;
        const size_t go = headbase + (size_t)(q0 + qrow) * HD_ + qcg;
        __half* Qh_s = (__half*)(smc + SM_QH);
        __half* Ql_s = (__half*)(smc + SM_QL);
        #pragma unroll
        for (int j = 0; j < 8; j++) {
            *(uint4*)&Qh_s[qrow * AQ_LD + qcg + j*8] = *(const uint4*)(g_qh + go + j*8);
            *(uint4*)&Ql_s[qrow * AQ_LD + qcg + j*8] = *(const uint4*)(g_ql + go + j*8);
        }
    }
    CP_WAIT0();
    __syncthreads();

    float acc[16][4];
    #pragma unroll
    for (int i = 0; i < 16; i++)
        #pragma unroll
        for (int j = 0; j < 4; j++) acc[i][j] = 0.f;
    float lp0 = 0.f, lp1 = 0.f;
    float mold0 = -INFINITY, mold1 = -INFINITY;

    const int arow  = lane & 15;
    const int akoff = (lane >> 4) << 3;
    const int brow8 = (lane & 7) + ((lane >> 4) << 3);
    const int bkoff = ((lane >> 3) & 1) << 3;
    const int rl0   = wid * 16 + (lane >> 2);
    const float* maskrow0 = mask + ((size_t)b * S_ + q0 + rl0) * S_ + (lane & 3) * 2;
    const float* maskrow1 = maskrow0 + (size_t)8 * S_;

    for (int t = 0; t < S_ / 64; t++) {
        const int kv0 = t * 64;
        const int cur = t & 1;
        const bool pf = (t + 1 < S_ / 64);
        if (pf) issue_kv(kv0 + 64, cur ^ 1);

        const uint32_t kh = smb + SM_KH + cur * BUFB;
        const uint32_t vh = smb + SM_VH + cur * BUFB;
        const uint32_t qh = smb + SM_QH;
        const uint32_t ql = smb + SM_QL;

        // ---- QK^T (fp16 2-term): 16 x 64 per warp ----
        float sc[8][4];
        #pragma unroll
        for (int i = 0; i < 8; i++)
            #pragma unroll
            for (int j = 0; j < 4; j++) sc[i][j] = 0.f;

        #pragma unroll
        for (int k0 = 0; k0 < 128; k0 += 16) {
            uint32_t ah[4], al[4];
            const uint32_t aoff = ((wid * 16 + arow) * AQ_LD + k0 + akoff) * 2;
            ldmx4(ah, qh + aoff);
            ldmx4(al, ql + aoff);
            #pragma unroll
            for (int nb = 0; nb < 4; nb++) {
                uint32_t bh[4];
                const uint32_t boff = ((nb * 16 + brow8) * AQ_LD + k0 + bkoff) * 2;
                ldmx4(bh, kh + boff);
                mma16816h(sc[nb*2],   ah, bh);   mma16816h(sc[nb*2+1], ah, bh + 2);
                mma16816h(sc[nb*2],   al, bh);   mma16816h(sc[nb*2+1], al, bh + 2);
            }
        }

        // ---- add mask + warp-local row max ----
        float mr0 = -INFINITY, mr1 = -INFINITY;
        #pragma unroll
        for (int i = 0; i < 8; i++) {
            float2 m0 = *(const float2*)(maskrow0 + kv0 + i * 8);
            float2 m1 = *(const float2*)(maskrow1 + kv0 + i * 8);
            sc[i][0] += m0.x; sc[i][1] += m0.y;
            sc[i][2] += m1.x; sc[i][3] += m1.y;
            mr0 = fmaxf(mr0, fmaxf(sc[i][0], sc[i][1]));
            mr1 = fmaxf(mr1, fmaxf(sc[i][2], sc[i][3]));
        }
        mr0 = fmaxf(mr0, __shfl_xor_sync(0xffffffffu, mr0, 1));
        mr0 = fmaxf(mr0, __shfl_xor_sync(0xffffffffu, mr0, 2));
        mr1 = fmaxf(mr1, __shfl_xor_sync(0xffffffffu, mr1, 1));
        mr1 = fmaxf(mr1, __shfl_xor_sync(0xffffffffu, mr1, 2));

        // ---- softmax update (warp-private) ----
        const float mnew0 = fmaxf(mold0, mr0);
        const float mnew1 = fmaxf(mold1, mr1);
        const float f0 = __expf(mold0 - mnew0);
        const float f1 = __expf(mold1 - mnew1);
        mold0 = mnew0; mold1 = mnew1;
        float s0 = 0.f, s1 = 0.f;
        #pragma unroll
        for (int i = 0; i < 8; i++) {
            sc[i][0] = __expf(sc[i][0] - mnew0);
            sc[i][1] = __expf(sc[i][1] - mnew0);
            sc[i][2] = __expf(sc[i][2] - mnew1);
            sc[i][3] = __expf(sc[i][3] - mnew1);
            s0 += sc[i][0] + sc[i][1];
            s1 += sc[i][2] + sc[i][3];
        }
        s0 += __shfl_xor_sync(0xffffffffu, s0, 1);
        s0 += __shfl_xor_sync(0xffffffffu, s0, 2);
        s1 += __shfl_xor_sync(0xffffffffu, s1, 1);
        s1 += __shfl_xor_sync(0xffffffffu, s1, 2);
        lp0 = lp0 * f0 + s0;
        lp1 = lp1 * f1 + s1;
        #pragma unroll
        for (int i = 0; i < 16; i++) {
            acc[i][0] *= f0; acc[i][1] *= f0;
            acc[i][2] *= f1; acc[i][3] *= f1;
        }

        // ---- PV (fp16 2-term): P from registers, V hi-only ----
        #pragma unroll
        for (int ks = 0; ks < 4; ks++) {
            uint32_t aPh[4], aPl[4];
            packsplit_h(sc[ks*2][0],   sc[ks*2][1],   aPh[0], aPl[0]);
            packsplit_h(sc[ks*2][2],   sc[ks*2][3],   aPh[1], aPl[1]);
            packsplit_h(sc[ks*2+1][0], sc[ks*2+1][1], aPh[2], aPl[2]);
            packsplit_h(sc[ks*2+1][2], sc[ks*2+1][3], aPh[3], aPl[3]);
            #pragma unroll
            for (int nb = 0; nb < 8; nb++) {
                uint32_t vfh[4];
                const uint32_t voff = ((ks * 16 + arow) * AQ_LD + nb * 16 + akoff) * 2;
                ldmx4t(vfh, vh + voff);
                mma16816h(acc[nb*2],   aPh, vfh);   mma16816h(acc[nb*2+1], aPh, vfh + 2);
                mma16816h(acc[nb*2],   aPl, vfh);   mma16816h(acc[nb*2+1], aPl, vfh + 2);
            }
        }

        if (pf) CP_WAIT0();
        __syncthreads();
    }

    // ---- epilogue: normalize, write fp16 [hi|lo] into g_Os (A-layout for gemm2) ----
    {
        const float inv0 = 1.f / lp0;
        const float inv1 = 1.f / lp1;
        const size_t row0 = ((size_t)b * S_ + q0 + rl0) * KS2_ + h * HD_;
        const size_t row1 = ((size_t)b * S_ + q0 + rl0 + 8) * KS2_ + h * HD_;
        #pragma unroll
        for (int ni = 0; ni < 16; ni++) {
            const int col = ni * 8 + (lane & 3) * 2;
            uint32_t ph, pl;
            packsplit_h(acc[ni][0] * inv0, acc[ni][1] * inv0, ph, pl);
            *(uint32_t*)(g_Os + row0 + col)        = ph;
            *(uint32_t*)(g_Os + row0 + col + HID_) = pl;
            packsplit_h(acc[ni][2] * inv1, acc[ni][3] * inv1, ph, pl);
            *(uint32_t*)(g_Os + row1 + col)        = ph;
            *(uint32_t*)(g_Os + row1 + col + HID_) = pl;
        }
    }
}

// ---------------- Host launcher ----------------
extern "C" void kernel_launch(void* const* d_in, const int* in_sizes, int n_in,
                              void* d_out, int out_size)
{
    const float* x    = (const float*)d_in[0];
    const float* cosb = (const float*)d_in[1];
    const float* sinb = (const float*)d_in[2];
    // d_in[3] = kv_write_indices (unused by reference)
    const float* mask = (const float*)d_in[4];
    const float* waq  = (const float*)d_in[5];
    const float* wak  = (const float*)d_in[6];
    const float* wav  = (const float*)d_in[7];
    const float* wbq  = (const float*)d_in[8];
    const float* wbk  = (const float*)d_in[9];
    const float* wbv  = (const float*)d_in[10];
    const float* wo   = (const float*)d_in[11];
    float* out = (float*)d_out;

    __half *pXs, *pWs, *pWos, *pOs;
    float *pY;
    cudaGetSymbolAddress((void**)&pXs,  g_Xs);
    cudaGetSymbolAddress((void**)&pWs,  g_Ws);
    cudaGetSymbolAddress((void**)&pWos, g_Wos);
    cudaGetSymbolAddress((void**)&pOs,  g_Os);
    cudaGetSymbolAddress((void**)&pY,   g_Y);

    // 1) conversions: X (A-layout [hi|lo]), Wcat (B-layout [hi|hi]), Wo (B-layout)
    split_fp16<<<(M_ * (HID_/4) + 255)/256, 256>>>(x, pXs, M_, HID_, 0);
    concat_w_split<<<(NPROJ_PAD * (HID_/4) + 255)/256, 256>>>(waq, wak, wav, wbq, wbk, wbv);
    split_fp16<<<(HID_ * (HID_/4) + 255)/256, 256>>>(wo, pWos, HID_, HID_, 1);

    // 2) projection GEMM (fp16 2-term, K'=4096)
    cudaFuncSetAttribute(gemm_fp16, cudaFuncAttributeMaxDynamicSharedMemorySize, GEMM_SMEM);
    gemm_fp16<<<dim3(NPROJ_PAD/128, M_/128), 256, GEMM_SMEM>>>(pXs, pWs, pY, NPROJ, NPROJ, KS2_);

    // 3) RoPE + contraction (fp16 outputs: q hi/lo, k hi, v hi)
    rope_contract_kernel<<<M_, 128>>>(cosb, sinb);

    // 4) attention (fp16 2-term QK and PV, K/V hi-only)
    cudaFuncSetAttribute(attn_kernel, cudaFuncAttributeMaxDynamicSharedMemorySize, ATT_SMEM_BYTES);
    attn_kernel<<<dim3(S_/128, NH_, B_), 256, ATT_SMEM_BYTES>>>(mask);

    // 5) output GEMM (fp16 2-term, K'=4096)
    gemm_fp16<<<dim3(HID_/128, M_/128), 256, GEMM_SMEM>>>(pOs, pWos, out, HID_, HID_, KS2_);
}

// round 13
// speedup vs baseline: 8.0716x; 1.0902x over previous
#include <cuda_runtime.h>
#include <cuda_fp16.h>
#include <math.h>
#include <stdint.h>

// ---------------- Problem constants ----------------
#define B_    2
#define S_    2048
#define HID_  2048
#define NH_   16
#define HD_   128
#define QR_   6
#define KR_   2
#define VR_   2
#define M_    (B_*S_)          // 4096 tokens
#define NPROJ 1440
#define NPROJ_PAD 1536
#define SCALING_F 0.08838834764831845f  // 128^-0.5

// Y row layout offsets
#define OFF_AQ 0
#define OFF_AK 96
#define OFF_AV 128
#define OFF_BQ 160
#define OFF_BK 928
#define OFF_BV 1184

// ---------------- Scratch (device globals; no allocation allowed) ----------------
__device__ __half g_Xs [(size_t)M_ * 2 * HID_];    // hidden A-layout [hi|lo]
__device__ __half g_Ws [(size_t)NPROJ_PAD * HID_]; // Wcat plain fp16
__device__ __half g_Wos[(size_t)HID_ * HID_];      // W_o plain fp16
__device__ __half g_Os [(size_t)M_ * 2 * HID_];    // attn out A-layout [hi|lo]
__device__ float g_Y[(size_t)M_ * NPROJ];          // projections fp32
__device__ __half g_qh[(size_t)B_*NH_*S_*HD_];     // q fp16 (hi only)
__device__ __half g_kh[(size_t)B_*NH_*S_*HD_];     // k fp16
__device__ __half g_vh[(size_t)B_*NH_*S_*HD_];     // v fp16

// ---------------- helpers ----------------
__device__ __forceinline__ uint32_t smem_u32(const void* p) {
    uint32_t a;
    asm("{ .reg .u64 t; cvta.to.shared.u64 t, %1; cvt.u32.u64 %0, t; }" : "=r"(a) : "l"(p));
    return a;
}
__device__ __forceinline__ void split2h(float x, __half& h, __half& l) {
    h = __float2half_rn(x);
    l = __float2half_rn(x - __half2float(h));
}
__device__ __forceinline__ void packsplit_h(float a, float b, uint32_t& ph, uint32_t& pl) {
    __half ha, la, hb, lb;
    split2h(a, ha, la); split2h(b, hb, lb);
    __half2 H; H.x = ha; H.y = hb;
    __half2 L; L.x = la; L.y = lb;
    ph = *(uint32_t*)&H; pl = *(uint32_t*)&L;
}
__device__ __forceinline__ void ldmx4(uint32_t* r, uint32_t addr) {
    asm volatile("ldmatrix.sync.aligned.m8n8.x4.shared.b16 {%0,%1,%2,%3}, [%4];"
                 : "=r"(r[0]), "=r"(r[1]), "=r"(r[2]), "=r"(r[3]) : "r"(addr));
}
__device__ __forceinline__ void ldmx4t(uint32_t* r, uint32_t addr) {
    asm volatile("ldmatrix.sync.aligned.m8n8.x4.trans.shared.b16 {%0,%1,%2,%3}, [%4];"
                 : "=r"(r[0]), "=r"(r[1]), "=r"(r[2]), "=r"(r[3]) : "r"(addr));
}
__device__ __forceinline__ void mma16816h(float* c, const uint32_t* a, const uint32_t* b) {
    asm volatile(
        "mma.sync.aligned.m16n8k16.row.col.f32.f16.f16.f32 "
        "{%0,%1,%2,%3}, {%4,%5,%6,%7}, {%8,%9}, {%0,%1,%2,%3};"
        : "+f"(c[0]), "+f"(c[1]), "+f"(c[2]), "+f"(c[3])
        : "r"(a[0]), "r"(a[1]), "r"(a[2]), "r"(a[3]), "r"(b[0]), "r"(b[1]));
}
#define CP16(dst, src) \
    asm volatile("cp.async.cg.shared.global [%0], [%1], 16;" \
                 :: "r"(dst), "l"((size_t)__cvta_generic_to_global(src)) : "memory")
#define CP_COMMIT() asm volatile("cp.async.commit_group;" ::: "memory")
#define CP_WAIT0()  asm volatile("cp.async.wait_group 0;" ::: "memory")
#define CP_WAIT1()  asm volatile("cp.async.wait_group 1;" ::: "memory")

// ---------------- Kernel: fp32 -> fp16 split ----------------
// mode 0 (A-operand): [hi | lo], row stride 2*cols.  mode 1 (B-operand): hi only, row stride cols.
__global__ void split_fp16(const float* __restrict__ src, __half* __restrict__ dst,
                           int rows, int cols, int mode)
{
    int idx = blockIdx.x * blockDim.x + threadIdx.x;
    int c4n = cols >> 2;
    if (idx >= rows * c4n) return;
    int r  = idx / c4n;
    int c  = (idx - r * c4n) << 2;
    float4 v = *(const float4*)(src + (size_t)r * cols + c);
    __half h[4], l[4];
    split2h(v.x, h[0], l[0]); split2h(v.y, h[1], l[1]);
    split2h(v.z, h[2], l[2]); split2h(v.w, h[3], l[3]);
    if (mode == 0) {
        size_t base = (size_t)r * (2 * cols) + c;
        *(uint2*)(dst + base)        = *(uint2*)h;
        *(uint2*)(dst + base + cols) = *(uint2*)l;
    } else {
        *(uint2*)(dst + (size_t)r * cols + c) = *(uint2*)h;
    }
}

// ---------------- Kernel: concat 6 weight mats -> g_Ws [1536][2048] plain fp16 ----------------
__global__ void concat_w_split(const float* __restrict__ waq, const float* __restrict__ wak,
                               const float* __restrict__ wav, const float* __restrict__ wbq,
                               const float* __restrict__ wbk, const float* __restrict__ wbv)
{
    int idx = blockIdx.x * blockDim.x + threadIdx.x;
    if (idx >= NPROJ_PAD * (HID_ / 4)) return;
    int row = idx >> 9;
    int c   = (idx & 511) << 2;
    float4 v = make_float4(0.f, 0.f, 0.f, 0.f);
    if (row < NPROJ) {
        const float* src; int r;
        if      (row < OFF_AK) { src = waq; r = row;          }
        else if (row < OFF_AV) { src = wak; r = row - OFF_AK; }
        else if (row < OFF_BQ) { src = wav; r = row - OFF_AV; }
        else if (row < OFF_BK) { src = wbq; r = row - OFF_BQ; }
        else if (row < OFF_BV) { src = wbk; r = row - OFF_BK; }
        else                   { src = wbv; r = row - OFF_BV; }
        v = *(const float4*)(src + (size_t)r * HID_ + c);
    }
    __half h[4];
    h[0] = __float2half_rn(v.x); h[1] = __float2half_rn(v.y);
    h[2] = __float2half_rn(v.z); h[3] = __float2half_rn(v.w);
    *(uint2*)(g_Ws + (size_t)row * HID_ + c) = *(uint2*)h;
}

// ---------------- HMMA fp16 GEMM: C = (Ah+Al) * B^T, shared-B fragments ----------------
// A: [M][2K] ([hi|lo]), B: [N][K]. 3-stage cp.async, BK=32, K=2048 -> 64 iters.
#define BK_ 32
#define LDA_ 40
#define GST 3
#define SLOT_H (128*LDA_)                  // one tile slot in halves
#define GEMM_SMEM (GST * 3 * SLOT_H * 2)   // 92160 B

__global__ __launch_bounds__(256, 2)
void gemm_fp16(const __half* __restrict__ A, const __half* __restrict__ Bm,
               float* __restrict__ C, int Nreal, int ldc, int K)
{
    extern __shared__ char gsm[];
    __half* sm = (__half*)gsm;   // [stage][3 slots: Ah, Al, B][128][LDA_]

    const int tid  = threadIdx.x;
    const int lane = tid & 31;
    const int wid  = tid >> 5;
    const int wm   = wid & 3;
    const int wn   = wid >> 2;
    const int bm   = blockIdx.y * 128;
    const int bn   = blockIdx.x * 128;

    const int lrow = tid >> 1;
    const int lseg = (tid & 1) * 16;
    const __half* ahrow = A  + (size_t)(bm + lrow) * (2 * K) + lseg;
    const __half* alrow = ahrow + K;
    const __half* browp = Bm + (size_t)(bn + lrow) * K + lseg;

    float acc[2][8][4];
    #pragma unroll
    for (int i = 0; i < 2; i++)
        #pragma unroll
        for (int j = 0; j < 8; j++)
            #pragma unroll
            for (int q = 0; q < 4; q++) acc[i][j][q] = 0.f;

    const int iters = K / BK_;

    auto issue = [&](int it, int st) {
        const int k0 = it * BK_;
        uint32_t d0 = smem_u32(&sm[(st*3 + 0) * SLOT_H + lrow * LDA_ + lseg]);
        uint32_t d1 = smem_u32(&sm[(st*3 + 1) * SLOT_H + lrow * LDA_ + lseg]);
        uint32_t d2 = smem_u32(&sm[(st*3 + 2) * SLOT_H + lrow * LDA_ + lseg]);
        CP16(d0,      ahrow + k0);
        CP16(d0 + 16, ahrow + k0 + 8);
        CP16(d1,      alrow + k0);
        CP16(d1 + 16, alrow + k0 + 8);
        CP16(d2,      browp + k0);
        CP16(d2 + 16, browp + k0 + 8);
        CP_COMMIT();
    };

    issue(0, 0);
    issue(1, 1);

    const int arow16 = lane & 15;
    const int akoff  = (lane >> 4) << 3;
    const int brow8  = (lane & 7) + ((lane >> 4) << 3);
    const int bkoff  = ((lane >> 3) & 1) << 3;

    for (int it = 0; it < iters; it++) {
        const int cur = it % GST;
        CP_WAIT1();
        __syncthreads();
        if (it + 2 < iters) issue(it + 2, (it + 2) % GST);
        else CP_COMMIT();   // keep group cadence

        #pragma unroll
        for (int ks = 0; ks < 2; ks++) {
            const int k0 = ks * 16;
            uint32_t br[8][2];
            #pragma unroll
            for (int nf2 = 0; nf2 < 4; nf2++) {
                uint32_t r[4];
                ldmx4(r, smem_u32(&sm[(cur*3 + 2) * SLOT_H + (wn*64 + nf2*16 + brow8) * LDA_ + k0 + bkoff]));
                br[2*nf2][0] = r[0]; br[2*nf2][1] = r[1];
                br[2*nf2+1][0] = r[2]; br[2*nf2+1][1] = r[3];
            }
            #pragma unroll
            for (int mf = 0; mf < 2; mf++) {
                uint32_t arh[4], arl[4];
                const int aro = (wm*32 + mf*16 + arow16) * LDA_ + k0 + akoff;
                ldmx4(arh, smem_u32(&sm[(cur*3 + 0) * SLOT_H + aro]));
                ldmx4(arl, smem_u32(&sm[(cur*3 + 1) * SLOT_H + aro]));
                #pragma unroll
                for (int nf = 0; nf < 8; nf++) {
                    mma16816h(acc[mf][nf], arh, br[nf]);
                    mma16816h(acc[mf][nf], arl, br[nf]);
                }
            }
        }
    }

    #pragma unroll
    for (int mf = 0; mf < 2; mf++) {
        const int grow = bm + wm * 32 + mf * 16 + (lane >> 2);
        #pragma unroll
        for (int nf = 0; nf < 8; nf++) {
            const int gcol = bn + wn * 64 + nf * 8 + (lane & 3) * 2;
            if (gcol < Nreal) {
                *(float2*)(C + (size_t)grow * ldc + gcol) =
                    make_float2(acc[mf][nf][0], acc[mf][nf][1]);
                *(float2*)(C + (size_t)(grow + 8) * ldc + gcol) =
                    make_float2(acc[mf][nf][2], acc[mf][nf][3]);
            }
        }
    }
}

// ---------------- RoPE + rank contraction -> fp16 q, k, v [b][h][s][d] ----------------
__global__ void rope_contract_kernel(const float* __restrict__ cosb, const float* __restrict__ sinb)
{
    int token = blockIdx.x;
    int b = token / S_;
    int s = token % S_;
    const float* y = g_Y + (size_t)token * NPROJ;
    int d = threadIdx.x;

    __shared__ float sA[160];
    for (int i = d; i < 160; i += 128) sA[i] = y[i];
    __syncthreads();

    int dh = d & 63;
    float c  = cosb[s * 64 + dh];
    float sn = sinb[s * 64 + dh];
    bool hi = (d >= 64);

    float bq[QR_], bk[KR_], bv[VR_];
    #pragma unroll
    for (int r = 0; r < QR_; r++) {
        float x1 = y[OFF_BQ + r * HD_ + dh];
        float x2 = y[OFF_BQ + r * HD_ + 64 + dh];
        bq[r] = hi ? (x1 * sn + x2 * c) : (x1 * c - x2 * sn);
    }
    #pragma unroll
    for (int r = 0; r < KR_; r++) {
        float x1 = y[OFF_BK + r * HD_ + dh];
        float x2 = y[OFF_BK + r * HD_ + 64 + dh];
        bk[r] = hi ? (x1 * sn + x2 * c) : (x1 * c - x2 * sn);
    }
    #pragma unroll
    for (int r = 0; r < VR_; r++) bv[r] = y[OFF_BV + r * HD_ + d];

    #pragma unroll
    for (int h = 0; h < NH_; h++) {
        float accq = 0.f, acck = 0.f, accv = 0.f;
        #pragma unroll
        for (int r = 0; r < QR_; r++) accq += sA[h * QR_ + r] * bq[r];
        #pragma unroll
        for (int r = 0; r < KR_; r++) acck += sA[96 + h * KR_ + r] * bk[r];
        #pragma unroll
        for (int r = 0; r < VR_; r++) accv += sA[128 + h * VR_ + r] * bv[r];
        size_t o = (((size_t)b * NH_ + h) * S_ + s) * HD_ + d;
        g_qh[o] = __float2half_rn(accq * (SCALING_F / (float)QR_));
        g_kh[o] = __float2half_rn(acck * (1.f / (float)KR_));
        g_vh[o] = __float2half_rn(accv * (1.f / (float)VR_));
    }
}

// ---------------- Flash attention v5: fp16 QK single-term, PV 2-term ----------------
#define AQ_LD  136                      // fp16 row stride (272B)
#define QBUFB  (128*AQ_LD*2)            // Q buffer: 34816 B
#define BUFB   (64*AQ_LD*2)             // one K/V buffer: 17408 B
#define SM_Q   0
#define SM_KH  (SM_Q + QBUFB)           // [2] buffers
#define SM_VH  (SM_KH + 2*BUFB)
#define ATT_SMEM_BYTES (SM_VH + 2*BUFB) // 104448 B

__global__ __launch_bounds__(256, 1)
void attn_kernel(const float* __restrict__ mask)
{
    extern __shared__ char smc[];
    const uint32_t smb = smem_u32(smc);

    const int tid  = threadIdx.x;
    const int lane = tid & 31;
    const int wid  = tid >> 5;
    const int q0   = blockIdx.x * 128;
    const int h    = blockIdx.y;
    const int b    = blockIdx.z;

    const size_t headbase = ((size_t)b * NH_ + h) * S_ * HD_;

    const int crow = tid >> 2;
    const int ccg  = (tid & 3) * 32;
    auto issue_kv = [&](int kv0, int bi) {
        const size_t go = headbase + (size_t)(kv0 + crow) * HD_ + ccg;
        const uint32_t so = (uint32_t)(crow * AQ_LD + ccg) * 2 + bi * BUFB;
        #pragma unroll
        for (int j = 0; j < 4; j++) {
            CP16(smb + SM_KH + so + j*16, g_kh + go + j*8);
            CP16(smb + SM_VH + so + j*16, g_vh + go + j*8);
        }
        CP_COMMIT();
    };

    issue_kv(0, 0);

    // Q tile: 128 rows x 128 cols (direct loads)
    {
        const int qrow = tid >> 1;
        const int qcg  = (tid & 1) * 64;
        const size_t go = headbase + (size_t)(q0 + qrow) * HD_ + qcg;
        __half* Q_s = (__half*)(smc + SM_Q);
        #pragma unroll
        for (int j = 0; j < 8; j++)
            *(uint4*)&Q_s[qrow * AQ_LD + qcg + j*8] = *(const uint4*)(g_qh + go + j*8);
    }
    CP_WAIT0();
    __syncthreads();

    float acc[16][4];
    #pragma unroll
    for (int i = 0; i < 16; i++)
        #pragma unroll
        for (int j = 0; j < 4; j++) acc[i][j] = 0.f;
    float lp0 = 0.f, lp1 = 0.f;
    float mold0 = -INFINITY, mold1 = -INFINITY;

    const int arow  = lane & 15;
    const int akoff = (lane >> 4) << 3;
    const int brow8 = (lane & 7) + ((lane >> 4) << 3);
    const int bkoff = ((lane >> 3) & 1) << 3;
    const int rl0   = wid * 16 + (lane >> 2);
    const float* maskrow0 = mask + ((size_t)b * S_ + q0 + rl0) * S_ + (lane & 3) * 2;
    const float* maskrow1 = maskrow0 + (size_t)8 * S_;

    for (int t = 0; t < S_ / 64; t++) {
        const int kv0 = t * 64;
        const int cur = t & 1;
        const bool pf = (t + 1 < S_ / 64);
        if (pf) issue_kv(kv0 + 64, cur ^ 1);

        const uint32_t kh = smb + SM_KH + cur * BUFB;
        const uint32_t vh = smb + SM_VH + cur * BUFB;
        const uint32_t qs = smb + SM_Q;

        // ---- QK^T (single-term fp16): 16 x 64 per warp ----
        float sc[8][4];
        #pragma unroll
        for (int i = 0; i < 8; i++)
            #pragma unroll
            for (int j = 0; j < 4; j++) sc[i][j] = 0.f;

        #pragma unroll
        for (int k0 = 0; k0 < 128; k0 += 16) {
            uint32_t ah[4];
            const uint32_t aoff = ((wid * 16 + arow) * AQ_LD + k0 + akoff) * 2;
            ldmx4(ah, qs + aoff);
            #pragma unroll
            for (int nb = 0; nb < 4; nb++) {
                uint32_t bh[4];
                const uint32_t boff = ((nb * 16 + brow8) * AQ_LD + k0 + bkoff) * 2;
                ldmx4(bh, kh + boff);
                mma16816h(sc[nb*2],   ah, bh);
                mma16816h(sc[nb*2+1], ah, bh + 2);
            }
        }

        // ---- add mask + warp-local row max ----
        float mr0 = -INFINITY, mr1 = -INFINITY;
        #pragma unroll
        for (int i = 0; i < 8; i++) {
            float2 m0 = *(const float2*)(maskrow0 + kv0 + i * 8);
            float2 m1 = *(const float2*)(maskrow1 + kv0 + i * 8);
            sc[i][0] += m0.x; sc[i][1] += m0.y;
            sc[i][2] += m1.x; sc[i][3] += m1.y;
            mr0 = fmaxf(mr0, fmaxf(sc[i][0], sc[i][1]));
            mr1 = fmaxf(mr1, fmaxf(sc[i][2], sc[i][3]));
        }
        mr0 = fmaxf(mr0, __shfl_xor_sync(0xffffffffu, mr0, 1));
        mr0 = fmaxf(mr0, __shfl_xor_sync(0xffffffffu, mr0, 2));
        mr1 = fmaxf(mr1, __shfl_xor_sync(0xffffffffu, mr1, 1));
        mr1 = fmaxf(mr1, __shfl_xor_sync(0xffffffffu, mr1, 2));

        // ---- softmax update (warp-private) ----
        const float mnew0 = fmaxf(mold0, mr0);
        const float mnew1 = fmaxf(mold1, mr1);
        const float f0 = __expf(mold0 - mnew0);
        const float f1 = __expf(mold1 - mnew1);
        mold0 = mnew0; mold1 = mnew1;
        float s0 = 0.f, s1 = 0.f;
        #pragma unroll
        for (int i = 0; i < 8; i++) {
            sc[i][0] = __expf(sc[i][0] - mnew0);
            sc[i][1] = __expf(sc[i][1] - mnew0);
            sc[i][2] = __expf(sc[i][2] - mnew1);
            sc[i][3] = __expf(sc[i][3] - mnew1);
            s0 += sc[i][0] + sc[i][1];
            s1 += sc[i][2] + sc[i][3];
        }
        s0 += __shfl_xor_sync(0xffffffffu, s0, 1);
        s0 += __shfl_xor_sync(0xffffffffu, s0, 2);
        s1 += __shfl_xor_sync(0xffffffffu, s1, 1);
        s1 += __shfl_xor_sync(0xffffffffu, s1, 2);
        lp0 = lp0 * f0 + s0;
        lp1 = lp1 * f1 + s1;
        #pragma unroll
        for (int i = 0; i < 16; i++) {
            acc[i][0] *= f0; acc[i][1] *= f0;
            acc[i][2] *= f1; acc[i][3] *= f1;
        }

        // ---- PV (fp16 2-term): P from registers, V hi-only ----
        #pragma unroll
        for (int ks = 0; ks < 4; ks++) {
            uint32_t aPh[4], aPl[4];
            packsplit_h(sc[ks*2][0],   sc[ks*2][1],   aPh[0], aPl[0]);
            packsplit_h(sc[ks*2][2],   sc[ks*2][3],   aPh[1], aPl[1]);
            packsplit_h(sc[ks*2+1][0], sc[ks*2+1][1], aPh[2], aPl[2]);
            packsplit_h(sc[ks*2+1][2], sc[ks*2+1][3], aPh[3], aPl[3]);
            #pragma unroll
            for (int nb = 0; nb < 8; nb++) {
                uint32_t vfh[4];
                const uint32_t voff = ((ks * 16 + arow) * AQ_LD + nb * 16 + akoff) * 2;
                ldmx4t(vfh, vh + voff);
                mma16816h(acc[nb*2],   aPh, vfh);   mma16816h(acc[nb*2+1], aPh, vfh + 2);
                mma16816h(acc[nb*2],   aPl, vfh);   mma16816h(acc[nb*2+1], aPl, vfh + 2);
            }
        }

        if (pf) CP_WAIT0();
        __syncthreads();
    }

    // ---- epilogue: normalize, write fp16 [hi|lo] into g_Os (A-layout for gemm2) ----
    {
        const float inv0 = 1.f / lp0;
        const float inv1 = 1.f / lp1;
        const size_t row0 = ((size_t)b * S_ + q0 + rl0) * (2*HID_) + h * HD_;
        const size_t row1 = ((size_t)b * S_ + q0 + rl0 + 8) * (2*HID_) + h * HD_;
        #pragma unroll
        for (int ni = 0; ni < 16; ni++) {
            const int col = ni * 8 + (lane & 3) * 2;
            uint32_t ph, pl;
            packsplit_h(acc[ni][0] * inv0, acc[ni][1] * inv0, ph, pl);
            *(uint32_t*)(g_Os + row0 + col)        = ph;
            *(uint32_t*)(g_Os + row0 + col + HID_) = pl;
            packsplit_h(acc[ni][2] * inv1, acc[ni][3] * inv1, ph, pl);
            *(uint32_t*)(g_Os + row1 + col)        = ph;
            *(uint32_t*)(g_Os + row1 + col + HID_) = pl;
        }
    }
}

// ---------------- Host launcher ----------------
extern "C" void kernel_launch(void* const* d_in, const int* in_sizes, int n_in,
                              void* d_out, int out_size)
{
    const float* x    = (const float*)d_in[0];
    const float* cosb = (const float*)d_in[1];
    const float* sinb = (const float*)d_in[2];
    // d_in[3] = kv_write_indices (unused by reference)
    const float* mask = (const float*)d_in[4];
    const float* waq  = (const float*)d_in[5];
    const float* wak  = (const float*)d_in[6];
    const float* wav  = (const float*)d_in[7];
    const float* wbq  = (const float*)d_in[8];
    const float* wbk  = (const float*)d_in[9];
    const float* wbv  = (const float*)d_in[10];
    const float* wo   = (const float*)d_in[11];
    float* out = (float*)d_out;

    __half *pXs, *pWs, *pWos, *pOs;
    float *pY;
    cudaGetSymbolAddress((void**)&pXs,  g_Xs);
    cudaGetSymbolAddress((void**)&pWs,  g_Ws);
    cudaGetSymbolAddress((void**)&pWos, g_Wos);
    cudaGetSymbolAddress((void**)&pOs,  g_Os);
    cudaGetSymbolAddress((void**)&pY,   g_Y);

    // 1) conversions: X (A-layout [hi|lo]), Wcat (plain fp16), Wo (plain fp16)
    split_fp16<<<(M_ * (HID_/4) + 255)/256, 256>>>(x, pXs, M_, HID_, 0);
    concat_w_split<<<(NPROJ_PAD * (HID_/4) + 255)/256, 256>>>(waq, wak, wav, wbq, wbk, wbv);
    split_fp16<<<(HID_ * (HID_/4) + 255)/256, 256>>>(wo, pWos, HID_, HID_, 1);

    // 2) projection GEMM (shared-B 2-term, K=2048)
    cudaFuncSetAttribute(gemm_fp16, cudaFuncAttributeMaxDynamicSharedMemorySize, GEMM_SMEM);
    gemm_fp16<<<dim3(NPROJ_PAD/128, M_/128), 256, GEMM_SMEM>>>(pXs, pWs, pY, NPROJ, NPROJ, HID_);

    // 3) RoPE + contraction (fp16 q, k, v)
    rope_contract_kernel<<<M_, 128>>>(cosb, sinb);

    // 4) attention (QK single-term, PV 2-term)
    cudaFuncSetAttribute(attn_kernel, cudaFuncAttributeMaxDynamicSharedMemorySize, ATT_SMEM_BYTES);
    attn_kernel<<<dim3(S_/128, NH_, B_), 256, ATT_SMEM_BYTES>>>(mask);

    // 5) output GEMM (shared-B 2-term, K=2048)
    gemm_fp16<<<dim3(HID_/128, M_/128), 256, GEMM_SMEM>>>(pOs, pWos, out, HID_, HID_, HID_);
}